// round 5
// baseline (speedup 1.0000x reference)
#include <cuda_runtime.h>
#include <cuda_bf16.h>
#include <cstdint>

// Problem constants
#define PB  8
#define PS  1024
#define PH  768
#define PNH 12
#define PDH 64
#define PM  (PB * PS)          // 8192
#define PELEMS (PM * PH)       // 6291456
#define WN  (PH * PH)          // 589824
#define LQKV 2304              // fused q|k|v row stride

// ---------------------------------------------------------------------------
// Scratch (static device globals — no allocation)
// ---------------------------------------------------------------------------
__device__ __nv_bfloat16 g_xhi [PELEMS], g_xlo [PELEMS];
__device__ __nv_bfloat16 g_yhi [PELEMS], g_ylo [PELEMS];
__device__ __nv_bfloat16 g_qkvxh[PM * LQKV], g_qkvxl[PM * LQKV];
__device__ __nv_bfloat16 g_qkvyh[PM * LQKV], g_qkvyl[PM * LQKV];
__device__ __nv_bfloat16 g_cxhi[PELEMS], g_cxlo[PELEMS];
__device__ __nv_bfloat16 g_cyhi[PELEMS], g_cylo[PELEMS];
__device__ __nv_bfloat16 g_whi [8 * WN], g_wlo [8 * WN];
__device__ float g_bcx[LQKV], g_bcy[LQKV];

// ---------------------------------------------------------------------------
// Helpers (sm_80+-portable: ldmatrix + mma.sync + cp.async only)
// ---------------------------------------------------------------------------
__device__ __forceinline__ uint32_t smem_u32(const void* p) {
    uint32_t a;
    asm("{ .reg .u64 t; cvta.to.shared.u64 t, %1; cvt.u32.u64 %0, t; }"
        : "=r"(a) : "l"(p));
    return a;
}

__device__ __forceinline__ void cpasync16(uint32_t dst, const void* src) {
    asm volatile("cp.async.cg.shared.global [%0], [%1], 16;"
                 :: "r"(dst), "l"(src));
}
#define CP_COMMIT() asm volatile("cp.async.commit_group;")
#define CP_WAIT(n)  asm volatile("cp.async.wait_group %0;" :: "n"(n))

__device__ __forceinline__ void ldm4(uint32_t r[4], uint32_t addr) {
    asm volatile("ldmatrix.sync.aligned.m8n8.x4.shared.b16 {%0,%1,%2,%3}, [%4];"
        : "=r"(r[0]), "=r"(r[1]), "=r"(r[2]), "=r"(r[3]) : "r"(addr));
}
__device__ __forceinline__ void ldm4t(uint32_t r[4], uint32_t addr) {
    asm volatile("ldmatrix.sync.aligned.m8n8.x4.trans.shared.b16 {%0,%1,%2,%3}, [%4];"
        : "=r"(r[0]), "=r"(r[1]), "=r"(r[2]), "=r"(r[3]) : "r"(addr));
}

__device__ __forceinline__ void mma16816(float c[4], const uint32_t a[4],
                                         const uint32_t b[2]) {
    asm volatile("mma.sync.aligned.m16n8k16.row.col.f32.bf16.bf16.f32 "
        "{%0,%1,%2,%3}, {%4,%5,%6,%7}, {%8,%9}, {%0,%1,%2,%3};"
        : "+f"(c[0]), "+f"(c[1]), "+f"(c[2]), "+f"(c[3])
        : "r"(a[0]), "r"(a[1]), "r"(a[2]), "r"(a[3]), "r"(b[0]), "r"(b[1]));
}

__device__ __forceinline__ uint32_t packbf(__nv_bfloat16 a, __nv_bfloat16 b) {
    __nv_bfloat162 t(a, b);
    return *(uint32_t*)&t;
}

// ---------------------------------------------------------------------------
// fp32 -> bf16 hi/lo split ;  bias concatenation
// ---------------------------------------------------------------------------
__global__ void split_bf16(const float* __restrict__ x,
                           __nv_bfloat16* __restrict__ hi,
                           __nv_bfloat16* __restrict__ lo, int n4)
{
    int i = blockIdx.x * blockDim.x + threadIdx.x;
    if (i >= n4) return;
    float4 v = *(const float4*)(x + (size_t)i * 4);
    __nv_bfloat16 h0 = __float2bfloat16(v.x);
    __nv_bfloat16 h1 = __float2bfloat16(v.y);
    __nv_bfloat16 h2 = __float2bfloat16(v.z);
    __nv_bfloat16 h3 = __float2bfloat16(v.w);
    ((__nv_bfloat162*)hi)[i * 2 + 0] = __nv_bfloat162(h0, h1);
    ((__nv_bfloat162*)hi)[i * 2 + 1] = __nv_bfloat162(h2, h3);
    ((__nv_bfloat162*)lo)[i * 2 + 0] = __nv_bfloat162(
        __float2bfloat16(v.x - __bfloat162float(h0)),
        __float2bfloat16(v.y - __bfloat162float(h1)));
    ((__nv_bfloat162*)lo)[i * 2 + 1] = __nv_bfloat162(
        __float2bfloat16(v.z - __bfloat162float(h2)),
        __float2bfloat16(v.w - __bfloat162float(h3)));
}

__global__ void concat3(const float* __restrict__ a, const float* __restrict__ b,
                        const float* __restrict__ c, float* __restrict__ o)
{
    int i = blockIdx.x * blockDim.x + threadIdx.x;
    if (i < PH) o[i] = a[i];
    else if (i < 2 * PH) o[i] = b[i - PH];
    else if (i < 3 * PH) o[i] = c[i - 2 * PH];
}

// ---------------------------------------------------------------------------
// Split-bf16 GEMM on mma.sync: C[M,N] = A[M,768] @ W[N,768]^T + bscale*bias
// CTA tile 128x128, K-chunk 32, cp.async double-buffered. 256 threads.
// ---------------------------------------------------------------------------
#define GBK   32
#define GKCH  (PH / GBK)         // 24
#define GSA   40                 // smem row stride bf16 (80B)
#define PLANE_B (128 * GSA * 2)  // 10240
#define STAGE_B (4 * PLANE_B)    // 40960
#define GEMM_SMEM (2 * STAGE_B)  // 81920

__global__ void __launch_bounds__(256)
mm_gemm(const __nv_bfloat16* __restrict__ Ahi, const __nv_bfloat16* __restrict__ Alo,
        const __nv_bfloat16* __restrict__ Whi, const __nv_bfloat16* __restrict__ Wlo,
        const float* __restrict__ bias,
        const float* __restrict__ s1, const float* __restrict__ s2,
        float* __restrict__ Cf,
        __nv_bfloat16* __restrict__ Chi, __nv_bfloat16* __restrict__ Clo,
        int lda, int ldc)
{
    extern __shared__ char smem[];
    const uint32_t sb = smem_u32(smem);
    const int tid = threadIdx.x;
    const int wid = tid >> 5, lane = tid & 31;
    const int warpM = wid >> 2, warpN = wid & 3;
    const int row0 = blockIdx.y * 128, col0 = blockIdx.x * 128;

    const __nv_bfloat16* g0 = Ahi + (size_t)row0 * lda;
    const __nv_bfloat16* g1 = Alo + (size_t)row0 * lda;
    const __nv_bfloat16* g2 = Whi + (size_t)col0 * PH;
    const __nv_bfloat16* g3 = Wlo + (size_t)col0 * PH;

    float acc[4][4][4];
    #pragma unroll
    for (int mt = 0; mt < 4; mt++)
        #pragma unroll
        for (int nt = 0; nt < 4; nt++)
            #pragma unroll
            for (int c = 0; c < 4; c++) acc[mt][nt][c] = 0.0f;

    const int arow  = warpM * 64 + (lane & 15);
    const int akh   = lane >> 4;
    const int bkey  = warpN * 32 + (lane & 7) + ((lane >> 4) << 3);
    const int bkh   = (lane >> 3) & 1;

#define G_LOAD(kc, st) do {                                                   \
    const uint32_t dbase = sb + (st) * STAGE_B;                               \
    _Pragma("unroll")                                                         \
    for (int j = 0; j < 2; j++) {                                             \
        const int cc = j * 256 + tid;                                         \
        const int r = cc >> 2, seg = cc & 3;                                  \
        const uint32_t so = r * (GSA * 2) + seg * 16;                         \
        const size_t goA = (size_t)r * lda + (kc) * GBK + seg * 8;            \
        const size_t goW = (size_t)r * PH  + (kc) * GBK + seg * 8;            \
        cpasync16(dbase + 0 * PLANE_B + so, g0 + goA);                        \
        cpasync16(dbase + 1 * PLANE_B + so, g1 + goA);                        \
        cpasync16(dbase + 2 * PLANE_B + so, g2 + goW);                        \
        cpasync16(dbase + 3 * PLANE_B + so, g3 + goW);                        \
    }                                                                         \
} while (0)

    G_LOAD(0, 0);
    CP_COMMIT();

    for (int kc = 0; kc < GKCH; kc++) {
        if (kc + 1 < GKCH) {
            G_LOAD(kc + 1, (kc + 1) & 1);
            CP_COMMIT();
            CP_WAIT(1);
        } else {
            CP_WAIT(0);
        }
        __syncthreads();

        const uint32_t stb = sb + (kc & 1) * STAGE_B;
        #pragma unroll
        for (int ks = 0; ks < 2; ks++) {
            uint32_t ahi[4][4], alo[4][4];
            #pragma unroll
            for (int mt = 0; mt < 4; mt++) {
                const uint32_t addr = stb + (arow + mt * 16) * (GSA * 2)
                                      + ks * 32 + akh * 16;
                ldm4(ahi[mt], addr);
                ldm4(alo[mt], addr + PLANE_B);
            }
            uint32_t bhi[4][2], blo[4][2];
            #pragma unroll
            for (int ntp = 0; ntp < 2; ntp++) {
                const uint32_t addr = stb + 2 * PLANE_B
                                      + (bkey + ntp * 16) * (GSA * 2)
                                      + ks * 32 + bkh * 16;
                uint32_t t[4];
                ldm4(t, addr);
                bhi[2 * ntp][0] = t[0]; bhi[2 * ntp][1] = t[1];
                bhi[2 * ntp + 1][0] = t[2]; bhi[2 * ntp + 1][1] = t[3];
                ldm4(t, addr + PLANE_B);
                blo[2 * ntp][0] = t[0]; blo[2 * ntp][1] = t[1];
                blo[2 * ntp + 1][0] = t[2]; blo[2 * ntp + 1][1] = t[3];
            }
            #pragma unroll
            for (int mt = 0; mt < 4; mt++)
                #pragma unroll
                for (int nt = 0; nt < 4; nt++) {
                    mma16816(acc[mt][nt], ahi[mt], bhi[nt]);
                    mma16816(acc[mt][nt], ahi[mt], blo[nt]);
                    mma16816(acc[mt][nt], alo[mt], bhi[nt]);
                }
        }
        __syncthreads();
    }

    const int g = lane >> 2, tig = lane & 3;
    const float bscale = s1 ? (*s1 + *s2) : 1.0f;
    #pragma unroll
    for (int mt = 0; mt < 4; mt++) {
        const int r0 = row0 + warpM * 64 + mt * 16 + g;
        #pragma unroll
        for (int nt = 0; nt < 4; nt++) {
            const int col = col0 + warpN * 32 + nt * 8 + tig * 2;
            const float b0 = bscale * bias[col];
            const float b1 = bscale * bias[col + 1];
            const float v00 = acc[mt][nt][0] + b0, v01 = acc[mt][nt][1] + b1;
            const float v10 = acc[mt][nt][2] + b0, v11 = acc[mt][nt][3] + b1;
            if (Cf) {
                *(float2*)(Cf + (size_t)r0 * ldc + col)       = make_float2(v00, v01);
                *(float2*)(Cf + (size_t)(r0 + 8) * ldc + col) = make_float2(v10, v11);
            }
            if (Chi) {
                __nv_bfloat16 h00 = __float2bfloat16(v00), h01 = __float2bfloat16(v01);
                __nv_bfloat16 h10 = __float2bfloat16(v10), h11 = __float2bfloat16(v11);
                *(__nv_bfloat162*)(Chi + (size_t)r0 * ldc + col) = __nv_bfloat162(h00, h01);
                *(__nv_bfloat162*)(Chi + (size_t)(r0 + 8) * ldc + col) = __nv_bfloat162(h10, h11);
                *(__nv_bfloat162*)(Clo + (size_t)r0 * ldc + col) = __nv_bfloat162(
                    __float2bfloat16(v00 - __bfloat162float(h00)),
                    __float2bfloat16(v01 - __bfloat162float(h01)));
                *(__nv_bfloat162*)(Clo + (size_t)(r0 + 8) * ldc + col) = __nv_bfloat162(
                    __float2bfloat16(v10 - __bfloat162float(h10)),
                    __float2bfloat16(v11 - __bfloat162float(h11)));
            }
        }
    }
}

// ---------------------------------------------------------------------------
// Dual-stream flash attention, 128 q-rows per CTA, 8 warps,
// cp.async double-buffered 64-key KV tiles, flattened 2x16 iteration loop.
// ctx = w1*attend(Q,K1,V1) + w2*attend(Q,K2,V2) -> bf16 hi/lo (stride PH).
// ---------------------------------------------------------------------------
#define AST     72
#define ROWB    (AST * 2)          // 144
#define AQ_PL   (128 * ROWB)       // 18432
#define AKV_PL  (64 * ROWB)        // 9216
#define AKV_STG (4 * AKV_PL)       // 36864
#define KV_BASE (2 * AQ_PL)        // 36864
#define ATT_SMEM (KV_BASE + 2 * AKV_STG)   // 110592

__global__ void __launch_bounds__(256)
attn_mma(const __nv_bfloat16* __restrict__ Qh,  const __nv_bfloat16* __restrict__ Ql,
         const __nv_bfloat16* __restrict__ K1h, const __nv_bfloat16* __restrict__ K1l,
         const __nv_bfloat16* __restrict__ V1h, const __nv_bfloat16* __restrict__ V1l,
         const __nv_bfloat16* __restrict__ K2h, const __nv_bfloat16* __restrict__ K2l,
         const __nv_bfloat16* __restrict__ V2h, const __nv_bfloat16* __restrict__ V2l,
         const float* __restrict__ w1p, const float* __restrict__ w2p,
         __nv_bfloat16* __restrict__ ctxh, __nv_bfloat16* __restrict__ ctxl)
{
    extern __shared__ char smem[];
    const uint32_t sb = smem_u32(smem);

    const int qt = blockIdx.x, h = blockIdx.y, b = blockIdx.z;
    const int tid = threadIdx.x, wid = tid >> 5, lane = tid & 31;
    const int g = lane >> 2, tig = lane & 3;

    // --- load Q tile (hi/lo), 128 rows ---
    #pragma unroll
    for (int j = 0; j < 8; j++) {
        const int plane = j >> 2;
        const int sub = (j & 3) * 256 + tid;     // [0,1024)
        const int r = sub >> 3, seg = sub & 7;
        const size_t go = (size_t)(b * PS + qt * 128 + r) * LQKV + h * PDH + seg * 8;
        const uint32_t so = plane * AQ_PL + r * ROWB + seg * 16;
        *(uint4*)(smem + so) = *(const uint4*)((plane ? Ql : Qh) + go);
    }
    __syncthreads();

    // --- Q fragments in registers ---
    uint32_t qfh[4][4], qfl[4][4];
    {
        const int qrow = wid * 16 + (lane & 15);
        const int khalf = lane >> 4;
        #pragma unroll
        for (int ks = 0; ks < 4; ks++) {
            const uint32_t addr = sb + qrow * ROWB + ks * 32 + khalf * 16;
            ldm4(qfh[ks], addr);
            ldm4(qfl[ks], addr + AQ_PL);
        }
    }

    const int bkey = (lane & 7) + ((lane >> 4) << 3);
    const int bkh  = (lane >> 3) & 1;
    const int vkey = (lane & 7) + (((lane >> 3) & 1) << 3);
    const int vdh  = (lane >> 4) << 3;

    const __nv_bfloat16* const PKH[2] = { K1h, K2h };
    const __nv_bfloat16* const PKL[2] = { K1l, K2l };
    const __nv_bfloat16* const PVH[2] = { V1h, V2h };
    const __nv_bfloat16* const PVL[2] = { V1l, V2l };

#define KV_LOAD(it) do {                                                      \
    const int _s = (it) >> 4, _kt = (it) & 15;                                \
    const uint32_t _db = sb + KV_BASE + ((it) & 1) * AKV_STG;                 \
    _Pragma("unroll")                                                         \
    for (int _j = 0; _j < 8; _j++) {                                          \
        const int _pl = _j >> 1;                                              \
        const int _sub = (_j & 1) * 256 + tid;                                \
        const int _r = _sub >> 3, _seg = _sub & 7;                            \
        const __nv_bfloat16* _src = _pl == 0 ? PKH[_s] : _pl == 1 ? PKL[_s]   \
                                  : _pl == 2 ? PVH[_s] : PVL[_s];             \
        const size_t _go = (size_t)(b * PS + _kt * 64 + _r) * LQKV            \
                           + h * PDH + _seg * 8;                              \
        cpasync16(_db + _pl * AKV_PL + _r * ROWB + _seg * 16, _src + _go);    \
    }                                                                         \
    CP_COMMIT();                                                              \
} while (0)

    const float w1 = *w1p, w2 = *w2p;
    float m[2], l[2], oacc[8][4], ostash[8][4];

    KV_LOAD(0);

    for (int it = 0; it < 32; it++) {
        __syncthreads();     // all warps done with the buffer being overwritten
        if (it + 1 < 32) {
            KV_LOAD(it + 1);
            CP_WAIT(1);
        } else {
            CP_WAIT(0);
        }
        __syncthreads();

        if ((it & 15) == 0) {
            if (it == 16) {
                const float i0 = w1 / l[0], i1 = w1 / l[1];
                #pragma unroll
                for (int nt = 0; nt < 8; nt++) {
                    ostash[nt][0] = oacc[nt][0] * i0;
                    ostash[nt][1] = oacc[nt][1] * i0;
                    ostash[nt][2] = oacc[nt][2] * i1;
                    ostash[nt][3] = oacc[nt][3] * i1;
                }
            }
            m[0] = m[1] = -1e30f;
            l[0] = l[1] = 0.0f;
            #pragma unroll
            for (int nt = 0; nt < 8; nt++)
                #pragma unroll
                for (int c = 0; c < 4; c++) oacc[nt][c] = 0.0f;
        }

        const uint32_t kh_s = sb + KV_BASE + (it & 1) * AKV_STG;
        const uint32_t vh_s = kh_s + 2 * AKV_PL;

        // --- scores S = Q @ K^T (split 3-mma) ---
        float sacc[8][4];
        #pragma unroll
        for (int nt = 0; nt < 8; nt++)
            #pragma unroll
            for (int c = 0; c < 4; c++) sacc[nt][c] = 0.0f;

        #pragma unroll
        for (int ks = 0; ks < 4; ks++) {
            #pragma unroll
            for (int ntp = 0; ntp < 4; ntp++) {
                const uint32_t addr = kh_s + (ntp * 16 + bkey) * ROWB
                                      + ks * 32 + bkh * 16;
                uint32_t th[4], tl[4];
                ldm4(th, addr);
                ldm4(tl, addr + AKV_PL);
                const uint32_t b0h[2] = { th[0], th[1] }, b1h[2] = { th[2], th[3] };
                const uint32_t b0l[2] = { tl[0], tl[1] }, b1l[2] = { tl[2], tl[3] };
                mma16816(sacc[2 * ntp],     qfh[ks], b0h);
                mma16816(sacc[2 * ntp],     qfh[ks], b0l);
                mma16816(sacc[2 * ntp],     qfl[ks], b0h);
                mma16816(sacc[2 * ntp + 1], qfh[ks], b1h);
                mma16816(sacc[2 * ntp + 1], qfh[ks], b1l);
                mma16816(sacc[2 * ntp + 1], qfl[ks], b1h);
            }
        }

        // --- online softmax ---
        #pragma unroll
        for (int nt = 0; nt < 8; nt++)
            #pragma unroll
            for (int c = 0; c < 4; c++) sacc[nt][c] *= 0.125f;

        #pragma unroll
        for (int half = 0; half < 2; half++) {
            float mx = -1e30f;
            #pragma unroll
            for (int nt = 0; nt < 8; nt++)
                mx = fmaxf(mx, fmaxf(sacc[nt][2 * half], sacc[nt][2 * half + 1]));
            mx = fmaxf(mx, __shfl_xor_sync(0xffffffffu, mx, 1));
            mx = fmaxf(mx, __shfl_xor_sync(0xffffffffu, mx, 2));
            const float mn = fmaxf(m[half], mx);
            const float corr = __expf(m[half] - mn);
            m[half] = mn;
            float rs = 0.0f;
            #pragma unroll
            for (int nt = 0; nt < 8; nt++) {
                const float p0 = __expf(sacc[nt][2 * half] - mn);
                const float p1 = __expf(sacc[nt][2 * half + 1] - mn);
                sacc[nt][2 * half] = p0;
                sacc[nt][2 * half + 1] = p1;
                rs += p0 + p1;
            }
            rs += __shfl_xor_sync(0xffffffffu, rs, 1);
            rs += __shfl_xor_sync(0xffffffffu, rs, 2);
            l[half] = l[half] * corr + rs;
            #pragma unroll
            for (int nt = 0; nt < 8; nt++) {
                oacc[nt][2 * half]     *= corr;
                oacc[nt][2 * half + 1] *= corr;
            }
        }

        // --- pack P into bf16 hi/lo fragments ---
        uint32_t ph[8][2], pl[8][2];
        #pragma unroll
        for (int nt = 0; nt < 8; nt++) {
            #pragma unroll
            for (int half = 0; half < 2; half++) {
                const float p0 = sacc[nt][2 * half], p1 = sacc[nt][2 * half + 1];
                const __nv_bfloat16 h0 = __float2bfloat16(p0);
                const __nv_bfloat16 h1 = __float2bfloat16(p1);
                ph[nt][half] = packbf(h0, h1);
                pl[nt][half] = packbf(__float2bfloat16(p0 - __bfloat162float(h0)),
                                      __float2bfloat16(p1 - __bfloat162float(h1)));
            }
        }

        // --- O += P @ V (split 3-mma) ---
        #pragma unroll
        for (int ks = 0; ks < 4; ks++) {
            const uint32_t pah[4] = { ph[2 * ks][0], ph[2 * ks][1],
                                      ph[2 * ks + 1][0], ph[2 * ks + 1][1] };
            const uint32_t pal[4] = { pl[2 * ks][0], pl[2 * ks][1],
                                      pl[2 * ks + 1][0], pl[2 * ks + 1][1] };
            #pragma unroll
            for (int dhp = 0; dhp < 4; dhp++) {
                const uint32_t addr = vh_s + (ks * 16 + vkey) * ROWB
                                      + (dhp * 16 + vdh) * 2;
                uint32_t th[4], tl[4];
                ldm4t(th, addr);
                ldm4t(tl, addr + AKV_PL);
                const uint32_t b0h[2] = { th[0], th[1] }, b1h[2] = { th[2], th[3] };
                const uint32_t b0l[2] = { tl[0], tl[1] }, b1l[2] = { tl[2], tl[3] };
                mma16816(oacc[2 * dhp],     pah, b0h);
                mma16816(oacc[2 * dhp],     pah, b0l);
                mma16816(oacc[2 * dhp],     pal, b0h);
                mma16816(oacc[2 * dhp + 1], pah, b1h);
                mma16816(oacc[2 * dhp + 1], pah, b1l);
                mma16816(oacc[2 * dhp + 1], pal, b1h);
            }
        }
    }

    // --- final combine + hi/lo store (ctx stride PH) ---
    {
        const float i0 = w2 / l[0], i1 = w2 / l[1];
        const int r0 = qt * 128 + wid * 16 + g;
        #pragma unroll
        for (int nt = 0; nt < 8; nt++) {
            const int col = h * PDH + nt * 8 + tig * 2;
            const float v00 = ostash[nt][0] + oacc[nt][0] * i0;
            const float v01 = ostash[nt][1] + oacc[nt][1] * i0;
            const float v10 = ostash[nt][2] + oacc[nt][2] * i1;
            const float v11 = ostash[nt][3] + oacc[nt][3] * i1;
            const size_t o0 = (size_t)(b * PS + r0) * PH + col;
            const size_t o1 = (size_t)(b * PS + r0 + 8) * PH + col;
            const __nv_bfloat16 h00 = __float2bfloat16(v00);
            const __nv_bfloat16 h01 = __float2bfloat16(v01);
            const __nv_bfloat16 h10 = __float2bfloat16(v10);
            const __nv_bfloat16 h11 = __float2bfloat16(v11);
            *(__nv_bfloat162*)(ctxh + o0) = __nv_bfloat162(h00, h01);
            *(__nv_bfloat162*)(ctxh + o1) = __nv_bfloat162(h10, h11);
            *(__nv_bfloat162*)(ctxl + o0) = __nv_bfloat162(
                __float2bfloat16(v00 - __bfloat162float(h00)),
                __float2bfloat16(v01 - __bfloat162float(h01)));
            *(__nv_bfloat162*)(ctxl + o1) = __nv_bfloat162(
                __float2bfloat16(v10 - __bfloat162float(h10)),
                __float2bfloat16(v11 - __bfloat162float(h11)));
        }
    }
}

// ---------------------------------------------------------------------------
// Launch
// ---------------------------------------------------------------------------
extern "C" void kernel_launch(void* const* d_in, const int* in_sizes, int n_in,
                              void* d_out, int out_size)
{
    const float* hx = (const float*)d_in[0];
    const float* hy = (const float*)d_in[1];
    const float* Wf[8] = { (const float*)d_in[2],  (const float*)d_in[4],
                           (const float*)d_in[6],  (const float*)d_in[8],
                           (const float*)d_in[10], (const float*)d_in[12],
                           (const float*)d_in[14], (const float*)d_in[16] };
    const float* Bf[8] = { (const float*)d_in[3],  (const float*)d_in[5],
                           (const float*)d_in[7],  (const float*)d_in[9],
                           (const float*)d_in[11], (const float*)d_in[13],
                           (const float*)d_in[15], (const float*)d_in[17] };
    // order: 0=q 1=k 2=v 3=o 4=qd 5=kd 6=vd 7=od
    const float* pw11 = (const float*)d_in[18];
    const float* pw12 = (const float*)d_in[19];
    const float* pw21 = (const float*)d_in[20];
    const float* pw22 = (const float*)d_in[21];
    float* out = (float*)d_out;

    __nv_bfloat16 *xhi, *xlo, *yhi, *ylo;
    __nv_bfloat16 *qkvxh, *qkvxl, *qkvyh, *qkvyl;
    __nv_bfloat16 *cxhi, *cxlo, *cyhi, *cylo, *whi, *wlo;
    float *bcx, *bcy;
    cudaGetSymbolAddress((void**)&xhi,   g_xhi);   cudaGetSymbolAddress((void**)&xlo,   g_xlo);
    cudaGetSymbolAddress((void**)&yhi,   g_yhi);   cudaGetSymbolAddress((void**)&ylo,   g_ylo);
    cudaGetSymbolAddress((void**)&qkvxh, g_qkvxh); cudaGetSymbolAddress((void**)&qkvxl, g_qkvxl);
    cudaGetSymbolAddress((void**)&qkvyh, g_qkvyh); cudaGetSymbolAddress((void**)&qkvyl, g_qkvyl);
    cudaGetSymbolAddress((void**)&cxhi,  g_cxhi);  cudaGetSymbolAddress((void**)&cxlo,  g_cxlo);
    cudaGetSymbolAddress((void**)&cyhi,  g_cyhi);  cudaGetSymbolAddress((void**)&cylo,  g_cylo);
    cudaGetSymbolAddress((void**)&whi,   g_whi);   cudaGetSymbolAddress((void**)&wlo,   g_wlo);
    cudaGetSymbolAddress((void**)&bcx,   g_bcx);   cudaGetSymbolAddress((void**)&bcy,   g_bcy);

    // splits + bias concat
    {
        const int n4a = PELEMS / 4, n4w = WN / 4;
        split_bf16<<<(n4a + 255) / 256, 256>>>(hx, xhi, xlo, n4a);
        split_bf16<<<(n4a + 255) / 256, 256>>>(hy, yhi, ylo, n4a);
        for (int i = 0; i < 8; i++)
            split_bf16<<<(n4w + 255) / 256, 256>>>(Wf[i], whi + (size_t)i * WN,
                                                   wlo + (size_t)i * WN, n4w);
        concat3<<<9, 256>>>(Bf[0], Bf[1], Bf[2], bcx);
        concat3<<<9, 256>>>(Bf[4], Bf[5], Bf[6], bcy);
    }

    cudaFuncSetAttribute(mm_gemm, cudaFuncAttributeMaxDynamicSharedMemorySize,
                         GEMM_SMEM);
    cudaFuncSetAttribute(attn_mma, cudaFuncAttributeMaxDynamicSharedMemorySize,
                         ATT_SMEM);

    // fused QKV projections (N = 2304)
    {
        const dim3 gq(LQKV / 128, PM / 128);    // (18, 64)
        mm_gemm<<<gq, 256, GEMM_SMEM>>>(xhi, xlo, whi + 0 * (size_t)WN,
                                        wlo + 0 * (size_t)WN, bcx,
                                        nullptr, nullptr, nullptr,
                                        qkvxh, qkvxl, PH, LQKV);
        mm_gemm<<<gq, 256, GEMM_SMEM>>>(yhi, ylo, whi + 4 * (size_t)WN,
                                        wlo + 4 * (size_t)WN, bcy,
                                        nullptr, nullptr, nullptr,
                                        qkvyh, qkvyl, PH, LQKV);
    }

    // dual-stream flash attention (128 q-rows per CTA)
    {
        const dim3 ga(PS / 128, PNH, PB);       // (8, 12, 8)
        attn_mma<<<ga, 256, ATT_SMEM>>>(
            qkvxh, qkvxl,
            qkvxh + PH, qkvxl + PH, qkvxh + 2 * PH, qkvxl + 2 * PH,
            qkvyh + PH, qkvyl + PH, qkvyh + 2 * PH, qkvyl + 2 * PH,
            pw11, pw12, cxhi, cxlo);
        attn_mma<<<ga, 256, ATT_SMEM>>>(
            qkvyh, qkvyl,
            qkvyh + PH, qkvyl + PH, qkvyh + 2 * PH, qkvyl + 2 * PH,
            qkvxh + PH, qkvxl + PH, qkvxh + 2 * PH, qkvxl + 2 * PH,
            pw21, pw22, cyhi, cylo);
    }

    // output projections (bias scaled by w1+w2)
    {
        const dim3 go(PH / 128, PM / 128);      // (6, 64)
        mm_gemm<<<go, 256, GEMM_SMEM>>>(cxhi, cxlo, whi + 3 * (size_t)WN,
                                        wlo + 3 * (size_t)WN, Bf[3],
                                        pw11, pw12, out, nullptr, nullptr, PH, PH);
        mm_gemm<<<go, 256, GEMM_SMEM>>>(cyhi, cylo, whi + 7 * (size_t)WN,
                                        wlo + 7 * (size_t)WN, Bf[7],
                                        pw21, pw22, out + (size_t)PM * PH,
                                        nullptr, nullptr, PH, PH);
    }
}

// round 6
// speedup vs baseline: 1.5757x; 1.5757x over previous
#include <cuda_runtime.h>
#include <cuda_bf16.h>
#include <cstdint>

// Problem constants
#define PB  8
#define PS  1024
#define PH  768
#define PNH 12
#define PDH 64
#define PM  (PB * PS)          // 8192
#define PELEMS (PM * PH)       // 6291456
#define WN  (PH * PH)          // 589824
#define LQKV 2304              // fused q|k|v row stride

// ---------------------------------------------------------------------------
// Scratch (static device globals — no allocation)
// ---------------------------------------------------------------------------
__device__ __nv_bfloat16 g_xhi [PELEMS], g_xlo [PELEMS];
__device__ __nv_bfloat16 g_yhi [PELEMS], g_ylo [PELEMS];
__device__ __nv_bfloat16 g_qkvxh[PM * LQKV], g_qkvxl[PM * LQKV];
__device__ __nv_bfloat16 g_qkvyh[PM * LQKV], g_qkvyl[PM * LQKV];
__device__ __nv_bfloat16 g_cxhi[PELEMS], g_cxlo[PELEMS];
__device__ __nv_bfloat16 g_cyhi[PELEMS], g_cylo[PELEMS];
__device__ __nv_bfloat16 g_whi [8 * WN], g_wlo [8 * WN];
__device__ float g_bcx[LQKV], g_bcy[LQKV];

// ---------------------------------------------------------------------------
// Helpers (sm_80+-portable: ldmatrix + mma.sync + cp.async only)
// ---------------------------------------------------------------------------
__device__ __forceinline__ uint32_t smem_u32(const void* p) {
    uint32_t a;
    asm("{ .reg .u64 t; cvta.to.shared.u64 t, %1; cvt.u32.u64 %0, t; }"
        : "=r"(a) : "l"(p));
    return a;
}

__device__ __forceinline__ void cpasync16(uint32_t dst, const void* src) {
    asm volatile("cp.async.cg.shared.global [%0], [%1], 16;"
                 :: "r"(dst), "l"(src));
}
#define CP_COMMIT() asm volatile("cp.async.commit_group;")
#define CP_WAIT(n)  asm volatile("cp.async.wait_group %0;" :: "n"(n))

__device__ __forceinline__ void ldm4(uint32_t r[4], uint32_t addr) {
    asm volatile("ldmatrix.sync.aligned.m8n8.x4.shared.b16 {%0,%1,%2,%3}, [%4];"
        : "=r"(r[0]), "=r"(r[1]), "=r"(r[2]), "=r"(r[3]) : "r"(addr));
}
__device__ __forceinline__ void ldm4t(uint32_t r[4], uint32_t addr) {
    asm volatile("ldmatrix.sync.aligned.m8n8.x4.trans.shared.b16 {%0,%1,%2,%3}, [%4];"
        : "=r"(r[0]), "=r"(r[1]), "=r"(r[2]), "=r"(r[3]) : "r"(addr));
}

__device__ __forceinline__ void mma16816(float c[4], const uint32_t a[4],
                                         const uint32_t b[2]) {
    asm volatile("mma.sync.aligned.m16n8k16.row.col.f32.bf16.bf16.f32 "
        "{%0,%1,%2,%3}, {%4,%5,%6,%7}, {%8,%9}, {%0,%1,%2,%3};"
        : "+f"(c[0]), "+f"(c[1]), "+f"(c[2]), "+f"(c[3])
        : "r"(a[0]), "r"(a[1]), "r"(a[2]), "r"(a[3]), "r"(b[0]), "r"(b[1]));
}

__device__ __forceinline__ uint32_t packbf(__nv_bfloat16 a, __nv_bfloat16 b) {
    __nv_bfloat162 t(a, b);
    return *(uint32_t*)&t;
}

// ---------------------------------------------------------------------------
// fp32 -> bf16 hi/lo splits (batched) ; bias concatenation
// ---------------------------------------------------------------------------
__device__ __forceinline__ void split4(const float* __restrict__ x,
                                       __nv_bfloat16* __restrict__ hi,
                                       __nv_bfloat16* __restrict__ lo, int i)
{
    float4 v = *(const float4*)(x + (size_t)i * 4);
    __nv_bfloat16 h0 = __float2bfloat16(v.x);
    __nv_bfloat16 h1 = __float2bfloat16(v.y);
    __nv_bfloat16 h2 = __float2bfloat16(v.z);
    __nv_bfloat16 h3 = __float2bfloat16(v.w);
    ((__nv_bfloat162*)hi)[i * 2 + 0] = __nv_bfloat162(h0, h1);
    ((__nv_bfloat162*)hi)[i * 2 + 1] = __nv_bfloat162(h2, h3);
    ((__nv_bfloat162*)lo)[i * 2 + 0] = __nv_bfloat162(
        __float2bfloat16(v.x - __bfloat162float(h0)),
        __float2bfloat16(v.y - __bfloat162float(h1)));
    ((__nv_bfloat162*)lo)[i * 2 + 1] = __nv_bfloat162(
        __float2bfloat16(v.z - __bfloat162float(h2)),
        __float2bfloat16(v.w - __bfloat162float(h3)));
}

__global__ void split_inputs(const float* __restrict__ hx, const float* __restrict__ hy,
                             __nv_bfloat16* __restrict__ xhi, __nv_bfloat16* __restrict__ xlo,
                             __nv_bfloat16* __restrict__ yhi, __nv_bfloat16* __restrict__ ylo)
{
    int i = blockIdx.x * blockDim.x + threadIdx.x;
    if (i >= PELEMS / 4) return;
    if (blockIdx.y == 0) split4(hx, xhi, xlo, i);
    else                 split4(hy, yhi, ylo, i);
}

__global__ void split_weights(const float* w0, const float* w1, const float* w2,
                              const float* w3, const float* w4, const float* w5,
                              const float* w6, const float* w7,
                              __nv_bfloat16* __restrict__ hi,
                              __nv_bfloat16* __restrict__ lo)
{
    int i = blockIdx.x * blockDim.x + threadIdx.x;
    if (i >= WN / 4) return;
    const int s = blockIdx.y;
    const float* src;
    switch (s) {
        case 0: src = w0; break; case 1: src = w1; break;
        case 2: src = w2; break; case 3: src = w3; break;
        case 4: src = w4; break; case 5: src = w5; break;
        case 6: src = w6; break; default: src = w7; break;
    }
    split4(src, hi + (size_t)s * WN, lo + (size_t)s * WN, i);
}

__global__ void concat3(const float* __restrict__ a, const float* __restrict__ b,
                        const float* __restrict__ c, float* __restrict__ o)
{
    int i = blockIdx.x * blockDim.x + threadIdx.x;
    if (i < PH) o[i] = a[i];
    else if (i < 2 * PH) o[i] = b[i - PH];
    else if (i < 3 * PH) o[i] = c[i - 2 * PH];
}

// ---------------------------------------------------------------------------
// Split-bf16 GEMM on mma.sync: C[M,N] = A[M,768] @ W[N,768]^T + bscale*bias
// CTA tile 128x128, K-chunk 32, cp.async double-buffered. 256 threads.
// ---------------------------------------------------------------------------
#define GBK   32
#define GKCH  (PH / GBK)         // 24
#define GSA   40                 // smem row stride bf16 (80B)
#define PLANE_B (128 * GSA * 2)  // 10240
#define STAGE_B (4 * PLANE_B)    // 40960
#define GEMM_SMEM (2 * STAGE_B)  // 81920

__global__ void __launch_bounds__(256)
mm_gemm(const __nv_bfloat16* __restrict__ Ahi, const __nv_bfloat16* __restrict__ Alo,
        const __nv_bfloat16* __restrict__ Whi, const __nv_bfloat16* __restrict__ Wlo,
        const float* __restrict__ bias,
        const float* __restrict__ s1, const float* __restrict__ s2,
        float* __restrict__ Cf,
        __nv_bfloat16* __restrict__ Chi, __nv_bfloat16* __restrict__ Clo,
        int lda, int ldc)
{
    extern __shared__ char smem[];
    const uint32_t sb = smem_u32(smem);
    const int tid = threadIdx.x;
    const int wid = tid >> 5, lane = tid & 31;
    const int warpM = wid >> 2, warpN = wid & 3;
    const int row0 = blockIdx.y * 128, col0 = blockIdx.x * 128;

    const __nv_bfloat16* g0 = Ahi + (size_t)row0 * lda;
    const __nv_bfloat16* g1 = Alo + (size_t)row0 * lda;
    const __nv_bfloat16* g2 = Whi + (size_t)col0 * PH;
    const __nv_bfloat16* g3 = Wlo + (size_t)col0 * PH;

    float acc[4][4][4];
    #pragma unroll
    for (int mt = 0; mt < 4; mt++)
        #pragma unroll
        for (int nt = 0; nt < 4; nt++)
            #pragma unroll
            for (int c = 0; c < 4; c++) acc[mt][nt][c] = 0.0f;

    const int arow  = warpM * 64 + (lane & 15);
    const int akh   = lane >> 4;
    const int bkey  = warpN * 32 + (lane & 7) + ((lane >> 4) << 3);
    const int bkh   = (lane >> 3) & 1;

#define G_LOAD(kc, st) do {                                                   \
    const uint32_t dbase = sb + (st) * STAGE_B;                               \
    _Pragma("unroll")                                                         \
    for (int j = 0; j < 2; j++) {                                             \
        const int cc = j * 256 + tid;                                         \
        const int r = cc >> 2, seg = cc & 3;                                  \
        const uint32_t so = r * (GSA * 2) + seg * 16;                         \
        const size_t goA = (size_t)r * lda + (kc) * GBK + seg * 8;            \
        const size_t goW = (size_t)r * PH  + (kc) * GBK + seg * 8;            \
        cpasync16(dbase + 0 * PLANE_B + so, g0 + goA);                        \
        cpasync16(dbase + 1 * PLANE_B + so, g1 + goA);                        \
        cpasync16(dbase + 2 * PLANE_B + so, g2 + goW);                        \
        cpasync16(dbase + 3 * PLANE_B + so, g3 + goW);                        \
    }                                                                         \
} while (0)

    G_LOAD(0, 0);
    CP_COMMIT();

    for (int kc = 0; kc < GKCH; kc++) {
        if (kc + 1 < GKCH) {
            G_LOAD(kc + 1, (kc + 1) & 1);
            CP_COMMIT();
            CP_WAIT(1);
        } else {
            CP_WAIT(0);
        }
        __syncthreads();

        const uint32_t stb = sb + (kc & 1) * STAGE_B;
        #pragma unroll
        for (int ks = 0; ks < 2; ks++) {
            uint32_t ahi[4][4], alo[4][4];
            #pragma unroll
            for (int mt = 0; mt < 4; mt++) {
                const uint32_t addr = stb + (arow + mt * 16) * (GSA * 2)
                                      + ks * 32 + akh * 16;
                ldm4(ahi[mt], addr);
                ldm4(alo[mt], addr + PLANE_B);
            }
            uint32_t bhi[4][2], blo[4][2];
            #pragma unroll
            for (int ntp = 0; ntp < 2; ntp++) {
                const uint32_t addr = stb + 2 * PLANE_B
                                      + (bkey + ntp * 16) * (GSA * 2)
                                      + ks * 32 + bkh * 16;
                uint32_t t[4];
                ldm4(t, addr);
                bhi[2 * ntp][0] = t[0]; bhi[2 * ntp][1] = t[1];
                bhi[2 * ntp + 1][0] = t[2]; bhi[2 * ntp + 1][1] = t[3];
                ldm4(t, addr + PLANE_B);
                blo[2 * ntp][0] = t[0]; blo[2 * ntp][1] = t[1];
                blo[2 * ntp + 1][0] = t[2]; blo[2 * ntp + 1][1] = t[3];
            }
            #pragma unroll
            for (int mt = 0; mt < 4; mt++)
                #pragma unroll
                for (int nt = 0; nt < 4; nt++) {
                    mma16816(acc[mt][nt], ahi[mt], bhi[nt]);
                    mma16816(acc[mt][nt], ahi[mt], blo[nt]);
                    mma16816(acc[mt][nt], alo[mt], bhi[nt]);
                }
        }
        __syncthreads();
    }

    const int g = lane >> 2, tig = lane & 3;
    const float bscale = s1 ? (*s1 + *s2) : 1.0f;
    #pragma unroll
    for (int mt = 0; mt < 4; mt++) {
        const int r0 = row0 + warpM * 64 + mt * 16 + g;
        #pragma unroll
        for (int nt = 0; nt < 4; nt++) {
            const int col = col0 + warpN * 32 + nt * 8 + tig * 2;
            const float b0 = bscale * bias[col];
            const float b1 = bscale * bias[col + 1];
            const float v00 = acc[mt][nt][0] + b0, v01 = acc[mt][nt][1] + b1;
            const float v10 = acc[mt][nt][2] + b0, v11 = acc[mt][nt][3] + b1;
            if (Cf) {
                *(float2*)(Cf + (size_t)r0 * ldc + col)       = make_float2(v00, v01);
                *(float2*)(Cf + (size_t)(r0 + 8) * ldc + col) = make_float2(v10, v11);
            }
            if (Chi) {
                __nv_bfloat16 h00 = __float2bfloat16(v00), h01 = __float2bfloat16(v01);
                __nv_bfloat16 h10 = __float2bfloat16(v10), h11 = __float2bfloat16(v11);
                *(__nv_bfloat162*)(Chi + (size_t)r0 * ldc + col) = __nv_bfloat162(h00, h01);
                *(__nv_bfloat162*)(Chi + (size_t)(r0 + 8) * ldc + col) = __nv_bfloat162(h10, h11);
                *(__nv_bfloat162*)(Clo + (size_t)r0 * ldc + col) = __nv_bfloat162(
                    __float2bfloat16(v00 - __bfloat162float(h00)),
                    __float2bfloat16(v01 - __bfloat162float(h01)));
                *(__nv_bfloat162*)(Clo + (size_t)(r0 + 8) * ldc + col) = __nv_bfloat162(
                    __float2bfloat16(v10 - __bfloat162float(h10)),
                    __float2bfloat16(v11 - __bfloat162float(h11)));
            }
        }
    }
}

// ---------------------------------------------------------------------------
// Dual-stream flash attention on mma.sync (round-4 shape: 64 q-rows, 4 warps,
// 55KB smem, two sequential stream loops). KV tiles loaded via cp.async.
// ctx = w1*attend(Q,K1,V1) + w2*attend(Q,K2,V2) -> bf16 hi/lo (stride PH).
// ---------------------------------------------------------------------------
#define AST     72                    // bf16 row stride (144B)
#define ROWB    (AST * 2)             // 144
#define ATILE_B (64 * ROWB)           // 9216
#define ATT_SMEM (6 * ATILE_B)        // 55296  [qh][ql][kh][kl][vh][vl]

__global__ void __launch_bounds__(128)
attn_mma(const __nv_bfloat16* __restrict__ Qh,  const __nv_bfloat16* __restrict__ Ql,
         const __nv_bfloat16* __restrict__ K1h, const __nv_bfloat16* __restrict__ K1l,
         const __nv_bfloat16* __restrict__ V1h, const __nv_bfloat16* __restrict__ V1l,
         const __nv_bfloat16* __restrict__ K2h, const __nv_bfloat16* __restrict__ K2l,
         const __nv_bfloat16* __restrict__ V2h, const __nv_bfloat16* __restrict__ V2l,
         const float* __restrict__ w1p, const float* __restrict__ w2p,
         __nv_bfloat16* __restrict__ ctxh, __nv_bfloat16* __restrict__ ctxl)
{
    extern __shared__ char smem[];
    const uint32_t sb = smem_u32(smem);
    const uint32_t kh_s = sb + 2 * ATILE_B;
    const uint32_t vh_s = sb + 4 * ATILE_B;

    const int qt = blockIdx.x, h = blockIdx.y, b = blockIdx.z;
    const int tid = threadIdx.x, wid = tid >> 5, lane = tid & 31;
    const int g = lane >> 2, tig = lane & 3;

    // --- load Q tile (hi/lo) via cp.async ---
    #pragma unroll
    for (int j = 0; j < 4; j++) {
        const int cc = j * 128 + tid;        // 512 chunks per plane
        const int r = cc >> 3, seg = cc & 7;
        const size_t go = (size_t)(b * PS + qt * 64 + r) * LQKV + h * PDH + seg * 8;
        const uint32_t so = r * ROWB + seg * 16;
        cpasync16(sb + so,           Qh + go);
        cpasync16(sb + ATILE_B + so, Ql + go);
    }
    CP_COMMIT();
    CP_WAIT(0);
    __syncthreads();

    // --- Q fragments (held in registers for both streams) ---
    uint32_t qfh[4][4], qfl[4][4];
    {
        const int qrow = wid * 16 + (lane & 15);
        const int khalf = lane >> 4;
        #pragma unroll
        for (int ks = 0; ks < 4; ks++) {
            const uint32_t addr = sb + qrow * ROWB + ks * 32 + khalf * 16;
            ldm4(qfh[ks], addr);
            ldm4(qfl[ks], addr + ATILE_B);
        }
    }

    const int bkey = (lane & 7) + ((lane >> 4) << 3);        // QK B-frag lane row
    const int bkh  = (lane >> 3) & 1;
    const int vkey = (lane & 7) + (((lane >> 3) & 1) << 3);  // PV B-frag lane row
    const int vdh  = (lane >> 4) << 3;

    const float w1 = *w1p, w2 = *w2p;
    float ostash[8][4];

    for (int s = 0; s < 2; s++) {
        const __nv_bfloat16* Kh_ = s ? K2h : K1h;
        const __nv_bfloat16* Kl_ = s ? K2l : K1l;
        const __nv_bfloat16* Vh_ = s ? V2h : V1h;
        const __nv_bfloat16* Vl_ = s ? V2l : V1l;

        float m[2] = { -1e30f, -1e30f }, l[2] = { 0.0f, 0.0f };
        float oacc[8][4];
        #pragma unroll
        for (int nt = 0; nt < 8; nt++)
            #pragma unroll
            for (int c = 0; c < 4; c++) oacc[nt][c] = 0.0f;

        for (int kt = 0; kt < PS / 64; kt++) {
            __syncthreads();
            #pragma unroll
            for (int j = 0; j < 4; j++) {
                const int cc = j * 128 + tid;
                const int r = cc >> 3, seg = cc & 7;
                const size_t go = (size_t)(b * PS + kt * 64 + r) * LQKV + h * PDH + seg * 8;
                const uint32_t so = r * ROWB + seg * 16;
                cpasync16(sb + 2 * ATILE_B + so, Kh_ + go);
                cpasync16(sb + 3 * ATILE_B + so, Kl_ + go);
                cpasync16(sb + 4 * ATILE_B + so, Vh_ + go);
                cpasync16(sb + 5 * ATILE_B + so, Vl_ + go);
            }
            CP_COMMIT();
            CP_WAIT(0);
            __syncthreads();

            // --- scores S = Q @ K^T (split 3-mma) ---
            float sacc[8][4];
            #pragma unroll
            for (int nt = 0; nt < 8; nt++)
                #pragma unroll
                for (int c = 0; c < 4; c++) sacc[nt][c] = 0.0f;

            #pragma unroll
            for (int ks = 0; ks < 4; ks++) {
                #pragma unroll
                for (int ntp = 0; ntp < 4; ntp++) {
                    const uint32_t addr = kh_s + (ntp * 16 + bkey) * ROWB
                                          + ks * 32 + bkh * 16;
                    uint32_t th[4], tl[4];
                    ldm4(th, addr);
                    ldm4(tl, addr + ATILE_B);
                    const uint32_t b0h[2] = { th[0], th[1] }, b1h[2] = { th[2], th[3] };
                    const uint32_t b0l[2] = { tl[0], tl[1] }, b1l[2] = { tl[2], tl[3] };
                    mma16816(sacc[2 * ntp],     qfh[ks], b0h);
                    mma16816(sacc[2 * ntp],     qfh[ks], b0l);
                    mma16816(sacc[2 * ntp],     qfl[ks], b0h);
                    mma16816(sacc[2 * ntp + 1], qfh[ks], b1h);
                    mma16816(sacc[2 * ntp + 1], qfh[ks], b1l);
                    mma16816(sacc[2 * ntp + 1], qfl[ks], b1h);
                }
            }

            // --- online softmax (rows g and g+8) ---
            #pragma unroll
            for (int nt = 0; nt < 8; nt++)
                #pragma unroll
                for (int c = 0; c < 4; c++) sacc[nt][c] *= 0.125f;

            #pragma unroll
            for (int half = 0; half < 2; half++) {
                float mx = -1e30f;
                #pragma unroll
                for (int nt = 0; nt < 8; nt++)
                    mx = fmaxf(mx, fmaxf(sacc[nt][2 * half], sacc[nt][2 * half + 1]));
                mx = fmaxf(mx, __shfl_xor_sync(0xffffffffu, mx, 1));
                mx = fmaxf(mx, __shfl_xor_sync(0xffffffffu, mx, 2));
                const float mn = fmaxf(m[half], mx);
                const float corr = __expf(m[half] - mn);
                m[half] = mn;
                float rs = 0.0f;
                #pragma unroll
                for (int nt = 0; nt < 8; nt++) {
                    const float p0 = __expf(sacc[nt][2 * half] - mn);
                    const float p1 = __expf(sacc[nt][2 * half + 1] - mn);
                    sacc[nt][2 * half] = p0;
                    sacc[nt][2 * half + 1] = p1;
                    rs += p0 + p1;
                }
                rs += __shfl_xor_sync(0xffffffffu, rs, 1);
                rs += __shfl_xor_sync(0xffffffffu, rs, 2);
                l[half] = l[half] * corr + rs;
                #pragma unroll
                for (int nt = 0; nt < 8; nt++) {
                    oacc[nt][2 * half]     *= corr;
                    oacc[nt][2 * half + 1] *= corr;
                }
            }

            // --- pack P into bf16 hi/lo A-fragments ---
            uint32_t ph[8][2], pl[8][2];
            #pragma unroll
            for (int nt = 0; nt < 8; nt++) {
                #pragma unroll
                for (int half = 0; half < 2; half++) {
                    const float p0 = sacc[nt][2 * half], p1 = sacc[nt][2 * half + 1];
                    const __nv_bfloat16 h0 = __float2bfloat16(p0);
                    const __nv_bfloat16 h1 = __float2bfloat16(p1);
                    ph[nt][half] = packbf(h0, h1);
                    pl[nt][half] = packbf(__float2bfloat16(p0 - __bfloat162float(h0)),
                                          __float2bfloat16(p1 - __bfloat162float(h1)));
                }
            }

            // --- O += P @ V (split 3-mma, V^T via trans ldmatrix) ---
            #pragma unroll
            for (int ks = 0; ks < 4; ks++) {
                const uint32_t pah[4] = { ph[2 * ks][0], ph[2 * ks][1],
                                          ph[2 * ks + 1][0], ph[2 * ks + 1][1] };
                const uint32_t pal[4] = { pl[2 * ks][0], pl[2 * ks][1],
                                          pl[2 * ks + 1][0], pl[2 * ks + 1][1] };
                #pragma unroll
                for (int dhp = 0; dhp < 4; dhp++) {
                    const uint32_t addr = vh_s + (ks * 16 + vkey) * ROWB
                                          + (dhp * 16 + vdh) * 2;
                    uint32_t th[4], tl[4];
                    ldm4t(th, addr);
                    ldm4t(tl, addr + ATILE_B);
                    const uint32_t b0h[2] = { th[0], th[1] }, b1h[2] = { th[2], th[3] };
                    const uint32_t b0l[2] = { tl[0], tl[1] }, b1l[2] = { tl[2], tl[3] };
                    mma16816(oacc[2 * dhp],     pah, b0h);
                    mma16816(oacc[2 * dhp],     pah, b0l);
                    mma16816(oacc[2 * dhp],     pal, b0h);
                    mma16816(oacc[2 * dhp + 1], pah, b1h);
                    mma16816(oacc[2 * dhp + 1], pah, b1l);
                    mma16816(oacc[2 * dhp + 1], pal, b1h);
                }
            }
        }

        if (s == 0) {
            const float i0 = w1 / l[0], i1 = w1 / l[1];
            #pragma unroll
            for (int nt = 0; nt < 8; nt++) {
                ostash[nt][0] = oacc[nt][0] * i0;
                ostash[nt][1] = oacc[nt][1] * i0;
                ostash[nt][2] = oacc[nt][2] * i1;
                ostash[nt][3] = oacc[nt][3] * i1;
            }
        } else {
            const float i0 = w2 / l[0], i1 = w2 / l[1];
            const int r0 = qt * 64 + wid * 16 + g;
            #pragma unroll
            for (int nt = 0; nt < 8; nt++) {
                const int col = h * PDH + nt * 8 + tig * 2;
                const float v00 = ostash[nt][0] + oacc[nt][0] * i0;
                const float v01 = ostash[nt][1] + oacc[nt][1] * i0;
                const float v10 = ostash[nt][2] + oacc[nt][2] * i1;
                const float v11 = ostash[nt][3] + oacc[nt][3] * i1;
                const size_t o0 = (size_t)(b * PS + r0) * PH + col;
                const size_t o1 = (size_t)(b * PS + r0 + 8) * PH + col;
                const __nv_bfloat16 h00 = __float2bfloat16(v00);
                const __nv_bfloat16 h01 = __float2bfloat16(v01);
                const __nv_bfloat16 h10 = __float2bfloat16(v10);
                const __nv_bfloat16 h11 = __float2bfloat16(v11);
                *(__nv_bfloat162*)(ctxh + o0) = __nv_bfloat162(h00, h01);
                *(__nv_bfloat162*)(ctxh + o1) = __nv_bfloat162(h10, h11);
                *(__nv_bfloat162*)(ctxl + o0) = __nv_bfloat162(
                    __float2bfloat16(v00 - __bfloat162float(h00)),
                    __float2bfloat16(v01 - __bfloat162float(h01)));
                *(__nv_bfloat162*)(ctxl + o1) = __nv_bfloat162(
                    __float2bfloat16(v10 - __bfloat162float(h10)),
                    __float2bfloat16(v11 - __bfloat162float(h11)));
            }
        }
    }
}

// ---------------------------------------------------------------------------
// Launch
// ---------------------------------------------------------------------------
extern "C" void kernel_launch(void* const* d_in, const int* in_sizes, int n_in,
                              void* d_out, int out_size)
{
    const float* hx = (const float*)d_in[0];
    const float* hy = (const float*)d_in[1];
    const float* Wf[8] = { (const float*)d_in[2],  (const float*)d_in[4],
                           (const float*)d_in[6],  (const float*)d_in[8],
                           (const float*)d_in[10], (const float*)d_in[12],
                           (const float*)d_in[14], (const float*)d_in[16] };
    const float* Bf[8] = { (const float*)d_in[3],  (const float*)d_in[5],
                           (const float*)d_in[7],  (const float*)d_in[9],
                           (const float*)d_in[11], (const float*)d_in[13],
                           (const float*)d_in[15], (const float*)d_in[17] };
    // order: 0=q 1=k 2=v 3=o 4=qd 5=kd 6=vd 7=od
    const float* pw11 = (const float*)d_in[18];
    const float* pw12 = (const float*)d_in[19];
    const float* pw21 = (const float*)d_in[20];
    const float* pw22 = (const float*)d_in[21];
    float* out = (float*)d_out;

    __nv_bfloat16 *xhi, *xlo, *yhi, *ylo;
    __nv_bfloat16 *qkvxh, *qkvxl, *qkvyh, *qkvyl;
    __nv_bfloat16 *cxhi, *cxlo, *cyhi, *cylo, *whi, *wlo;
    float *bcx, *bcy;
    cudaGetSymbolAddress((void**)&xhi,   g_xhi);   cudaGetSymbolAddress((void**)&xlo,   g_xlo);
    cudaGetSymbolAddress((void**)&yhi,   g_yhi);   cudaGetSymbolAddress((void**)&ylo,   g_ylo);
    cudaGetSymbolAddress((void**)&qkvxh, g_qkvxh); cudaGetSymbolAddress((void**)&qkvxl, g_qkvxl);
    cudaGetSymbolAddress((void**)&qkvyh, g_qkvyh); cudaGetSymbolAddress((void**)&qkvyl, g_qkvyl);
    cudaGetSymbolAddress((void**)&cxhi,  g_cxhi);  cudaGetSymbolAddress((void**)&cxlo,  g_cxlo);
    cudaGetSymbolAddress((void**)&cyhi,  g_cyhi);  cudaGetSymbolAddress((void**)&cylo,  g_cylo);
    cudaGetSymbolAddress((void**)&whi,   g_whi);   cudaGetSymbolAddress((void**)&wlo,   g_wlo);
    cudaGetSymbolAddress((void**)&bcx,   g_bcx);   cudaGetSymbolAddress((void**)&bcy,   g_bcy);

    // splits + bias concat (batched: 2 kernels + 2 tiny concats)
    {
        const int n4a = PELEMS / 4, n4w = WN / 4;
        dim3 gi((n4a + 255) / 256, 2);
        split_inputs<<<gi, 256>>>(hx, hy, xhi, xlo, yhi, ylo);
        dim3 gw((n4w + 255) / 256, 8);
        split_weights<<<gw, 256>>>(Wf[0], Wf[1], Wf[2], Wf[3],
                                   Wf[4], Wf[5], Wf[6], Wf[7], whi, wlo);
        concat3<<<9, 256>>>(Bf[0], Bf[1], Bf[2], bcx);
        concat3<<<9, 256>>>(Bf[4], Bf[5], Bf[6], bcy);
    }

    cudaFuncSetAttribute(mm_gemm, cudaFuncAttributeMaxDynamicSharedMemorySize,
                         GEMM_SMEM);
    cudaFuncSetAttribute(attn_mma, cudaFuncAttributeMaxDynamicSharedMemorySize,
                         ATT_SMEM);

    // fused QKV projections (N = 2304)
    {
        const dim3 gq(LQKV / 128, PM / 128);    // (18, 64)
        mm_gemm<<<gq, 256, GEMM_SMEM>>>(xhi, xlo, whi + 0 * (size_t)WN,
                                        wlo + 0 * (size_t)WN, bcx,
                                        nullptr, nullptr, nullptr,
                                        qkvxh, qkvxl, PH, LQKV);
        mm_gemm<<<gq, 256, GEMM_SMEM>>>(yhi, ylo, whi + 4 * (size_t)WN,
                                        wlo + 4 * (size_t)WN, bcy,
                                        nullptr, nullptr, nullptr,
                                        qkvyh, qkvyl, PH, LQKV);
    }

    // dual-stream flash attention (64 q-rows per CTA, round-4 shape)
    {
        const dim3 ga(PS / 64, PNH, PB);        // (16, 12, 8)
        attn_mma<<<ga, 128, ATT_SMEM>>>(
            qkvxh, qkvxl,
            qkvxh + PH, qkvxl + PH, qkvxh + 2 * PH, qkvxl + 2 * PH,
            qkvyh + PH, qkvyl + PH, qkvyh + 2 * PH, qkvyl + 2 * PH,
            pw11, pw12, cxhi, cxlo);
        attn_mma<<<ga, 128, ATT_SMEM>>>(
            qkvyh, qkvyl,
            qkvyh + PH, qkvyl + PH, qkvyh + 2 * PH, qkvyl + 2 * PH,
            qkvxh + PH, qkvxl + PH, qkvxh + 2 * PH, qkvxl + 2 * PH,
            pw21, pw22, cyhi, cylo);
    }

    // output projections (bias scaled by w1+w2)
    {
        const dim3 go(PH / 128, PM / 128);      // (6, 64)
        mm_gemm<<<go, 256, GEMM_SMEM>>>(cxhi, cxlo, whi + 3 * (size_t)WN,
                                        wlo + 3 * (size_t)WN, Bf[3],
                                        pw11, pw12, out, nullptr, nullptr, PH, PH);
        mm_gemm<<<go, 256, GEMM_SMEM>>>(cyhi, cylo, whi + 7 * (size_t)WN,
                                        wlo + 7 * (size_t)WN, Bf[7],
                                        pw21, pw22, out + (size_t)PM * PH,
                                        nullptr, nullptr, PH, PH);
    }
}

// round 7
// speedup vs baseline: 1.6567x; 1.0514x over previous
#include <cuda_runtime.h>
#include <cuda_bf16.h>
#include <cstdint>

// Problem constants
#define PB  8
#define PS  1024
#define PH  768
#define PNH 12
#define PDH 64
#define PM  (PB * PS)          // 8192
#define PELEMS (PM * PH)       // 6291456
#define WN  (PH * PH)          // 589824
#define LQKV 2304              // fused q|k|v row stride

// ---------------------------------------------------------------------------
// Scratch (static device globals — no allocation)
// ---------------------------------------------------------------------------
__device__ __nv_bfloat16 g_xhi [PELEMS], g_xlo [PELEMS];
__device__ __nv_bfloat16 g_yhi [PELEMS], g_ylo [PELEMS];
__device__ __nv_bfloat16 g_qkvxh[PM * LQKV], g_qkvxl[PM * LQKV];
__device__ __nv_bfloat16 g_qkvyh[PM * LQKV], g_qkvyl[PM * LQKV];
__device__ __nv_bfloat16 g_cxhi[PELEMS], g_cxlo[PELEMS];
__device__ __nv_bfloat16 g_cyhi[PELEMS], g_cylo[PELEMS];
__device__ __nv_bfloat16 g_whi [8 * WN], g_wlo [8 * WN];
__device__ float g_bcx[LQKV], g_bcy[LQKV];

// ---------------------------------------------------------------------------
// Helpers (sm_80+-portable: ldmatrix + mma.sync + cp.async only)
// ---------------------------------------------------------------------------
__device__ __forceinline__ uint32_t smem_u32(const void* p) {
    uint32_t a;
    asm("{ .reg .u64 t; cvta.to.shared.u64 t, %1; cvt.u32.u64 %0, t; }"
        : "=r"(a) : "l"(p));
    return a;
}

__device__ __forceinline__ void cpasync16(uint32_t dst, const void* src) {
    asm volatile("cp.async.cg.shared.global [%0], [%1], 16;"
                 :: "r"(dst), "l"(src));
}
#define CP_COMMIT() asm volatile("cp.async.commit_group;")
#define CP_WAIT(n)  asm volatile("cp.async.wait_group %0;" :: "n"(n))

__device__ __forceinline__ void ldm4(uint32_t r[4], uint32_t addr) {
    asm volatile("ldmatrix.sync.aligned.m8n8.x4.shared.b16 {%0,%1,%2,%3}, [%4];"
        : "=r"(r[0]), "=r"(r[1]), "=r"(r[2]), "=r"(r[3]) : "r"(addr));
}
__device__ __forceinline__ void ldm4t(uint32_t r[4], uint32_t addr) {
    asm volatile("ldmatrix.sync.aligned.m8n8.x4.trans.shared.b16 {%0,%1,%2,%3}, [%4];"
        : "=r"(r[0]), "=r"(r[1]), "=r"(r[2]), "=r"(r[3]) : "r"(addr));
}

__device__ __forceinline__ void mma16816(float c[4], const uint32_t a[4],
                                         const uint32_t b[2]) {
    asm volatile("mma.sync.aligned.m16n8k16.row.col.f32.bf16.bf16.f32 "
        "{%0,%1,%2,%3}, {%4,%5,%6,%7}, {%8,%9}, {%0,%1,%2,%3};"
        : "+f"(c[0]), "+f"(c[1]), "+f"(c[2]), "+f"(c[3])
        : "r"(a[0]), "r"(a[1]), "r"(a[2]), "r"(a[3]), "r"(b[0]), "r"(b[1]));
}

__device__ __forceinline__ uint32_t packbf(__nv_bfloat16 a, __nv_bfloat16 b) {
    __nv_bfloat162 t(a, b);
    return *(uint32_t*)&t;
}

// ---------------------------------------------------------------------------
// fp32 -> bf16 hi/lo splits (batched) ; bias concatenation
// ---------------------------------------------------------------------------
__device__ __forceinline__ void split4(const float* __restrict__ x,
                                       __nv_bfloat16* __restrict__ hi,
                                       __nv_bfloat16* __restrict__ lo, int i)
{
    float4 v = *(const float4*)(x + (size_t)i * 4);
    __nv_bfloat16 h0 = __float2bfloat16(v.x);
    __nv_bfloat16 h1 = __float2bfloat16(v.y);
    __nv_bfloat16 h2 = __float2bfloat16(v.z);
    __nv_bfloat16 h3 = __float2bfloat16(v.w);
    ((__nv_bfloat162*)hi)[i * 2 + 0] = __nv_bfloat162(h0, h1);
    ((__nv_bfloat162*)hi)[i * 2 + 1] = __nv_bfloat162(h2, h3);
    ((__nv_bfloat162*)lo)[i * 2 + 0] = __nv_bfloat162(
        __float2bfloat16(v.x - __bfloat162float(h0)),
        __float2bfloat16(v.y - __bfloat162float(h1)));
    ((__nv_bfloat162*)lo)[i * 2 + 1] = __nv_bfloat162(
        __float2bfloat16(v.z - __bfloat162float(h2)),
        __float2bfloat16(v.w - __bfloat162float(h3)));
}

__global__ void split_inputs(const float* __restrict__ hx, const float* __restrict__ hy,
                             __nv_bfloat16* __restrict__ xhi, __nv_bfloat16* __restrict__ xlo,
                             __nv_bfloat16* __restrict__ yhi, __nv_bfloat16* __restrict__ ylo)
{
    int i = blockIdx.x * blockDim.x + threadIdx.x;
    if (i >= PELEMS / 4) return;
    if (blockIdx.y == 0) split4(hx, xhi, xlo, i);
    else                 split4(hy, yhi, ylo, i);
}

__global__ void split_weights(const float* w0, const float* w1, const float* w2,
                              const float* w3, const float* w4, const float* w5,
                              const float* w6, const float* w7,
                              __nv_bfloat16* __restrict__ hi,
                              __nv_bfloat16* __restrict__ lo)
{
    int i = blockIdx.x * blockDim.x + threadIdx.x;
    if (i >= WN / 4) return;
    const int s = blockIdx.y;
    const float* src;
    switch (s) {
        case 0: src = w0; break; case 1: src = w1; break;
        case 2: src = w2; break; case 3: src = w3; break;
        case 4: src = w4; break; case 5: src = w5; break;
        case 6: src = w6; break; default: src = w7; break;
    }
    split4(src, hi + (size_t)s * WN, lo + (size_t)s * WN, i);
}

__global__ void concat_biases(const float* __restrict__ a0, const float* __restrict__ a1,
                              const float* __restrict__ a2, float* __restrict__ ox,
                              const float* __restrict__ b0, const float* __restrict__ b1,
                              const float* __restrict__ b2, float* __restrict__ oy)
{
    int i = blockIdx.x * blockDim.x + threadIdx.x;
    const float* s0 = blockIdx.y ? b0 : a0;
    const float* s1 = blockIdx.y ? b1 : a1;
    const float* s2 = blockIdx.y ? b2 : a2;
    float* o = blockIdx.y ? oy : ox;
    if (i < PH) o[i] = s0[i];
    else if (i < 2 * PH) o[i] = s1[i - PH];
    else if (i < 3 * PH) o[i] = s2[i - 2 * PH];
}

// ---------------------------------------------------------------------------
// Split-bf16 GEMM on mma.sync: C[M,N] = A[M,768] @ W[N,768]^T + bscale*bias
// CTA tile 128x128, K-chunk 32, cp.async double-buffered. 256 threads.
// Two problem configs in one launch: blockIdx.y >= 64 selects config 2.
// ---------------------------------------------------------------------------
#define GBK   32
#define GKCH  (PH / GBK)         // 24
#define GSA   40                 // smem row stride bf16 (80B)
#define PLANE_B (128 * GSA * 2)  // 10240
#define STAGE_B (4 * PLANE_B)    // 40960
#define GEMM_SMEM (2 * STAGE_B)  // 81920

__global__ void __launch_bounds__(256)
mm_gemm(const __nv_bfloat16* __restrict__ A1hi, const __nv_bfloat16* __restrict__ A1lo,
        const __nv_bfloat16* __restrict__ W1hi, const __nv_bfloat16* __restrict__ W1lo,
        const float* __restrict__ bias1,
        const float* __restrict__ s1a, const float* __restrict__ s1b,
        float* __restrict__ Cf1,
        __nv_bfloat16* __restrict__ C1hi, __nv_bfloat16* __restrict__ C1lo,
        const __nv_bfloat16* __restrict__ A2hi, const __nv_bfloat16* __restrict__ A2lo,
        const __nv_bfloat16* __restrict__ W2hi, const __nv_bfloat16* __restrict__ W2lo,
        const float* __restrict__ bias2,
        const float* __restrict__ s2a, const float* __restrict__ s2b,
        float* __restrict__ Cf2,
        __nv_bfloat16* __restrict__ C2hi, __nv_bfloat16* __restrict__ C2lo,
        int lda, int ldc)
{
    extern __shared__ char smem[];
    const uint32_t sb = smem_u32(smem);
    const int tid = threadIdx.x;
    const int wid = tid >> 5, lane = tid & 31;
    const int warpM = wid >> 2, warpN = wid & 3;

    int by = blockIdx.y;
    const bool second = (by >= 64);
    if (second) by -= 64;

    const __nv_bfloat16* Ahi  = second ? A2hi  : A1hi;
    const __nv_bfloat16* Alo  = second ? A2lo  : A1lo;
    const __nv_bfloat16* Whi  = second ? W2hi  : W1hi;
    const __nv_bfloat16* Wlo  = second ? W2lo  : W1lo;
    const float* bias         = second ? bias2 : bias1;
    const float* sa           = second ? s2a   : s1a;
    const float* sbv          = second ? s2b   : s1b;
    float* Cf                 = second ? Cf2   : Cf1;
    __nv_bfloat16* Chi        = second ? C2hi  : C1hi;
    __nv_bfloat16* Clo        = second ? C2lo  : C1lo;

    const int row0 = by * 128, col0 = blockIdx.x * 128;

    const __nv_bfloat16* g0 = Ahi + (size_t)row0 * lda;
    const __nv_bfloat16* g1 = Alo + (size_t)row0 * lda;
    const __nv_bfloat16* g2 = Whi + (size_t)col0 * PH;
    const __nv_bfloat16* g3 = Wlo + (size_t)col0 * PH;

    float acc[4][4][4];
    #pragma unroll
    for (int mt = 0; mt < 4; mt++)
        #pragma unroll
        for (int nt = 0; nt < 4; nt++)
            #pragma unroll
            for (int c = 0; c < 4; c++) acc[mt][nt][c] = 0.0f;

    const int arow  = warpM * 64 + (lane & 15);
    const int akh   = lane >> 4;
    const int bkey  = warpN * 32 + (lane & 7) + ((lane >> 4) << 3);
    const int bkh   = (lane >> 3) & 1;

#define G_LOAD(kc, st) do {                                                   \
    const uint32_t dbase = sb + (st) * STAGE_B;                               \
    _Pragma("unroll")                                                         \
    for (int j = 0; j < 2; j++) {                                             \
        const int cc = j * 256 + tid;                                         \
        const int r = cc >> 2, seg = cc & 3;                                  \
        const uint32_t so = r * (GSA * 2) + seg * 16;                         \
        const size_t goA = (size_t)r * lda + (kc) * GBK + seg * 8;            \
        const size_t goW = (size_t)r * PH  + (kc) * GBK + seg * 8;            \
        cpasync16(dbase + 0 * PLANE_B + so, g0 + goA);                        \
        cpasync16(dbase + 1 * PLANE_B + so, g1 + goA);                        \
        cpasync16(dbase + 2 * PLANE_B + so, g2 + goW);                        \
        cpasync16(dbase + 3 * PLANE_B + so, g3 + goW);                        \
    }                                                                         \
} while (0)

    G_LOAD(0, 0);
    CP_COMMIT();

    for (int kc = 0; kc < GKCH; kc++) {
        if (kc + 1 < GKCH) {
            G_LOAD(kc + 1, (kc + 1) & 1);
            CP_COMMIT();
            CP_WAIT(1);
        } else {
            CP_WAIT(0);
        }
        __syncthreads();

        const uint32_t stb = sb + (kc & 1) * STAGE_B;
        #pragma unroll
        for (int ks = 0; ks < 2; ks++) {
            uint32_t ahi[4][4], alo[4][4];
            #pragma unroll
            for (int mt = 0; mt < 4; mt++) {
                const uint32_t addr = stb + (arow + mt * 16) * (GSA * 2)
                                      + ks * 32 + akh * 16;
                ldm4(ahi[mt], addr);
                ldm4(alo[mt], addr + PLANE_B);
            }
            uint32_t bhi[4][2], blo[4][2];
            #pragma unroll
            for (int ntp = 0; ntp < 2; ntp++) {
                const uint32_t addr = stb + 2 * PLANE_B
                                      + (bkey + ntp * 16) * (GSA * 2)
                                      + ks * 32 + bkh * 16;
                uint32_t t[4];
                ldm4(t, addr);
                bhi[2 * ntp][0] = t[0]; bhi[2 * ntp][1] = t[1];
                bhi[2 * ntp + 1][0] = t[2]; bhi[2 * ntp + 1][1] = t[3];
                ldm4(t, addr + PLANE_B);
                blo[2 * ntp][0] = t[0]; blo[2 * ntp][1] = t[1];
                blo[2 * ntp + 1][0] = t[2]; blo[2 * ntp + 1][1] = t[3];
            }
            #pragma unroll
            for (int mt = 0; mt < 4; mt++)
                #pragma unroll
                for (int nt = 0; nt < 4; nt++) {
                    mma16816(acc[mt][nt], ahi[mt], bhi[nt]);
                    mma16816(acc[mt][nt], ahi[mt], blo[nt]);
                    mma16816(acc[mt][nt], alo[mt], bhi[nt]);
                }
        }
        __syncthreads();
    }

    const int g = lane >> 2, tig = lane & 3;
    const float bscale = sa ? (*sa + *sbv) : 1.0f;
    #pragma unroll
    for (int mt = 0; mt < 4; mt++) {
        const int r0 = row0 + warpM * 64 + mt * 16 + g;
        #pragma unroll
        for (int nt = 0; nt < 4; nt++) {
            const int col = col0 + warpN * 32 + nt * 8 + tig * 2;
            const float b0 = bscale * bias[col];
            const float b1 = bscale * bias[col + 1];
            const float v00 = acc[mt][nt][0] + b0, v01 = acc[mt][nt][1] + b1;
            const float v10 = acc[mt][nt][2] + b0, v11 = acc[mt][nt][3] + b1;
            if (Cf) {
                *(float2*)(Cf + (size_t)r0 * ldc + col)       = make_float2(v00, v01);
                *(float2*)(Cf + (size_t)(r0 + 8) * ldc + col) = make_float2(v10, v11);
            }
            if (Chi) {
                __nv_bfloat16 h00 = __float2bfloat16(v00), h01 = __float2bfloat16(v01);
                __nv_bfloat16 h10 = __float2bfloat16(v10), h11 = __float2bfloat16(v11);
                *(__nv_bfloat162*)(Chi + (size_t)r0 * ldc + col) = __nv_bfloat162(h00, h01);
                *(__nv_bfloat162*)(Chi + (size_t)(r0 + 8) * ldc + col) = __nv_bfloat162(h10, h11);
                *(__nv_bfloat162*)(Clo + (size_t)r0 * ldc + col) = __nv_bfloat162(
                    __float2bfloat16(v00 - __bfloat162float(h00)),
                    __float2bfloat16(v01 - __bfloat162float(h01)));
                *(__nv_bfloat162*)(Clo + (size_t)(r0 + 8) * ldc + col) = __nv_bfloat162(
                    __float2bfloat16(v10 - __bfloat162float(h10)),
                    __float2bfloat16(v11 - __bfloat162float(h11)));
            }
        }
    }
}

// ---------------------------------------------------------------------------
// Dual-stream flash attention on mma.sync, BOTH outputs in ONE launch.
// blockIdx.x & 1 selects the output stream (cx or cy); adjacent CTAs stream
// through identical KV tiles in the same phase order -> L2 traffic halves.
// Per-CTA shape unchanged from round 6: 64 q-rows, 4 warps, 55KB smem.
// Phase s=0 reads x-KV, phase s=1 reads y-KV for BOTH variants:
//   st=0: cx = w11*attend(qx,Kx,Vx)[s0] + w12*attend(qx,Ky,Vy)[s1]
//   st=1: cy = w22*attend(qy,Kx,Vx)[s0] + w21*attend(qy,Ky,Vy)[s1]
// ---------------------------------------------------------------------------
#define AST     72                    // bf16 row stride (144B)
#define ROWB    (AST * 2)             // 144
#define ATILE_B (64 * ROWB)           // 9216
#define ATT_SMEM (6 * ATILE_B)        // 55296  [qh][ql][kh][kl][vh][vl]

__global__ void __launch_bounds__(128)
attn_mma(const __nv_bfloat16* __restrict__ qkvxh, const __nv_bfloat16* __restrict__ qkvxl,
         const __nv_bfloat16* __restrict__ qkvyh, const __nv_bfloat16* __restrict__ qkvyl,
         const float* __restrict__ pw11, const float* __restrict__ pw12,
         const float* __restrict__ pw21, const float* __restrict__ pw22,
         __nv_bfloat16* __restrict__ cxh, __nv_bfloat16* __restrict__ cxl,
         __nv_bfloat16* __restrict__ cyh, __nv_bfloat16* __restrict__ cyl)
{
    extern __shared__ char smem[];
    const uint32_t sb = smem_u32(smem);
    const uint32_t kh_s = sb + 2 * ATILE_B;
    const uint32_t vh_s = sb + 4 * ATILE_B;

    const int st = blockIdx.x & 1;
    const int qt = blockIdx.x >> 1;
    const int h = blockIdx.y, b = blockIdx.z;
    const int tid = threadIdx.x, wid = tid >> 5, lane = tid & 31;
    const int g = lane >> 2, tig = lane & 3;

    const __nv_bfloat16* Qh = st ? qkvyh : qkvxh;
    const __nv_bfloat16* Ql = st ? qkvyl : qkvxl;
    // phase 0 = x-KV, phase 1 = y-KV (identical order for both st)
    const __nv_bfloat16* const KH[2] = { qkvxh + PH, qkvyh + PH };
    const __nv_bfloat16* const KL[2] = { qkvxl + PH, qkvyl + PH };
    const __nv_bfloat16* const VH[2] = { qkvxh + 2 * PH, qkvyh + 2 * PH };
    const __nv_bfloat16* const VL[2] = { qkvxl + 2 * PH, qkvyl + 2 * PH };
    const float ws0 = st ? *pw22 : *pw11;   // weight for phase-0 attend
    const float ws1 = st ? *pw21 : *pw12;   // weight for phase-1 attend
    __nv_bfloat16* ctxh = st ? cyh : cxh;
    __nv_bfloat16* ctxl = st ? cyl : cxl;

    // --- load Q tile (hi/lo) via cp.async ---
    #pragma unroll
    for (int j = 0; j < 4; j++) {
        const int cc = j * 128 + tid;        // 512 chunks per plane
        const int r = cc >> 3, seg = cc & 7;
        const size_t go = (size_t)(b * PS + qt * 64 + r) * LQKV + h * PDH + seg * 8;
        const uint32_t so = r * ROWB + seg * 16;
        cpasync16(sb + so,           Qh + go);
        cpasync16(sb + ATILE_B + so, Ql + go);
    }
    CP_COMMIT();
    CP_WAIT(0);
    __syncthreads();

    // --- Q fragments (held in registers for both phases) ---
    uint32_t qfh[4][4], qfl[4][4];
    {
        const int qrow = wid * 16 + (lane & 15);
        const int khalf = lane >> 4;
        #pragma unroll
        for (int ks = 0; ks < 4; ks++) {
            const uint32_t addr = sb + qrow * ROWB + ks * 32 + khalf * 16;
            ldm4(qfh[ks], addr);
            ldm4(qfl[ks], addr + ATILE_B);
        }
    }

    const int bkey = (lane & 7) + ((lane >> 4) << 3);        // QK B-frag lane row
    const int bkh  = (lane >> 3) & 1;
    const int vkey = (lane & 7) + (((lane >> 3) & 1) << 3);  // PV B-frag lane row
    const int vdh  = (lane >> 4) << 3;

    float ostash[8][4];

    for (int s = 0; s < 2; s++) {
        const __nv_bfloat16* Kh_ = KH[s];
        const __nv_bfloat16* Kl_ = KL[s];
        const __nv_bfloat16* Vh_ = VH[s];
        const __nv_bfloat16* Vl_ = VL[s];

        float m[2] = { -1e30f, -1e30f }, l[2] = { 0.0f, 0.0f };
        float oacc[8][4];
        #pragma unroll
        for (int nt = 0; nt < 8; nt++)
            #pragma unroll
            for (int c = 0; c < 4; c++) oacc[nt][c] = 0.0f;

        for (int kt = 0; kt < PS / 64; kt++) {
            __syncthreads();
            #pragma unroll
            for (int j = 0; j < 4; j++) {
                const int cc = j * 128 + tid;
                const int r = cc >> 3, seg = cc & 7;
                const size_t go = (size_t)(b * PS + kt * 64 + r) * LQKV + h * PDH + seg * 8;
                const uint32_t so = r * ROWB + seg * 16;
                cpasync16(sb + 2 * ATILE_B + so, Kh_ + go);
                cpasync16(sb + 3 * ATILE_B + so, Kl_ + go);
                cpasync16(sb + 4 * ATILE_B + so, Vh_ + go);
                cpasync16(sb + 5 * ATILE_B + so, Vl_ + go);
            }
            CP_COMMIT();
            CP_WAIT(0);
            __syncthreads();

            // --- scores S = Q @ K^T (split 3-mma) ---
            float sacc[8][4];
            #pragma unroll
            for (int nt = 0; nt < 8; nt++)
                #pragma unroll
                for (int c = 0; c < 4; c++) sacc[nt][c] = 0.0f;

            #pragma unroll
            for (int ks = 0; ks < 4; ks++) {
                #pragma unroll
                for (int ntp = 0; ntp < 4; ntp++) {
                    const uint32_t addr = kh_s + (ntp * 16 + bkey) * ROWB
                                          + ks * 32 + bkh * 16;
                    uint32_t th[4], tl[4];
                    ldm4(th, addr);
                    ldm4(tl, addr + ATILE_B);
                    const uint32_t b0h[2] = { th[0], th[1] }, b1h[2] = { th[2], th[3] };
                    const uint32_t b0l[2] = { tl[0], tl[1] }, b1l[2] = { tl[2], tl[3] };
                    mma16816(sacc[2 * ntp],     qfh[ks], b0h);
                    mma16816(sacc[2 * ntp],     qfh[ks], b0l);
                    mma16816(sacc[2 * ntp],     qfl[ks], b0h);
                    mma16816(sacc[2 * ntp + 1], qfh[ks], b1h);
                    mma16816(sacc[2 * ntp + 1], qfh[ks], b1l);
                    mma16816(sacc[2 * ntp + 1], qfl[ks], b1h);
                }
            }

            // --- online softmax (rows g and g+8) ---
            #pragma unroll
            for (int nt = 0; nt < 8; nt++)
                #pragma unroll
                for (int c = 0; c < 4; c++) sacc[nt][c] *= 0.125f;

            #pragma unroll
            for (int half = 0; half < 2; half++) {
                float mx = -1e30f;
                #pragma unroll
                for (int nt = 0; nt < 8; nt++)
                    mx = fmaxf(mx, fmaxf(sacc[nt][2 * half], sacc[nt][2 * half + 1]));
                mx = fmaxf(mx, __shfl_xor_sync(0xffffffffu, mx, 1));
                mx = fmaxf(mx, __shfl_xor_sync(0xffffffffu, mx, 2));
                const float mn = fmaxf(m[half], mx);
                const float corr = __expf(m[half] - mn);
                m[half] = mn;
                float rs = 0.0f;
                #pragma unroll
                for (int nt = 0; nt < 8; nt++) {
                    const float p0 = __expf(sacc[nt][2 * half] - mn);
                    const float p1 = __expf(sacc[nt][2 * half + 1] - mn);
                    sacc[nt][2 * half] = p0;
                    sacc[nt][2 * half + 1] = p1;
                    rs += p0 + p1;
                }
                rs += __shfl_xor_sync(0xffffffffu, rs, 1);
                rs += __shfl_xor_sync(0xffffffffu, rs, 2);
                l[half] = l[half] * corr + rs;
                #pragma unroll
                for (int nt = 0; nt < 8; nt++) {
                    oacc[nt][2 * half]     *= corr;
                    oacc[nt][2 * half + 1] *= corr;
                }
            }

            // --- pack P into bf16 hi/lo A-fragments ---
            uint32_t ph[8][2], pl[8][2];
            #pragma unroll
            for (int nt = 0; nt < 8; nt++) {
                #pragma unroll
                for (int half = 0; half < 2; half++) {
                    const float p0 = sacc[nt][2 * half], p1 = sacc[nt][2 * half + 1];
                    const __nv_bfloat16 h0 = __float2bfloat16(p0);
                    const __nv_bfloat16 h1 = __float2bfloat16(p1);
                    ph[nt][half] = packbf(h0, h1);
                    pl[nt][half] = packbf(__float2bfloat16(p0 - __bfloat162float(h0)),
                                          __float2bfloat16(p1 - __bfloat162float(h1)));
                }
            }

            // --- O += P @ V (split 3-mma, V^T via trans ldmatrix) ---
            #pragma unroll
            for (int ks = 0; ks < 4; ks++) {
                const uint32_t pah[4] = { ph[2 * ks][0], ph[2 * ks][1],
                                          ph[2 * ks + 1][0], ph[2 * ks + 1][1] };
                const uint32_t pal[4] = { pl[2 * ks][0], pl[2 * ks][1],
                                          pl[2 * ks + 1][0], pl[2 * ks + 1][1] };
                #pragma unroll
                for (int dhp = 0; dhp < 4; dhp++) {
                    const uint32_t addr = vh_s + (ks * 16 + vkey) * ROWB
                                          + (dhp * 16 + vdh) * 2;
                    uint32_t th[4], tl[4];
                    ldm4t(th, addr);
                    ldm4t(tl, addr + ATILE_B);
                    const uint32_t b0h[2] = { th[0], th[1] }, b1h[2] = { th[2], th[3] };
                    const uint32_t b0l[2] = { tl[0], tl[1] }, b1l[2] = { tl[2], tl[3] };
                    mma16816(oacc[2 * dhp],     pah, b0h);
                    mma16816(oacc[2 * dhp],     pah, b0l);
                    mma16816(oacc[2 * dhp],     pal, b0h);
                    mma16816(oacc[2 * dhp + 1], pah, b1h);
                    mma16816(oacc[2 * dhp + 1], pah, b1l);
                    mma16816(oacc[2 * dhp + 1], pal, b1h);
                }
            }
        }

        if (s == 0) {
            const float i0 = ws0 / l[0], i1 = ws0 / l[1];
            #pragma unroll
            for (int nt = 0; nt < 8; nt++) {
                ostash[nt][0] = oacc[nt][0] * i0;
                ostash[nt][1] = oacc[nt][1] * i0;
                ostash[nt][2] = oacc[nt][2] * i1;
                ostash[nt][3] = oacc[nt][3] * i1;
            }
        } else {
            const float i0 = ws1 / l[0], i1 = ws1 / l[1];
            const int r0 = qt * 64 + wid * 16 + g;
            #pragma unroll
            for (int nt = 0; nt < 8; nt++) {
                const int col = h * PDH + nt * 8 + tig * 2;
                const float v00 = ostash[nt][0] + oacc[nt][0] * i0;
                const float v01 = ostash[nt][1] + oacc[nt][1] * i0;
                const float v10 = ostash[nt][2] + oacc[nt][2] * i1;
                const float v11 = ostash[nt][3] + oacc[nt][3] * i1;
                const size_t o0 = (size_t)(b * PS + r0) * PH + col;
                const size_t o1 = (size_t)(b * PS + r0 + 8) * PH + col;
                const __nv_bfloat16 h00 = __float2bfloat16(v00);
                const __nv_bfloat16 h01 = __float2bfloat16(v01);
                const __nv_bfloat16 h10 = __float2bfloat16(v10);
                const __nv_bfloat16 h11 = __float2bfloat16(v11);
                *(__nv_bfloat162*)(ctxh + o0) = __nv_bfloat162(h00, h01);
                *(__nv_bfloat162*)(ctxh + o1) = __nv_bfloat162(h10, h11);
                *(__nv_bfloat162*)(ctxl + o0) = __nv_bfloat162(
                    __float2bfloat16(v00 - __bfloat162float(h00)),
                    __float2bfloat16(v01 - __bfloat162float(h01)));
                *(__nv_bfloat162*)(ctxl + o1) = __nv_bfloat162(
                    __float2bfloat16(v10 - __bfloat162float(h10)),
                    __float2bfloat16(v11 - __bfloat162float(h11)));
            }
        }
    }
}

// ---------------------------------------------------------------------------
// Launch
// ---------------------------------------------------------------------------
extern "C" void kernel_launch(void* const* d_in, const int* in_sizes, int n_in,
                              void* d_out, int out_size)
{
    const float* hx = (const float*)d_in[0];
    const float* hy = (const float*)d_in[1];
    const float* Wf[8] = { (const float*)d_in[2],  (const float*)d_in[4],
                           (const float*)d_in[6],  (const float*)d_in[8],
                           (const float*)d_in[10], (const float*)d_in[12],
                           (const float*)d_in[14], (const float*)d_in[16] };
    const float* Bf[8] = { (const float*)d_in[3],  (const float*)d_in[5],
                           (const float*)d_in[7],  (const float*)d_in[9],
                           (const float*)d_in[11], (const float*)d_in[13],
                           (const float*)d_in[15], (const float*)d_in[17] };
    // order: 0=q 1=k 2=v 3=o 4=qd 5=kd 6=vd 7=od
    const float* pw11 = (const float*)d_in[18];
    const float* pw12 = (const float*)d_in[19];
    const float* pw21 = (const float*)d_in[20];
    const float* pw22 = (const float*)d_in[21];
    float* out = (float*)d_out;

    __nv_bfloat16 *xhi, *xlo, *yhi, *ylo;
    __nv_bfloat16 *qkvxh, *qkvxl, *qkvyh, *qkvyl;
    __nv_bfloat16 *cxhi, *cxlo, *cyhi, *cylo, *whi, *wlo;
    float *bcx, *bcy;
    cudaGetSymbolAddress((void**)&xhi,   g_xhi);   cudaGetSymbolAddress((void**)&xlo,   g_xlo);
    cudaGetSymbolAddress((void**)&yhi,   g_yhi);   cudaGetSymbolAddress((void**)&ylo,   g_ylo);
    cudaGetSymbolAddress((void**)&qkvxh, g_qkvxh); cudaGetSymbolAddress((void**)&qkvxl, g_qkvxl);
    cudaGetSymbolAddress((void**)&qkvyh, g_qkvyh); cudaGetSymbolAddress((void**)&qkvyl, g_qkvyl);
    cudaGetSymbolAddress((void**)&cxhi,  g_cxhi);  cudaGetSymbolAddress((void**)&cxlo,  g_cxlo);
    cudaGetSymbolAddress((void**)&cyhi,  g_cyhi);  cudaGetSymbolAddress((void**)&cylo,  g_cylo);
    cudaGetSymbolAddress((void**)&whi,   g_whi);   cudaGetSymbolAddress((void**)&wlo,   g_wlo);
    cudaGetSymbolAddress((void**)&bcx,   g_bcx);   cudaGetSymbolAddress((void**)&bcy,   g_bcy);

    // splits + bias concat (batched)
    {
        const int n4a = PELEMS / 4, n4w = WN / 4;
        dim3 gi((n4a + 255) / 256, 2);
        split_inputs<<<gi, 256>>>(hx, hy, xhi, xlo, yhi, ylo);
        dim3 gw((n4w + 255) / 256, 8);
        split_weights<<<gw, 256>>>(Wf[0], Wf[1], Wf[2], Wf[3],
                                   Wf[4], Wf[5], Wf[6], Wf[7], whi, wlo);
        concat_biases<<<dim3(9, 2), 256>>>(Bf[0], Bf[1], Bf[2], bcx,
                                           Bf[4], Bf[5], Bf[6], bcy);
    }

    cudaFuncSetAttribute(mm_gemm, cudaFuncAttributeMaxDynamicSharedMemorySize,
                         GEMM_SMEM);
    cudaFuncSetAttribute(attn_mma, cudaFuncAttributeMaxDynamicSharedMemorySize,
                         ATT_SMEM);

    // fused QKV projections for BOTH streams in one launch (N = 2304)
    {
        const dim3 gq(LQKV / 128, 2 * (PM / 128));    // (18, 128)
        mm_gemm<<<gq, 256, GEMM_SMEM>>>(
            xhi, xlo, whi + 0 * (size_t)WN, wlo + 0 * (size_t)WN, bcx,
            nullptr, nullptr, nullptr, qkvxh, qkvxl,
            yhi, ylo, whi + 4 * (size_t)WN, wlo + 4 * (size_t)WN, bcy,
            nullptr, nullptr, nullptr, qkvyh, qkvyl,
            PH, LQKV);
    }

    // dual-stream flash attention, both outputs in one launch
    {
        const dim3 ga(2 * (PS / 64), PNH, PB);        // (32, 12, 8)
        attn_mma<<<ga, 128, ATT_SMEM>>>(qkvxh, qkvxl, qkvyh, qkvyl,
                                        pw11, pw12, pw21, pw22,
                                        cxhi, cxlo, cyhi, cylo);
    }

    // output projections for BOTH streams in one launch
    {
        const dim3 go(PH / 128, 2 * (PM / 128));      // (6, 128)
        mm_gemm<<<go, 256, GEMM_SMEM>>>(
            cxhi, cxlo, whi + 3 * (size_t)WN, wlo + 3 * (size_t)WN, Bf[3],
            pw11, pw12, out, nullptr, nullptr,
            cyhi, cylo, whi + 7 * (size_t)WN, wlo + 7 * (size_t)WN, Bf[7],
            pw21, pw22, out + (size_t)PM * PH, nullptr, nullptr,
            PH, PH);
    }
}

// round 9
// speedup vs baseline: 2.2091x; 1.3335x over previous
#include <cuda_runtime.h>
#include <cuda_fp16.h>
#include <cstdint>

// Problem constants
#define PB  8
#define PS  1024
#define PH  768
#define PNH 12
#define PDH 64
#define PM  (PB * PS)          // 8192
#define PELEMS (PM * PH)       // 6291456
#define WN  (PH * PH)          // 589824
#define LQKV 2304              // fused q|k|v row stride

// ---------------------------------------------------------------------------
// Scratch (static device globals — no allocation)
// ---------------------------------------------------------------------------
__device__ __half g_xh [PELEMS];
__device__ __half g_yh [PELEMS];
__device__ __half g_qkvxh[PM * LQKV], g_qkvxl[PM * LQKV];
__device__ __half g_qkvyh[PM * LQKV], g_qkvyl[PM * LQKV];
__device__ __half g_cxh[PELEMS];
__device__ __half g_cyh[PELEMS];
__device__ __half g_whi[8 * WN], g_wlo[8 * WN];
__device__ float g_bcx[LQKV], g_bcy[LQKV];

// ---------------------------------------------------------------------------
// Helpers (sm_80+-portable: ldmatrix + mma.sync + cp.async only)
// ---------------------------------------------------------------------------
__device__ __forceinline__ uint32_t smem_u32(const void* p) {
    uint32_t a;
    asm("{ .reg .u64 t; cvta.to.shared.u64 t, %1; cvt.u32.u64 %0, t; }"
        : "=r"(a) : "l"(p));
    return a;
}

__device__ __forceinline__ void cpasync16(uint32_t dst, const void* src) {
    asm volatile("cp.async.cg.shared.global [%0], [%1], 16;"
                 :: "r"(dst), "l"(src));
}
#define CP_COMMIT() asm volatile("cp.async.commit_group;")
#define CP_WAIT(n)  asm volatile("cp.async.wait_group %0;" :: "n"(n))

__device__ __forceinline__ void ldm4(uint32_t r[4], uint32_t addr) {
    asm volatile("ldmatrix.sync.aligned.m8n8.x4.shared.b16 {%0,%1,%2,%3}, [%4];"
        : "=r"(r[0]), "=r"(r[1]), "=r"(r[2]), "=r"(r[3]) : "r"(addr));
}
__device__ __forceinline__ void ldm4t(uint32_t r[4], uint32_t addr) {
    asm volatile("ldmatrix.sync.aligned.m8n8.x4.trans.shared.b16 {%0,%1,%2,%3}, [%4];"
        : "=r"(r[0]), "=r"(r[1]), "=r"(r[2]), "=r"(r[3]) : "r"(addr));
}

__device__ __forceinline__ void mma16816(float c[4], const uint32_t a[4],
                                         const uint32_t b[2]) {
    asm volatile("mma.sync.aligned.m16n8k16.row.col.f32.f16.f16.f32 "
        "{%0,%1,%2,%3}, {%4,%5,%6,%7}, {%8,%9}, {%0,%1,%2,%3};"
        : "+f"(c[0]), "+f"(c[1]), "+f"(c[2]), "+f"(c[3])
        : "r"(a[0]), "r"(a[1]), "r"(a[2]), "r"(a[3]), "r"(b[0]), "r"(b[1]));
}

__device__ __forceinline__ uint32_t packh(__half a, __half b) {
    __half2 t = __halves2half2(a, b);
    return *(uint32_t*)&t;
}

// ---------------------------------------------------------------------------
// fp32 -> fp16 conversions / hi+lo splits (batched) ; bias concatenation
// ---------------------------------------------------------------------------
__global__ void cvt_inputs(const float* __restrict__ hx, const float* __restrict__ hy,
                           __half* __restrict__ xh, __half* __restrict__ yh)
{
    int i = blockIdx.x * blockDim.x + threadIdx.x;
    if (i >= PELEMS / 4) return;
    const float* src = blockIdx.y ? hy : hx;
    __half* dst = blockIdx.y ? yh : xh;
    float4 v = *(const float4*)(src + (size_t)i * 4);
    ((__half2*)dst)[i * 2 + 0] = __halves2half2(__float2half_rn(v.x), __float2half_rn(v.y));
    ((__half2*)dst)[i * 2 + 1] = __halves2half2(__float2half_rn(v.z), __float2half_rn(v.w));
}

__global__ void split_weights(const float* w0, const float* w1, const float* w2,
                              const float* w3, const float* w4, const float* w5,
                              const float* w6, const float* w7,
                              __half* __restrict__ hi, __half* __restrict__ lo)
{
    int i = blockIdx.x * blockDim.x + threadIdx.x;
    if (i >= WN / 4) return;
    const int s = blockIdx.y;
    const float* src;
    switch (s) {
        case 0: src = w0; break; case 1: src = w1; break;
        case 2: src = w2; break; case 3: src = w3; break;
        case 4: src = w4; break; case 5: src = w5; break;
        case 6: src = w6; break; default: src = w7; break;
    }
    float4 v = *(const float4*)(src + (size_t)i * 4);
    __half h0 = __float2half_rn(v.x), h1 = __float2half_rn(v.y);
    __half h2 = __float2half_rn(v.z), h3 = __float2half_rn(v.w);
    __half2* ph = (__half2*)(hi + (size_t)s * WN);
    __half2* pl = (__half2*)(lo + (size_t)s * WN);
    ph[i * 2 + 0] = __halves2half2(h0, h1);
    ph[i * 2 + 1] = __halves2half2(h2, h3);
    pl[i * 2 + 0] = __halves2half2(__float2half_rn(v.x - __half2float(h0)),
                                   __float2half_rn(v.y - __half2float(h1)));
    pl[i * 2 + 1] = __halves2half2(__float2half_rn(v.z - __half2float(h2)),
                                   __float2half_rn(v.w - __half2float(h3)));
}

__global__ void concat_biases(const float* __restrict__ a0, const float* __restrict__ a1,
                              const float* __restrict__ a2, float* __restrict__ ox,
                              const float* __restrict__ b0, const float* __restrict__ b1,
                              const float* __restrict__ b2, float* __restrict__ oy)
{
    int i = blockIdx.x * blockDim.x + threadIdx.x;
    const float* s0 = blockIdx.y ? b0 : a0;
    const float* s1 = blockIdx.y ? b1 : a1;
    const float* s2 = blockIdx.y ? b2 : a2;
    float* o = blockIdx.y ? oy : ox;
    if (i < PH) o[i] = s0[i];
    else if (i < 2 * PH) o[i] = s1[i - PH];
    else if (i < 3 * PH) o[i] = s2[i - 2 * PH];
}

// ---------------------------------------------------------------------------
// fp16 2-MMA GEMM: C[M,N] = A[M,768] @ (Whi+Wlo)[N,768]^T + bscale*bias
// A single fp16 plane; W split hi/lo. CTA tile 128x128, K-chunk 32,
// cp.async double-buffered, 256 threads. Dual-config dispatch on blockIdx.y.
// ---------------------------------------------------------------------------
#define GBK   32
#define GKCH  (PH / GBK)         // 24
#define GSA   40                 // smem row stride fp16 (80B)
#define PLANE_B (128 * GSA * 2)  // 10240
#define STAGE_B (3 * PLANE_B)    // 30720  [A][Whi][Wlo]
#define GEMM_SMEM (2 * STAGE_B)  // 61440

__global__ void __launch_bounds__(256)
mm_gemm(const __half* __restrict__ A1, const __half* __restrict__ W1hi,
        const __half* __restrict__ W1lo, const float* __restrict__ bias1,
        const float* __restrict__ s1a, const float* __restrict__ s1b,
        float* __restrict__ Cf1,
        __half* __restrict__ C1hi, __half* __restrict__ C1lo,
        const __half* __restrict__ A2, const __half* __restrict__ W2hi,
        const __half* __restrict__ W2lo, const float* __restrict__ bias2,
        const float* __restrict__ s2a, const float* __restrict__ s2b,
        float* __restrict__ Cf2,
        __half* __restrict__ C2hi, __half* __restrict__ C2lo,
        int lda, int ldc)
{
    extern __shared__ char smem[];
    const uint32_t sb = smem_u32(smem);
    const int tid = threadIdx.x;
    const int wid = tid >> 5, lane = tid & 31;
    const int warpM = wid >> 2, warpN = wid & 3;

    int by = blockIdx.y;
    const bool second = (by >= 64);
    if (second) by -= 64;

    const __half* A        = second ? A2    : A1;
    const __half* Whi      = second ? W2hi  : W1hi;
    const __half* Wlo      = second ? W2lo  : W1lo;
    const float* bias      = second ? bias2 : bias1;
    const float* sa        = second ? s2a   : s1a;
    const float* sbv       = second ? s2b   : s1b;
    float* Cf              = second ? Cf2   : Cf1;
    __half* Chi            = second ? C2hi  : C1hi;
    __half* Clo            = second ? C2lo  : C1lo;

    const int row0 = by * 128, col0 = blockIdx.x * 128;

    const __half* g0 = A   + (size_t)row0 * lda;
    const __half* g2 = Whi + (size_t)col0 * PH;
    const __half* g3 = Wlo + (size_t)col0 * PH;

    float acc[4][4][4];
    #pragma unroll
    for (int mt = 0; mt < 4; mt++)
        #pragma unroll
        for (int nt = 0; nt < 4; nt++)
            #pragma unroll
            for (int c = 0; c < 4; c++) acc[mt][nt][c] = 0.0f;

    const int arow  = warpM * 64 + (lane & 15);
    const int akh   = lane >> 4;
    const int bkey  = warpN * 32 + (lane & 7) + ((lane >> 4) << 3);
    const int bkh   = (lane >> 3) & 1;

#define G_LOAD(kc, st) do {                                                   \
    const uint32_t dbase = sb + (st) * STAGE_B;                               \
    _Pragma("unroll")                                                         \
    for (int j = 0; j < 2; j++) {                                             \
        const int cc = j * 256 + tid;                                         \
        const int r = cc >> 2, seg = cc & 3;                                  \
        const uint32_t so = r * (GSA * 2) + seg * 16;                         \
        const size_t goA = (size_t)r * lda + (kc) * GBK + seg * 8;            \
        const size_t goW = (size_t)r * PH  + (kc) * GBK + seg * 8;            \
        cpasync16(dbase + 0 * PLANE_B + so, g0 + goA);                        \
        cpasync16(dbase + 1 * PLANE_B + so, g2 + goW);                        \
        cpasync16(dbase + 2 * PLANE_B + so, g3 + goW);                        \
    }                                                                         \
} while (0)

    G_LOAD(0, 0);
    CP_COMMIT();

    for (int kc = 0; kc < GKCH; kc++) {
        if (kc + 1 < GKCH) {
            G_LOAD(kc + 1, (kc + 1) & 1);
            CP_COMMIT();
            CP_WAIT(1);
        } else {
            CP_WAIT(0);
        }
        __syncthreads();

        const uint32_t stb = sb + (kc & 1) * STAGE_B;
        #pragma unroll
        for (int ks = 0; ks < 2; ks++) {
            uint32_t af[4][4];
            #pragma unroll
            for (int mt = 0; mt < 4; mt++)
                ldm4(af[mt], stb + (arow + mt * 16) * (GSA * 2) + ks * 32 + akh * 16);
            uint32_t bhi[4][2], blo[4][2];
            #pragma unroll
            for (int ntp = 0; ntp < 2; ntp++) {
                const uint32_t addr = stb + PLANE_B
                                      + (bkey + ntp * 16) * (GSA * 2)
                                      + ks * 32 + bkh * 16;
                uint32_t t[4];
                ldm4(t, addr);
                bhi[2 * ntp][0] = t[0]; bhi[2 * ntp][1] = t[1];
                bhi[2 * ntp + 1][0] = t[2]; bhi[2 * ntp + 1][1] = t[3];
                ldm4(t, addr + PLANE_B);
                blo[2 * ntp][0] = t[0]; blo[2 * ntp][1] = t[1];
                blo[2 * ntp + 1][0] = t[2]; blo[2 * ntp + 1][1] = t[3];
            }
            #pragma unroll
            for (int mt = 0; mt < 4; mt++)
                #pragma unroll
                for (int nt = 0; nt < 4; nt++) {
                    mma16816(acc[mt][nt], af[mt], bhi[nt]);
                    mma16816(acc[mt][nt], af[mt], blo[nt]);
                }
        }
        __syncthreads();
    }

    const int g = lane >> 2, tig = lane & 3;
    const float bscale = sa ? (*sa + *sbv) : 1.0f;
    #pragma unroll
    for (int mt = 0; mt < 4; mt++) {
        const int r0 = row0 + warpM * 64 + mt * 16 + g;
        #pragma unroll
        for (int nt = 0; nt < 4; nt++) {
            const int col = col0 + warpN * 32 + nt * 8 + tig * 2;
            const float b0 = bscale * bias[col];
            const float b1 = bscale * bias[col + 1];
            const float v00 = acc[mt][nt][0] + b0, v01 = acc[mt][nt][1] + b1;
            const float v10 = acc[mt][nt][2] + b0, v11 = acc[mt][nt][3] + b1;
            if (Cf) {
                *(float2*)(Cf + (size_t)r0 * ldc + col)       = make_float2(v00, v01);
                *(float2*)(Cf + (size_t)(r0 + 8) * ldc + col) = make_float2(v10, v11);
            }
            if (Chi) {
                __half h00 = __float2half_rn(v00), h01 = __float2half_rn(v01);
                __half h10 = __float2half_rn(v10), h11 = __float2half_rn(v11);
                *(__half2*)(Chi + (size_t)r0 * ldc + col) = __halves2half2(h00, h01);
                *(__half2*)(Chi + (size_t)(r0 + 8) * ldc + col) = __halves2half2(h10, h11);
                *(__half2*)(Clo + (size_t)r0 * ldc + col) = __halves2half2(
                    __float2half_rn(v00 - __half2float(h00)),
                    __float2half_rn(v01 - __half2float(h01)));
                *(__half2*)(Clo + (size_t)(r0 + 8) * ldc + col) = __halves2half2(
                    __float2half_rn(v10 - __half2float(h10)),
                    __float2half_rn(v11 - __half2float(h11)));
            }
        }
    }
}

// ---------------------------------------------------------------------------
// Dual-stream flash attention, fp16 2-MMA, both outputs in one launch.
// blockIdx.x&1 selects output stream; adjacent CTAs share KV tiles in L2.
// 64 q-rows, 4 warps, base-2 softmax. Q single plane; K/V hi+lo.
//   st=0: cx = w11*attend(qx,Kx,Vx)[s0] + w12*attend(qx,Ky,Vy)[s1]
//   st=1: cy = w22*attend(qy,Kx,Vx)[s0] + w21*attend(qy,Ky,Vy)[s1]
// ---------------------------------------------------------------------------
#define AST     72                    // fp16 row stride (144B)
#define ROWB    (AST * 2)             // 144
#define ATILE_B (64 * ROWB)           // 9216
#define ATT_SMEM (5 * ATILE_B)        // 46080  [q][kh][kl][vh][vl]
#define SC2     0.1803368801f         // 0.125 * log2(e)

__global__ void __launch_bounds__(128)
attn_mma(const __half* __restrict__ qkvxh, const __half* __restrict__ qkvxl,
         const __half* __restrict__ qkvyh, const __half* __restrict__ qkvyl,
         const float* __restrict__ pw11, const float* __restrict__ pw12,
         const float* __restrict__ pw21, const float* __restrict__ pw22,
         __half* __restrict__ cxh, __half* __restrict__ cyh)
{
    extern __shared__ char smem[];
    const uint32_t sb = smem_u32(smem);
    const uint32_t kh_s = sb + 1 * ATILE_B;
    const uint32_t vh_s = sb + 3 * ATILE_B;

    const int st = blockIdx.x & 1;
    const int qt = blockIdx.x >> 1;
    const int h = blockIdx.y, b = blockIdx.z;
    const int tid = threadIdx.x, wid = tid >> 5, lane = tid & 31;
    const int g = lane >> 2, tig = lane & 3;

    const __half* Qh = st ? qkvyh : qkvxh;
    // phase 0 = x-KV, phase 1 = y-KV (identical order for both st)
    const __half* const KH[2] = { qkvxh + PH, qkvyh + PH };
    const __half* const KL[2] = { qkvxl + PH, qkvyl + PH };
    const __half* const VH[2] = { qkvxh + 2 * PH, qkvyh + 2 * PH };
    const __half* const VL[2] = { qkvxl + 2 * PH, qkvyl + 2 * PH };
    const float ws0 = st ? *pw22 : *pw11;
    const float ws1 = st ? *pw21 : *pw12;
    __half* ctx = st ? cyh : cxh;

    // --- load Q tile (single plane) via cp.async ---
    #pragma unroll
    for (int j = 0; j < 4; j++) {
        const int cc = j * 128 + tid;        // 512 chunks
        const int r = cc >> 3, seg = cc & 7;
        const size_t go = (size_t)(b * PS + qt * 64 + r) * LQKV + h * PDH + seg * 8;
        cpasync16(sb + r * ROWB + seg * 16, Qh + go);
    }
    CP_COMMIT();
    CP_WAIT(0);
    __syncthreads();

    // --- Q fragments (registers, reused across phases) ---
    uint32_t qf[4][4];
    {
        const int qrow = wid * 16 + (lane & 15);
        const int khalf = lane >> 4;
        #pragma unroll
        for (int ks = 0; ks < 4; ks++)
            ldm4(qf[ks], sb + qrow * ROWB + ks * 32 + khalf * 16);
    }

    const int bkey = (lane & 7) + ((lane >> 4) << 3);        // QK B-frag lane row
    const int bkh  = (lane >> 3) & 1;
    const int vkey = (lane & 7) + (((lane >> 3) & 1) << 3);  // PV B-frag lane row
    const int vdh  = (lane >> 4) << 3;

    float ostash[8][4];

    for (int s = 0; s < 2; s++) {
        const __half* Kh_ = KH[s];
        const __half* Kl_ = KL[s];
        const __half* Vh_ = VH[s];
        const __half* Vl_ = VL[s];

        float m[2] = { -1e30f, -1e30f }, l[2] = { 0.0f, 0.0f };
        float oacc[8][4];
        #pragma unroll
        for (int nt = 0; nt < 8; nt++)
            #pragma unroll
            for (int c = 0; c < 4; c++) oacc[nt][c] = 0.0f;

        for (int kt = 0; kt < PS / 64; kt++) {
            __syncthreads();
            #pragma unroll
            for (int j = 0; j < 4; j++) {
                const int cc = j * 128 + tid;
                const int r = cc >> 3, seg = cc & 7;
                const size_t go = (size_t)(b * PS + kt * 64 + r) * LQKV + h * PDH + seg * 8;
                const uint32_t so = r * ROWB + seg * 16;
                cpasync16(sb + 1 * ATILE_B + so, Kh_ + go);
                cpasync16(sb + 2 * ATILE_B + so, Kl_ + go);
                cpasync16(sb + 3 * ATILE_B + so, Vh_ + go);
                cpasync16(sb + 4 * ATILE_B + so, Vl_ + go);
            }
            CP_COMMIT();
            CP_WAIT(0);
            __syncthreads();

            // --- scores S = Q @ (Khi+Klo)^T (2-mma) ---
            float sacc[8][4];
            #pragma unroll
            for (int nt = 0; nt < 8; nt++)
                #pragma unroll
                for (int c = 0; c < 4; c++) sacc[nt][c] = 0.0f;

            #pragma unroll
            for (int ks = 0; ks < 4; ks++) {
                #pragma unroll
                for (int ntp = 0; ntp < 4; ntp++) {
                    const uint32_t addr = kh_s + (ntp * 16 + bkey) * ROWB
                                          + ks * 32 + bkh * 16;
                    uint32_t th[4], tl[4];
                    ldm4(th, addr);
                    ldm4(tl, addr + ATILE_B);
                    const uint32_t b0h[2] = { th[0], th[1] }, b1h[2] = { th[2], th[3] };
                    const uint32_t b0l[2] = { tl[0], tl[1] }, b1l[2] = { tl[2], tl[3] };
                    mma16816(sacc[2 * ntp],     qf[ks], b0h);
                    mma16816(sacc[2 * ntp],     qf[ks], b0l);
                    mma16816(sacc[2 * ntp + 1], qf[ks], b1h);
                    mma16816(sacc[2 * ntp + 1], qf[ks], b1l);
                }
            }

            // --- online softmax in base-2 (rows g and g+8) ---
            #pragma unroll
            for (int nt = 0; nt < 8; nt++)
                #pragma unroll
                for (int c = 0; c < 4; c++) sacc[nt][c] *= SC2;

            #pragma unroll
            for (int half = 0; half < 2; half++) {
                float mx = -1e30f;
                #pragma unroll
                for (int nt = 0; nt < 8; nt++)
                    mx = fmaxf(mx, fmaxf(sacc[nt][2 * half], sacc[nt][2 * half + 1]));
                mx = fmaxf(mx, __shfl_xor_sync(0xffffffffu, mx, 1));
                mx = fmaxf(mx, __shfl_xor_sync(0xffffffffu, mx, 2));
                const float mn = fmaxf(m[half], mx);
                const float corr = exp2f(m[half] - mn);
                m[half] = mn;
                float rs = 0.0f;
                #pragma unroll
                for (int nt = 0; nt < 8; nt++) {
                    const float p0 = exp2f(sacc[nt][2 * half] - mn);
                    const float p1 = exp2f(sacc[nt][2 * half + 1] - mn);
                    sacc[nt][2 * half] = p0;
                    sacc[nt][2 * half + 1] = p1;
                    rs += p0 + p1;
                }
                rs += __shfl_xor_sync(0xffffffffu, rs, 1);
                rs += __shfl_xor_sync(0xffffffffu, rs, 2);
                l[half] = l[half] * corr + rs;
                #pragma unroll
                for (int nt = 0; nt < 8; nt++) {
                    oacc[nt][2 * half]     *= corr;
                    oacc[nt][2 * half + 1] *= corr;
                }
            }

            // --- pack P into fp16 A-fragments (single plane) ---
            uint32_t ph[8][2];
            #pragma unroll
            for (int nt = 0; nt < 8; nt++) {
                #pragma unroll
                for (int half = 0; half < 2; half++) {
                    ph[nt][half] = packh(__float2half_rn(sacc[nt][2 * half]),
                                         __float2half_rn(sacc[nt][2 * half + 1]));
                }
            }

            // --- O += P @ (Vhi+Vlo) (2-mma, V^T via trans ldmatrix) ---
            #pragma unroll
            for (int ks = 0; ks < 4; ks++) {
                const uint32_t pa[4] = { ph[2 * ks][0], ph[2 * ks][1],
                                         ph[2 * ks + 1][0], ph[2 * ks + 1][1] };
                #pragma unroll
                for (int dhp = 0; dhp < 4; dhp++) {
                    const uint32_t addr = vh_s + (ks * 16 + vkey) * ROWB
                                          + (dhp * 16 + vdh) * 2;
                    uint32_t th[4], tl[4];
                    ldm4t(th, addr);
                    ldm4t(tl, addr + ATILE_B);
                    const uint32_t b0h[2] = { th[0], th[1] }, b1h[2] = { th[2], th[3] };
                    const uint32_t b0l[2] = { tl[0], tl[1] }, b1l[2] = { tl[2], tl[3] };
                    mma16816(oacc[2 * dhp],     pa, b0h);
                    mma16816(oacc[2 * dhp],     pa, b0l);
                    mma16816(oacc[2 * dhp + 1], pa, b1h);
                    mma16816(oacc[2 * dhp + 1], pa, b1l);
                }
            }
        }

        if (s == 0) {
            const float i0 = ws0 / l[0], i1 = ws0 / l[1];
            #pragma unroll
            for (int nt = 0; nt < 8; nt++) {
                ostash[nt][0] = oacc[nt][0] * i0;
                ostash[nt][1] = oacc[nt][1] * i0;
                ostash[nt][2] = oacc[nt][2] * i1;
                ostash[nt][3] = oacc[nt][3] * i1;
            }
        } else {
            const float i0 = ws1 / l[0], i1 = ws1 / l[1];
            const int r0 = qt * 64 + wid * 16 + g;
            #pragma unroll
            for (int nt = 0; nt < 8; nt++) {
                const int col = h * PDH + nt * 8 + tig * 2;
                const float v00 = ostash[nt][0] + oacc[nt][0] * i0;
                const float v01 = ostash[nt][1] + oacc[nt][1] * i0;
                const float v10 = ostash[nt][2] + oacc[nt][2] * i1;
                const float v11 = ostash[nt][3] + oacc[nt][3] * i1;
                const size_t o0 = (size_t)(b * PS + r0) * PH + col;
                const size_t o1 = (size_t)(b * PS + r0 + 8) * PH + col;
                *(__half2*)(ctx + o0) = __halves2half2(__float2half_rn(v00),
                                                       __float2half_rn(v01));
                *(__half2*)(ctx + o1) = __halves2half2(__float2half_rn(v10),
                                                       __float2half_rn(v11));
            }
        }
    }
}

// ---------------------------------------------------------------------------
// Launch
// ---------------------------------------------------------------------------
extern "C" void kernel_launch(void* const* d_in, const int* in_sizes, int n_in,
                              void* d_out, int out_size)
{
    const float* hx = (const float*)d_in[0];
    const float* hy = (const float*)d_in[1];
    const float* Wf[8] = { (const float*)d_in[2],  (const float*)d_in[4],
                           (const float*)d_in[6],  (const float*)d_in[8],
                           (const float*)d_in[10], (const float*)d_in[12],
                           (const float*)d_in[14], (const float*)d_in[16] };
    const float* Bf[8] = { (const float*)d_in[3],  (const float*)d_in[5],
                           (const float*)d_in[7],  (const float*)d_in[9],
                           (const float*)d_in[11], (const float*)d_in[13],
                           (const float*)d_in[15], (const float*)d_in[17] };
    // order: 0=q 1=k 2=v 3=o 4=qd 5=kd 6=vd 7=od
    const float* pw11 = (const float*)d_in[18];
    const float* pw12 = (const float*)d_in[19];
    const float* pw21 = (const float*)d_in[20];
    const float* pw22 = (const float*)d_in[21];
    float* out = (float*)d_out;

    __half *xh, *yh, *qkvxh, *qkvxl, *qkvyh, *qkvyl, *cxh, *cyh, *whi, *wlo;
    float *bcx, *bcy;
    cudaGetSymbolAddress((void**)&xh,    g_xh);
    cudaGetSymbolAddress((void**)&yh,    g_yh);
    cudaGetSymbolAddress((void**)&qkvxh, g_qkvxh);
    cudaGetSymbolAddress((void**)&qkvxl, g_qkvxl);
    cudaGetSymbolAddress((void**)&qkvyh, g_qkvyh);
    cudaGetSymbolAddress((void**)&qkvyl, g_qkvyl);
    cudaGetSymbolAddress((void**)&cxh,   g_cxh);
    cudaGetSymbolAddress((void**)&cyh,   g_cyh);
    cudaGetSymbolAddress((void**)&whi,   g_whi);
    cudaGetSymbolAddress((void**)&wlo,   g_wlo);
    cudaGetSymbolAddress((void**)&bcx,   g_bcx);
    cudaGetSymbolAddress((void**)&bcy,   g_bcy);

    // conversions + bias concat
    {
        const int n4a = PELEMS / 4, n4w = WN / 4;
        dim3 gi((n4a + 255) / 256, 2);
        cvt_inputs<<<gi, 256>>>(hx, hy, xh, yh);
        dim3 gw((n4w + 255) / 256, 8);
        split_weights<<<gw, 256>>>(Wf[0], Wf[1], Wf[2], Wf[3],
                                   Wf[4], Wf[5], Wf[6], Wf[7], whi, wlo);
        concat_biases<<<dim3(9, 2), 256>>>(Bf[0], Bf[1], Bf[2], bcx,
                                           Bf[4], Bf[5], Bf[6], bcy);
    }

    cudaFuncSetAttribute(mm_gemm, cudaFuncAttributeMaxDynamicSharedMemorySize,
                         GEMM_SMEM);
    cudaFuncSetAttribute(attn_mma, cudaFuncAttributeMaxDynamicSharedMemorySize,
                         ATT_SMEM);

    // fused QKV projections for BOTH streams in one launch (N = 2304)
    {
        const dim3 gq(LQKV / 128, 2 * (PM / 128));    // (18, 128)
        mm_gemm<<<gq, 256, GEMM_SMEM>>>(
            xh, whi + 0 * (size_t)WN, wlo + 0 * (size_t)WN, bcx,
            nullptr, nullptr, nullptr, qkvxh, qkvxl,
            yh, whi + 4 * (size_t)WN, wlo + 4 * (size_t)WN, bcy,
            nullptr, nullptr, nullptr, qkvyh, qkvyl,
            PH, LQKV);
    }

    // dual-stream flash attention, both outputs in one launch
    {
        const dim3 ga(2 * (PS / 64), PNH, PB);        // (32, 12, 8)
        attn_mma<<<ga, 128, ATT_SMEM>>>(qkvxh, qkvxl, qkvyh, qkvyl,
                                        pw11, pw12, pw21, pw22, cxh, cyh);
    }

    // output projections for BOTH streams in one launch
    {
        const dim3 go(PH / 128, 2 * (PM / 128));      // (6, 128)
        mm_gemm<<<go, 256, GEMM_SMEM>>>(
            cxh, whi + 3 * (size_t)WN, wlo + 3 * (size_t)WN, Bf[3],
            pw11, pw12, out, nullptr, nullptr,
            cyh, whi + 7 * (size_t)WN, wlo + 7 * (size_t)WN, Bf[7],
            pw21, pw22, out + (size_t)PM * PH, nullptr, nullptr,
            PH, PH);
    }
}

// round 11
// speedup vs baseline: 3.1212x; 1.4129x over previous
#include <cuda_runtime.h>
#include <cuda_fp16.h>
#include <cstdint>

// Problem constants
#define PB  8
#define PS  1024
#define PH  768
#define PNH 12
#define PDH 64
#define PM  (PB * PS)          // 8192
#define PELEMS (PM * PH)       // 6291456
#define WN  (PH * PH)          // 589824
#define LQKV 2304              // fused q|k|v row stride

// ---------------------------------------------------------------------------
// Scratch (static device globals — no allocation)
// ---------------------------------------------------------------------------
__device__ __half g_xh [PELEMS];
__device__ __half g_yh [PELEMS];
__device__ __half g_qkvx[PM * LQKV];
__device__ __half g_qkvy[PM * LQKV];
__device__ __half g_cxh[PELEMS];
__device__ __half g_cyh[PELEMS];
__device__ __half g_whi[8 * WN], g_wlo[8 * WN];
__device__ float g_bcx[LQKV], g_bcy[LQKV];

// ---------------------------------------------------------------------------
// Helpers (sm_80+-portable: ldmatrix + mma.sync + cp.async only)
// ---------------------------------------------------------------------------
__device__ __forceinline__ uint32_t smem_u32(const void* p) {
    uint32_t a;
    asm("{ .reg .u64 t; cvta.to.shared.u64 t, %1; cvt.u32.u64 %0, t; }"
        : "=r"(a) : "l"(p));
    return a;
}

__device__ __forceinline__ void cpasync16(uint32_t dst, const void* src) {
    asm volatile("cp.async.cg.shared.global [%0], [%1], 16;"
                 :: "r"(dst), "l"(src));
}
#define CP_COMMIT() asm volatile("cp.async.commit_group;")
#define CP_WAIT(n)  asm volatile("cp.async.wait_group %0;" :: "n"(n))

__device__ __forceinline__ void ldm4(uint32_t r[4], uint32_t addr) {
    asm volatile("ldmatrix.sync.aligned.m8n8.x4.shared.b16 {%0,%1,%2,%3}, [%4];"
        : "=r"(r[0]), "=r"(r[1]), "=r"(r[2]), "=r"(r[3]) : "r"(addr));
}
__device__ __forceinline__ void ldm4t(uint32_t r[4], uint32_t addr) {
    asm volatile("ldmatrix.sync.aligned.m8n8.x4.trans.shared.b16 {%0,%1,%2,%3}, [%4];"
        : "=r"(r[0]), "=r"(r[1]), "=r"(r[2]), "=r"(r[3]) : "r"(addr));
}

__device__ __forceinline__ void mma16816(float c[4], const uint32_t a[4],
                                         const uint32_t b[2]) {
    asm volatile("mma.sync.aligned.m16n8k16.row.col.f32.f16.f16.f32 "
        "{%0,%1,%2,%3}, {%4,%5,%6,%7}, {%8,%9}, {%0,%1,%2,%3};"
        : "+f"(c[0]), "+f"(c[1]), "+f"(c[2]), "+f"(c[3])
        : "r"(a[0]), "r"(a[1]), "r"(a[2]), "r"(a[3]), "r"(b[0]), "r"(b[1]));
}

__device__ __forceinline__ uint32_t packh(__half a, __half b) {
    __half2 t = __halves2half2(a, b);
    return *(uint32_t*)&t;
}

// ---------------------------------------------------------------------------
// fp32 -> fp16 conversions / hi+lo weight splits ; bias concatenation
// ---------------------------------------------------------------------------
__global__ void cvt_inputs(const float* __restrict__ hx, const float* __restrict__ hy,
                           __half* __restrict__ xh, __half* __restrict__ yh)
{
    int i = blockIdx.x * blockDim.x + threadIdx.x;
    if (i >= PELEMS / 4) return;
    const float* src = blockIdx.y ? hy : hx;
    __half* dst = blockIdx.y ? yh : xh;
    float4 v = *(const float4*)(src + (size_t)i * 4);
    ((__half2*)dst)[i * 2 + 0] = __halves2half2(__float2half_rn(v.x), __float2half_rn(v.y));
    ((__half2*)dst)[i * 2 + 1] = __halves2half2(__float2half_rn(v.z), __float2half_rn(v.w));
}

__global__ void split_weights(const float* w0, const float* w1, const float* w2,
                              const float* w3, const float* w4, const float* w5,
                              const float* w6, const float* w7,
                              __half* __restrict__ hi, __half* __restrict__ lo)
{
    int i = blockIdx.x * blockDim.x + threadIdx.x;
    if (i >= WN / 4) return;
    const int s = blockIdx.y;
    const float* src;
    switch (s) {
        case 0: src = w0; break; case 1: src = w1; break;
        case 2: src = w2; break; case 3: src = w3; break;
        case 4: src = w4; break; case 5: src = w5; break;
        case 6: src = w6; break; default: src = w7; break;
    }
    float4 v = *(const float4*)(src + (size_t)i * 4);
    __half h0 = __float2half_rn(v.x), h1 = __float2half_rn(v.y);
    __half h2 = __float2half_rn(v.z), h3 = __float2half_rn(v.w);
    __half2* ph = (__half2*)(hi + (size_t)s * WN);
    __half2* pl = (__half2*)(lo + (size_t)s * WN);
    ph[i * 2 + 0] = __halves2half2(h0, h1);
    ph[i * 2 + 1] = __halves2half2(h2, h3);
    pl[i * 2 + 0] = __halves2half2(__float2half_rn(v.x - __half2float(h0)),
                                   __float2half_rn(v.y - __half2float(h1)));
    pl[i * 2 + 1] = __halves2half2(__float2half_rn(v.z - __half2float(h2)),
                                   __float2half_rn(v.w - __half2float(h3)));
}

__global__ void concat_biases(const float* __restrict__ a0, const float* __restrict__ a1,
                              const float* __restrict__ a2, float* __restrict__ ox,
                              const float* __restrict__ b0, const float* __restrict__ b1,
                              const float* __restrict__ b2, float* __restrict__ oy)
{
    int i = blockIdx.x * blockDim.x + threadIdx.x;
    const float* s0 = blockIdx.y ? b0 : a0;
    const float* s1 = blockIdx.y ? b1 : a1;
    const float* s2 = blockIdx.y ? b2 : a2;
    float* o = blockIdx.y ? oy : ox;
    if (i < PH) o[i] = s0[i];
    else if (i < 2 * PH) o[i] = s1[i - PH];
    else if (i < 3 * PH) o[i] = s2[i - 2 * PH];
}

// ---------------------------------------------------------------------------
// fp16 2-MMA GEMM: C[M,N] = A[M,768] @ (Whi+Wlo)[N,768]^T + bscale*bias
// A single fp16 plane; W split hi/lo. CTA tile 128x128, K-chunk 32,
// cp.async double-buffered, 256 threads. Dual-config dispatch on blockIdx.y.
// Epilogue: fp32 (Cf) and/or single fp16 plane (Ch).
// ---------------------------------------------------------------------------
#define GBK   32
#define GKCH  (PH / GBK)         // 24
#define GSA   40                 // smem row stride fp16 (80B)
#define PLANE_B (128 * GSA * 2)  // 10240
#define STAGE_B (3 * PLANE_B)    // 30720  [A][Whi][Wlo]
#define GEMM_SMEM (2 * STAGE_B)  // 61440

__global__ void __launch_bounds__(256)
mm_gemm(const __half* __restrict__ A1, const __half* __restrict__ W1hi,
        const __half* __restrict__ W1lo, const float* __restrict__ bias1,
        const float* __restrict__ s1a, const float* __restrict__ s1b,
        float* __restrict__ Cf1, __half* __restrict__ C1h,
        const __half* __restrict__ A2, const __half* __restrict__ W2hi,
        const __half* __restrict__ W2lo, const float* __restrict__ bias2,
        const float* __restrict__ s2a, const float* __restrict__ s2b,
        float* __restrict__ Cf2, __half* __restrict__ C2h,
        int lda, int ldc)
{
    extern __shared__ char smem[];
    const uint32_t sb = smem_u32(smem);
    const int tid = threadIdx.x;
    const int wid = tid >> 5, lane = tid & 31;
    const int warpM = wid >> 2, warpN = wid & 3;

    int by = blockIdx.y;
    const bool second = (by >= 64);
    if (second) by -= 64;

    const __half* A        = second ? A2    : A1;
    const __half* Whi      = second ? W2hi  : W1hi;
    const __half* Wlo      = second ? W2lo  : W1lo;
    const float* bias      = second ? bias2 : bias1;
    const float* sa        = second ? s2a   : s1a;
    const float* sbv       = second ? s2b   : s1b;
    float* Cf              = second ? Cf2   : Cf1;
    __half* Ch             = second ? C2h   : C1h;

    const int row0 = by * 128, col0 = blockIdx.x * 128;

    const __half* g0 = A   + (size_t)row0 * lda;
    const __half* g2 = Whi + (size_t)col0 * PH;
    const __half* g3 = Wlo + (size_t)col0 * PH;

    float acc[4][4][4];
    #pragma unroll
    for (int mt = 0; mt < 4; mt++)
        #pragma unroll
        for (int nt = 0; nt < 4; nt++)
            #pragma unroll
            for (int c = 0; c < 4; c++) acc[mt][nt][c] = 0.0f;

    const int arow  = warpM * 64 + (lane & 15);
    const int akh   = lane >> 4;
    const int bkey  = warpN * 32 + (lane & 7) + ((lane >> 4) << 3);
    const int bkh   = (lane >> 3) & 1;

#define G_LOAD(kc, st) do {                                                   \
    const uint32_t dbase = sb + (st) * STAGE_B;                               \
    _Pragma("unroll")                                                         \
    for (int j = 0; j < 2; j++) {                                             \
        const int cc = j * 256 + tid;                                         \
        const int r = cc >> 2, seg = cc & 3;                                  \
        const uint32_t so = r * (GSA * 2) + seg * 16;                         \
        const size_t goA = (size_t)r * lda + (kc) * GBK + seg * 8;            \
        const size_t goW = (size_t)r * PH  + (kc) * GBK + seg * 8;            \
        cpasync16(dbase + 0 * PLANE_B + so, g0 + goA);                        \
        cpasync16(dbase + 1 * PLANE_B + so, g2 + goW);                        \
        cpasync16(dbase + 2 * PLANE_B + so, g3 + goW);                        \
    }                                                                         \
} while (0)

    G_LOAD(0, 0);
    CP_COMMIT();

    for (int kc = 0; kc < GKCH; kc++) {
        if (kc + 1 < GKCH) {
            G_LOAD(kc + 1, (kc + 1) & 1);
            CP_COMMIT();
            CP_WAIT(1);
        } else {
            CP_WAIT(0);
        }
        __syncthreads();

        const uint32_t stb = sb + (kc & 1) * STAGE_B;
        #pragma unroll
        for (int ks = 0; ks < 2; ks++) {
            uint32_t af[4][4];
            #pragma unroll
            for (int mt = 0; mt < 4; mt++)
                ldm4(af[mt], stb + (arow + mt * 16) * (GSA * 2) + ks * 32 + akh * 16);
            uint32_t bhi[4][2], blo[4][2];
            #pragma unroll
            for (int ntp = 0; ntp < 2; ntp++) {
                const uint32_t addr = stb + PLANE_B
                                      + (bkey + ntp * 16) * (GSA * 2)
                                      + ks * 32 + bkh * 16;
                uint32_t t[4];
                ldm4(t, addr);
                bhi[2 * ntp][0] = t[0]; bhi[2 * ntp][1] = t[1];
                bhi[2 * ntp + 1][0] = t[2]; bhi[2 * ntp + 1][1] = t[3];
                ldm4(t, addr + PLANE_B);
                blo[2 * ntp][0] = t[0]; blo[2 * ntp][1] = t[1];
                blo[2 * ntp + 1][0] = t[2]; blo[2 * ntp + 1][1] = t[3];
            }
            #pragma unroll
            for (int mt = 0; mt < 4; mt++)
                #pragma unroll
                for (int nt = 0; nt < 4; nt++) {
                    mma16816(acc[mt][nt], af[mt], bhi[nt]);
                    mma16816(acc[mt][nt], af[mt], blo[nt]);
                }
        }
        __syncthreads();
    }

    const int g = lane >> 2, tig = lane & 3;
    const float bscale = sa ? (*sa + *sbv) : 1.0f;
    #pragma unroll
    for (int mt = 0; mt < 4; mt++) {
        const int r0 = row0 + warpM * 64 + mt * 16 + g;
        #pragma unroll
        for (int nt = 0; nt < 4; nt++) {
            const int col = col0 + warpN * 32 + nt * 8 + tig * 2;
            const float b0 = bscale * bias[col];
            const float b1 = bscale * bias[col + 1];
            const float v00 = acc[mt][nt][0] + b0, v01 = acc[mt][nt][1] + b1;
            const float v10 = acc[mt][nt][2] + b0, v11 = acc[mt][nt][3] + b1;
            if (Cf) {
                *(float2*)(Cf + (size_t)r0 * ldc + col)       = make_float2(v00, v01);
                *(float2*)(Cf + (size_t)(r0 + 8) * ldc + col) = make_float2(v10, v11);
            }
            if (Ch) {
                *(__half2*)(Ch + (size_t)r0 * ldc + col) =
                    __halves2half2(__float2half_rn(v00), __float2half_rn(v01));
                *(__half2*)(Ch + (size_t)(r0 + 8) * ldc + col) =
                    __halves2half2(__float2half_rn(v10), __float2half_rn(v11));
            }
        }
    }
}

// ---------------------------------------------------------------------------
// Dual-stream flash attention, fp16 single-plane Q/K/V, both outputs in one
// launch. blockIdx.x&1 selects output stream; adjacent CTAs share KV tiles
// in L2. 64 q-rows, 4 warps, base-2 softmax.
//   st=0: cx = w11*attend(qx,Kx,Vx)[s0] + w12*attend(qx,Ky,Vy)[s1]
//   st=1: cy = w22*attend(qy,Kx,Vx)[s0] + w21*attend(qy,Ky,Vy)[s1]
// ---------------------------------------------------------------------------
#define AST     72                    // fp16 row stride (144B)
#define ROWB    (AST * 2)             // 144
#define ATILE_B (64 * ROWB)           // 9216
#define ATT_SMEM (3 * ATILE_B)        // 27648  [q][k][v]
#define SC2     0.1803368801f         // 0.125 * log2(e)

__global__ void __launch_bounds__(128)
attn_mma(const __half* __restrict__ qkvx, const __half* __restrict__ qkvy,
         const float* __restrict__ pw11, const float* __restrict__ pw12,
         const float* __restrict__ pw21, const float* __restrict__ pw22,
         __half* __restrict__ cxh, __half* __restrict__ cyh)
{
    extern __shared__ char smem[];
    const uint32_t sb = smem_u32(smem);
    const uint32_t kh_s = sb + 1 * ATILE_B;
    const uint32_t vh_s = sb + 2 * ATILE_B;

    const int st = blockIdx.x & 1;
    const int qt = blockIdx.x >> 1;
    const int h = blockIdx.y, b = blockIdx.z;
    const int tid = threadIdx.x, wid = tid >> 5, lane = tid & 31;
    const int g = lane >> 2, tig = lane & 3;

    const __half* Qh = st ? qkvy : qkvx;
    // phase 0 = x-KV, phase 1 = y-KV (identical order for both st)
    const __half* const KH[2] = { qkvx + PH, qkvy + PH };
    const __half* const VH[2] = { qkvx + 2 * PH, qkvy + 2 * PH };
    const float ws0 = st ? *pw22 : *pw11;
    const float ws1 = st ? *pw21 : *pw12;
    __half* ctx = st ? cyh : cxh;

    // --- load Q tile via cp.async ---
    #pragma unroll
    for (int j = 0; j < 4; j++) {
        const int cc = j * 128 + tid;        // 512 chunks
        const int r = cc >> 3, seg = cc & 7;
        const size_t go = (size_t)(b * PS + qt * 64 + r) * LQKV + h * PDH + seg * 8;
        cpasync16(sb + r * ROWB + seg * 16, Qh + go);
    }
    CP_COMMIT();
    CP_WAIT(0);
    __syncthreads();

    // --- Q fragments (registers, reused across phases) ---
    uint32_t qf[4][4];
    {
        const int qrow = wid * 16 + (lane & 15);
        const int khalf = lane >> 4;
        #pragma unroll
        for (int ks = 0; ks < 4; ks++)
            ldm4(qf[ks], sb + qrow * ROWB + ks * 32 + khalf * 16);
    }

    const int bkey = (lane & 7) + ((lane >> 4) << 3);        // QK B-frag lane row
    const int bkh  = (lane >> 3) & 1;
    const int vkey = (lane & 7) + (((lane >> 3) & 1) << 3);  // PV B-frag lane row
    const int vdh  = (lane >> 4) << 3;

    float ostash[8][4];

    for (int s = 0; s < 2; s++) {
        const __half* Kh_ = KH[s];
        const __half* Vh_ = VH[s];

        float m[2] = { -1e30f, -1e30f }, l[2] = { 0.0f, 0.0f };
        float oacc[8][4];
        #pragma unroll
        for (int nt = 0; nt < 8; nt++)
            #pragma unroll
            for (int c = 0; c < 4; c++) oacc[nt][c] = 0.0f;

        for (int kt = 0; kt < PS / 64; kt++) {
            __syncthreads();
            #pragma unroll
            for (int j = 0; j < 4; j++) {
                const int cc = j * 128 + tid;
                const int r = cc >> 3, seg = cc & 7;
                const size_t go = (size_t)(b * PS + kt * 64 + r) * LQKV + h * PDH + seg * 8;
                const uint32_t so = r * ROWB + seg * 16;
                cpasync16(kh_s + so, Kh_ + go);
                cpasync16(vh_s + so, Vh_ + go);
            }
            CP_COMMIT();
            CP_WAIT(0);
            __syncthreads();

            // --- scores S = Q @ K^T ---
            float sacc[8][4];
            #pragma unroll
            for (int nt = 0; nt < 8; nt++)
                #pragma unroll
                for (int c = 0; c < 4; c++) sacc[nt][c] = 0.0f;

            #pragma unroll
            for (int ks = 0; ks < 4; ks++) {
                #pragma unroll
                for (int ntp = 0; ntp < 4; ntp++) {
                    const uint32_t addr = kh_s + (ntp * 16 + bkey) * ROWB
                                          + ks * 32 + bkh * 16;
                    uint32_t th[4];
                    ldm4(th, addr);
                    const uint32_t b0h[2] = { th[0], th[1] }, b1h[2] = { th[2], th[3] };
                    mma16816(sacc[2 * ntp],     qf[ks], b0h);
                    mma16816(sacc[2 * ntp + 1], qf[ks], b1h);
                }
            }

            // --- online softmax in base-2 (rows g and g+8) ---
            #pragma unroll
            for (int nt = 0; nt < 8; nt++)
                #pragma unroll
                for (int c = 0; c < 4; c++) sacc[nt][c] *= SC2;

            #pragma unroll
            for (int half = 0; half < 2; half++) {
                float mx = -1e30f;
                #pragma unroll
                for (int nt = 0; nt < 8; nt++)
                    mx = fmaxf(mx, fmaxf(sacc[nt][2 * half], sacc[nt][2 * half + 1]));
                mx = fmaxf(mx, __shfl_xor_sync(0xffffffffu, mx, 1));
                mx = fmaxf(mx, __shfl_xor_sync(0xffffffffu, mx, 2));
                const float mn = fmaxf(m[half], mx);
                const float corr = exp2f(m[half] - mn);
                m[half] = mn;
                float rs = 0.0f;
                #pragma unroll
                for (int nt = 0; nt < 8; nt++) {
                    const float p0 = exp2f(sacc[nt][2 * half] - mn);
                    const float p1 = exp2f(sacc[nt][2 * half + 1] - mn);
                    sacc[nt][2 * half] = p0;
                    sacc[nt][2 * half + 1] = p1;
                    rs += p0 + p1;
                }
                rs += __shfl_xor_sync(0xffffffffu, rs, 1);
                rs += __shfl_xor_sync(0xffffffffu, rs, 2);
                l[half] = l[half] * corr + rs;
                #pragma unroll
                for (int nt = 0; nt < 8; nt++) {
                    oacc[nt][2 * half]     *= corr;
                    oacc[nt][2 * half + 1] *= corr;
                }
            }

            // --- pack P into fp16 A-fragments ---
            uint32_t ph[8][2];
            #pragma unroll
            for (int nt = 0; nt < 8; nt++) {
                #pragma unroll
                for (int half = 0; half < 2; half++) {
                    ph[nt][half] = packh(__float2half_rn(sacc[nt][2 * half]),
                                         __float2half_rn(sacc[nt][2 * half + 1]));
                }
            }

            // --- O += P @ V (V^T via trans ldmatrix) ---
            #pragma unroll
            for (int ks = 0; ks < 4; ks++) {
                const uint32_t pa[4] = { ph[2 * ks][0], ph[2 * ks][1],
                                         ph[2 * ks + 1][0], ph[2 * ks + 1][1] };
                #pragma unroll
                for (int dhp = 0; dhp < 4; dhp++) {
                    const uint32_t addr = vh_s + (ks * 16 + vkey) * ROWB
                                          + (dhp * 16 + vdh) * 2;
                    uint32_t th[4];
                    ldm4t(th, addr);
                    const uint32_t b0h[2] = { th[0], th[1] }, b1h[2] = { th[2], th[3] };
                    mma16816(oacc[2 * dhp],     pa, b0h);
                    mma16816(oacc[2 * dhp + 1], pa, b1h);
                }
            }
        }

        if (s == 0) {
            const float i0 = ws0 / l[0], i1 = ws0 / l[1];
            #pragma unroll
            for (int nt = 0; nt < 8; nt++) {
                ostash[nt][0] = oacc[nt][0] * i0;
                ostash[nt][1] = oacc[nt][1] * i0;
                ostash[nt][2] = oacc[nt][2] * i1;
                ostash[nt][3] = oacc[nt][3] * i1;
            }
        } else {
            const float i0 = ws1 / l[0], i1 = ws1 / l[1];
            const int r0 = qt * 64 + wid * 16 + g;
            #pragma unroll
            for (int nt = 0; nt < 8; nt++) {
                const int col = h * PDH + nt * 8 + tig * 2;
                const float v00 = ostash[nt][0] + oacc[nt][0] * i0;
                const float v01 = ostash[nt][1] + oacc[nt][1] * i0;
                const float v10 = ostash[nt][2] + oacc[nt][2] * i1;
                const float v11 = ostash[nt][3] + oacc[nt][3] * i1;
                const size_t o0 = (size_t)(b * PS + r0) * PH + col;
                const size_t o1 = (size_t)(b * PS + r0 + 8) * PH + col;
                *(__half2*)(ctx + o0) = __halves2half2(__float2half_rn(v00),
                                                       __float2half_rn(v01));
                *(__half2*)(ctx + o1) = __halves2half2(__float2half_rn(v10),
                                                       __float2half_rn(v11));
            }
        }
    }
}

// ---------------------------------------------------------------------------
// Launch
// ---------------------------------------------------------------------------
extern "C" void kernel_launch(void* const* d_in, const int* in_sizes, int n_in,
                              void* d_out, int out_size)
{
    const float* hx = (const float*)d_in[0];
    const float* hy = (const float*)d_in[1];
    const float* Wf[8] = { (const float*)d_in[2],  (const float*)d_in[4],
                           (const float*)d_in[6],  (const float*)d_in[8],
                           (const float*)d_in[10], (const float*)d_in[12],
                           (const float*)d_in[14], (const float*)d_in[16] };
    const float* Bf[8] = { (const float*)d_in[3],  (const float*)d_in[5],
                           (const float*)d_in[7],  (const float*)d_in[9],
                           (const float*)d_in[11], (const float*)d_in[13],
                           (const float*)d_in[15], (const float*)d_in[17] };
    // order: 0=q 1=k 2=v 3=o 4=qd 5=kd 6=vd 7=od
    const float* pw11 = (const float*)d_in[18];
    const float* pw12 = (const float*)d_in[19];
    const float* pw21 = (const float*)d_in[20];
    const float* pw22 = (const float*)d_in[21];
    float* out = (float*)d_out;

    __half *xh, *yh, *qkvx, *qkvy, *cxh, *cyh, *whi, *wlo;
    float *bcx, *bcy;
    cudaGetSymbolAddress((void**)&xh,   g_xh);
    cudaGetSymbolAddress((void**)&yh,   g_yh);
    cudaGetSymbolAddress((void**)&qkvx, g_qkvx);
    cudaGetSymbolAddress((void**)&qkvy, g_qkvy);
    cudaGetSymbolAddress((void**)&cxh,  g_cxh);
    cudaGetSymbolAddress((void**)&cyh,  g_cyh);
    cudaGetSymbolAddress((void**)&whi,  g_whi);
    cudaGetSymbolAddress((void**)&wlo,  g_wlo);
    cudaGetSymbolAddress((void**)&bcx,  g_bcx);
    cudaGetSymbolAddress((void**)&bcy,  g_bcy);

    // conversions + bias concat
    {
        const int n4a = PELEMS / 4, n4w = WN / 4;
        dim3 gi((n4a + 255) / 256, 2);
        cvt_inputs<<<gi, 256>>>(hx, hy, xh, yh);
        dim3 gw((n4w + 255) / 256, 8);
        split_weights<<<gw, 256>>>(Wf[0], Wf[1], Wf[2], Wf[3],
                                   Wf[4], Wf[5], Wf[6], Wf[7], whi, wlo);
        concat_biases<<<dim3(9, 2), 256>>>(Bf[0], Bf[1], Bf[2], bcx,
                                           Bf[4], Bf[5], Bf[6], bcy);
    }

    cudaFuncSetAttribute(mm_gemm, cudaFuncAttributeMaxDynamicSharedMemorySize,
                         GEMM_SMEM);
    cudaFuncSetAttribute(attn_mma, cudaFuncAttributeMaxDynamicSharedMemorySize,
                         ATT_SMEM);

    // fused QKV projections for BOTH streams in one launch (N = 2304)
    {
        const dim3 gq(LQKV / 128, 2 * (PM / 128));    // (18, 128)
        mm_gemm<<<gq, 256, GEMM_SMEM>>>(
            xh, whi + 0 * (size_t)WN, wlo + 0 * (size_t)WN, bcx,
            nullptr, nullptr, nullptr, qkvx,
            yh, whi + 4 * (size_t)WN, wlo + 4 * (size_t)WN, bcy,
            nullptr, nullptr, nullptr, qkvy,
            PH, LQKV);
    }

    // dual-stream flash attention, both outputs in one launch
    {
        const dim3 ga(2 * (PS / 64), PNH, PB);        // (32, 12, 8)
        attn_mma<<<ga, 128, ATT_SMEM>>>(qkvx, qkvy,
                                        pw11, pw12, pw21, pw22, cxh, cyh);
    }

    // output projections for BOTH streams in one launch
    {
        const dim3 go(PH / 128, 2 * (PM / 128));      // (6, 128)
        mm_gemm<<<go, 256, GEMM_SMEM>>>(
            cxh, whi + 3 * (size_t)WN, wlo + 3 * (size_t)WN, Bf[3],
            pw11, pw12, out, nullptr,
            cyh, whi + 7 * (size_t)WN, wlo + 7 * (size_t)WN, Bf[7],
            pw21, pw22, out + (size_t)PM * PH, nullptr,
            PH, PH);
    }
}

// round 13
// speedup vs baseline: 3.8764x; 1.2419x over previous
#include <cuda_runtime.h>
#include <cuda_fp16.h>
#include <cstdint>

// Problem constants
#define PB  8
#define PS  1024
#define PH  768
#define PNH 12
#define PDH 64
#define PM  (PB * PS)          // 8192
#define PELEMS (PM * PH)       // 6291456
#define WN  (PH * PH)          // 589824
#define LQKV 2304              // fused q|k|v row stride

// ---------------------------------------------------------------------------
// Scratch (static device globals — no allocation)
// ---------------------------------------------------------------------------
__device__ __half g_xh [PELEMS];
__device__ __half g_yh [PELEMS];
__device__ __half g_qkvx[PM * LQKV];
__device__ __half g_qkvy[PM * LQKV];
__device__ __half g_cxh[PELEMS];
__device__ __half g_cyh[PELEMS];
__device__ __half g_w[8 * WN];
__device__ float g_bcx[LQKV], g_bcy[LQKV];

// ---------------------------------------------------------------------------
// Helpers (sm_80+-portable: ldmatrix + mma.sync + cp.async only)
// ---------------------------------------------------------------------------
__device__ __forceinline__ uint32_t smem_u32(const void* p) {
    uint32_t a;
    asm("{ .reg .u64 t; cvta.to.shared.u64 t, %1; cvt.u32.u64 %0, t; }"
        : "=r"(a) : "l"(p));
    return a;
}

__device__ __forceinline__ void cpasync16(uint32_t dst, const void* src) {
    asm volatile("cp.async.cg.shared.global [%0], [%1], 16;"
                 :: "r"(dst), "l"(src));
}
#define CP_COMMIT() asm volatile("cp.async.commit_group;")
#define CP_WAIT(n)  asm volatile("cp.async.wait_group %0;" :: "n"(n))

__device__ __forceinline__ void ldm4(uint32_t r[4], uint32_t addr) {
    asm volatile("ldmatrix.sync.aligned.m8n8.x4.shared.b16 {%0,%1,%2,%3}, [%4];"
        : "=r"(r[0]), "=r"(r[1]), "=r"(r[2]), "=r"(r[3]) : "r"(addr));
}
__device__ __forceinline__ void ldm4t(uint32_t r[4], uint32_t addr) {
    asm volatile("ldmatrix.sync.aligned.m8n8.x4.trans.shared.b16 {%0,%1,%2,%3}, [%4];"
        : "=r"(r[0]), "=r"(r[1]), "=r"(r[2]), "=r"(r[3]) : "r"(addr));
}

__device__ __forceinline__ void mma16816(float c[4], const uint32_t a[4],
                                         const uint32_t b[2]) {
    asm volatile("mma.sync.aligned.m16n8k16.row.col.f32.f16.f16.f32 "
        "{%0,%1,%2,%3}, {%4,%5,%6,%7}, {%8,%9}, {%0,%1,%2,%3};"
        : "+f"(c[0]), "+f"(c[1]), "+f"(c[2]), "+f"(c[3])
        : "r"(a[0]), "r"(a[1]), "r"(a[2]), "r"(a[3]), "r"(b[0]), "r"(b[1]));
}

__device__ __forceinline__ uint32_t packh(__half a, __half b) {
    __half2 t = __halves2half2(a, b);
    return *(uint32_t*)&t;
}

// ---------------------------------------------------------------------------
// fp32 -> fp16 conversions ; bias concatenation
// ---------------------------------------------------------------------------
__global__ void cvt_inputs(const float* __restrict__ hx, const float* __restrict__ hy,
                           __half* __restrict__ xh, __half* __restrict__ yh)
{
    int i = blockIdx.x * blockDim.x + threadIdx.x;
    if (i >= PELEMS / 4) return;
    const float* src = blockIdx.y ? hy : hx;
    __half* dst = blockIdx.y ? yh : xh;
    float4 v = *(const float4*)(src + (size_t)i * 4);
    ((__half2*)dst)[i * 2 + 0] = __halves2half2(__float2half_rn(v.x), __float2half_rn(v.y));
    ((__half2*)dst)[i * 2 + 1] = __halves2half2(__float2half_rn(v.z), __float2half_rn(v.w));
}

__global__ void cvt_weights(const float* w0, const float* w1, const float* w2,
                            const float* w3, const float* w4, const float* w5,
                            const float* w6, const float* w7,
                            __half* __restrict__ dst)
{
    int i = blockIdx.x * blockDim.x + threadIdx.x;
    if (i >= WN / 4) return;
    const int s = blockIdx.y;
    const float* src;
    switch (s) {
        case 0: src = w0; break; case 1: src = w1; break;
        case 2: src = w2; break; case 3: src = w3; break;
        case 4: src = w4; break; case 5: src = w5; break;
        case 6: src = w6; break; default: src = w7; break;
    }
    float4 v = *(const float4*)(src + (size_t)i * 4);
    __half2* ph = (__half2*)(dst + (size_t)s * WN);
    ph[i * 2 + 0] = __halves2half2(__float2half_rn(v.x), __float2half_rn(v.y));
    ph[i * 2 + 1] = __halves2half2(__float2half_rn(v.z), __float2half_rn(v.w));
}

__global__ void concat_biases(const float* __restrict__ a0, const float* __restrict__ a1,
                              const float* __restrict__ a2, float* __restrict__ ox,
                              const float* __restrict__ b0, const float* __restrict__ b1,
                              const float* __restrict__ b2, float* __restrict__ oy)
{
    int i = blockIdx.x * blockDim.x + threadIdx.x;
    const float* s0 = blockIdx.y ? b0 : a0;
    const float* s1 = blockIdx.y ? b1 : a1;
    const float* s2 = blockIdx.y ? b2 : a2;
    float* o = blockIdx.y ? oy : ox;
    if (i < PH) o[i] = s0[i];
    else if (i < 2 * PH) o[i] = s1[i - PH];
    else if (i < 3 * PH) o[i] = s2[i - 2 * PH];
}

// ---------------------------------------------------------------------------
// fp16 GEMM: C[M,N] = A[M,768] @ W[N,768]^T + bscale*bias
// Single fp16 planes. CTA tile 128x128, K-chunk 32, cp.async 3-stage
// pipeline (prefetch distance 2), 256 threads. Dual-config on blockIdx.y.
// ---------------------------------------------------------------------------
#define GBK   32
#define GKCH  (PH / GBK)         // 24
#define GSA   40                 // smem row stride fp16 (80B)
#define PLANE_B (128 * GSA * 2)  // 10240
#define STAGE_B (2 * PLANE_B)    // 20480  [A][W]
#define GEMM_SMEM (3 * STAGE_B)  // 61440

__global__ void __launch_bounds__(256)
mm_gemm(const __half* __restrict__ A1, const __half* __restrict__ W1,
        const float* __restrict__ bias1,
        const float* __restrict__ s1a, const float* __restrict__ s1b,
        float* __restrict__ Cf1, __half* __restrict__ C1h,
        const __half* __restrict__ A2, const __half* __restrict__ W2,
        const float* __restrict__ bias2,
        const float* __restrict__ s2a, const float* __restrict__ s2b,
        float* __restrict__ Cf2, __half* __restrict__ C2h,
        int lda, int ldc)
{
    extern __shared__ char smem[];
    const uint32_t sb = smem_u32(smem);
    const int tid = threadIdx.x;
    const int wid = tid >> 5, lane = tid & 31;
    const int warpM = wid >> 2, warpN = wid & 3;

    int by = blockIdx.y;
    const bool second = (by >= 64);
    if (second) by -= 64;

    const __half* A        = second ? A2    : A1;
    const __half* W        = second ? W2    : W1;
    const float* bias      = second ? bias2 : bias1;
    const float* sa        = second ? s2a   : s1a;
    const float* sbv       = second ? s2b   : s1b;
    float* Cf              = second ? Cf2   : Cf1;
    __half* Ch             = second ? C2h   : C1h;

    const int row0 = by * 128, col0 = blockIdx.x * 128;

    const __half* g0 = A + (size_t)row0 * lda;
    const __half* g2 = W + (size_t)col0 * PH;

    float acc[4][4][4];
    #pragma unroll
    for (int mt = 0; mt < 4; mt++)
        #pragma unroll
        for (int nt = 0; nt < 4; nt++)
            #pragma unroll
            for (int c = 0; c < 4; c++) acc[mt][nt][c] = 0.0f;

    const int arow  = warpM * 64 + (lane & 15);
    const int akh   = lane >> 4;
    const int bkey  = warpN * 32 + (lane & 7) + ((lane >> 4) << 3);
    const int bkh   = (lane >> 3) & 1;

#define G_LOAD(kc, st) do {                                                   \
    const uint32_t dbase = sb + (st) * STAGE_B;                               \
    _Pragma("unroll")                                                         \
    for (int j = 0; j < 2; j++) {                                             \
        const int cc = j * 256 + tid;                                         \
        const int r = cc >> 2, seg = cc & 3;                                  \
        const uint32_t so = r * (GSA * 2) + seg * 16;                         \
        const size_t goA = (size_t)r * lda + (kc) * GBK + seg * 8;            \
        const size_t goW = (size_t)r * PH  + (kc) * GBK + seg * 8;            \
        cpasync16(dbase + 0 * PLANE_B + so, g0 + goA);                        \
        cpasync16(dbase + 1 * PLANE_B + so, g2 + goW);                        \
    }                                                                         \
} while (0)

    G_LOAD(0, 0);
    CP_COMMIT();
    G_LOAD(1, 1);
    CP_COMMIT();

    for (int kc = 0; kc < GKCH; kc++) {
        if (kc + 2 < GKCH) {
            G_LOAD(kc + 2, (kc + 2) % 3);
            CP_COMMIT();
            CP_WAIT(2);
        } else if (kc + 1 < GKCH) {
            CP_WAIT(1);
        } else {
            CP_WAIT(0);
        }
        __syncthreads();

        const uint32_t stb = sb + (kc % 3) * STAGE_B;
        #pragma unroll
        for (int ks = 0; ks < 2; ks++) {
            uint32_t af[4][4];
            #pragma unroll
            for (int mt = 0; mt < 4; mt++)
                ldm4(af[mt], stb + (arow + mt * 16) * (GSA * 2) + ks * 32 + akh * 16);
            uint32_t bf[4][2];
            #pragma unroll
            for (int ntp = 0; ntp < 2; ntp++) {
                const uint32_t addr = stb + PLANE_B
                                      + (bkey + ntp * 16) * (GSA * 2)
                                      + ks * 32 + bkh * 16;
                uint32_t t[4];
                ldm4(t, addr);
                bf[2 * ntp][0] = t[0]; bf[2 * ntp][1] = t[1];
                bf[2 * ntp + 1][0] = t[2]; bf[2 * ntp + 1][1] = t[3];
            }
            #pragma unroll
            for (int mt = 0; mt < 4; mt++)
                #pragma unroll
                for (int nt = 0; nt < 4; nt++)
                    mma16816(acc[mt][nt], af[mt], bf[nt]);
        }
        __syncthreads();
    }

    const int g = lane >> 2, tig = lane & 3;
    const float bscale = sa ? (*sa + *sbv) : 1.0f;
    #pragma unroll
    for (int mt = 0; mt < 4; mt++) {
        const int r0 = row0 + warpM * 64 + mt * 16 + g;
        #pragma unroll
        for (int nt = 0; nt < 4; nt++) {
            const int col = col0 + warpN * 32 + nt * 8 + tig * 2;
            const float b0 = bscale * bias[col];
            const float b1 = bscale * bias[col + 1];
            const float v00 = acc[mt][nt][0] + b0, v01 = acc[mt][nt][1] + b1;
            const float v10 = acc[mt][nt][2] + b0, v11 = acc[mt][nt][3] + b1;
            if (Cf) {
                *(float2*)(Cf + (size_t)r0 * ldc + col)       = make_float2(v00, v01);
                *(float2*)(Cf + (size_t)(r0 + 8) * ldc + col) = make_float2(v10, v11);
            }
            if (Ch) {
                *(__half2*)(Ch + (size_t)r0 * ldc + col) =
                    __halves2half2(__float2half_rn(v00), __float2half_rn(v01));
                *(__half2*)(Ch + (size_t)(r0 + 8) * ldc + col) =
                    __halves2half2(__float2half_rn(v10), __float2half_rn(v11));
            }
        }
    }
}

// ---------------------------------------------------------------------------
// Dual-stream flash attention, fp16 single-plane Q/K/V, both outputs in one
// launch. blockIdx.x&1 selects output stream; adjacent CTAs share KV tiles
// in L2. 64 q-rows, 4 warps, base-2 softmax. (unchanged from round 10)
// ---------------------------------------------------------------------------
#define AST     72                    // fp16 row stride (144B)
#define ROWB    (AST * 2)             // 144
#define ATILE_B (64 * ROWB)           // 9216
#define ATT_SMEM (3 * ATILE_B)        // 27648  [q][k][v]
#define SC2     0.1803368801f         // 0.125 * log2(e)

__global__ void __launch_bounds__(128)
attn_mma(const __half* __restrict__ qkvx, const __half* __restrict__ qkvy,
         const float* __restrict__ pw11, const float* __restrict__ pw12,
         const float* __restrict__ pw21, const float* __restrict__ pw22,
         __half* __restrict__ cxh, __half* __restrict__ cyh)
{
    extern __shared__ char smem[];
    const uint32_t sb = smem_u32(smem);
    const uint32_t kh_s = sb + 1 * ATILE_B;
    const uint32_t vh_s = sb + 2 * ATILE_B;

    const int st = blockIdx.x & 1;
    const int qt = blockIdx.x >> 1;
    const int h = blockIdx.y, b = blockIdx.z;
    const int tid = threadIdx.x, wid = tid >> 5, lane = tid & 31;
    const int g = lane >> 2, tig = lane & 3;

    const __half* Qh = st ? qkvy : qkvx;
    const __half* const KH[2] = { qkvx + PH, qkvy + PH };
    const __half* const VH[2] = { qkvx + 2 * PH, qkvy + 2 * PH };
    const float ws0 = st ? *pw22 : *pw11;
    const float ws1 = st ? *pw21 : *pw12;
    __half* ctx = st ? cyh : cxh;

    // --- load Q tile via cp.async ---
    #pragma unroll
    for (int j = 0; j < 4; j++) {
        const int cc = j * 128 + tid;
        const int r = cc >> 3, seg = cc & 7;
        const size_t go = (size_t)(b * PS + qt * 64 + r) * LQKV + h * PDH + seg * 8;
        cpasync16(sb + r * ROWB + seg * 16, Qh + go);
    }
    CP_COMMIT();
    CP_WAIT(0);
    __syncthreads();

    // --- Q fragments (registers, reused across phases) ---
    uint32_t qf[4][4];
    {
        const int qrow = wid * 16 + (lane & 15);
        const int khalf = lane >> 4;
        #pragma unroll
        for (int ks = 0; ks < 4; ks++)
            ldm4(qf[ks], sb + qrow * ROWB + ks * 32 + khalf * 16);
    }

    const int bkey = (lane & 7) + ((lane >> 4) << 3);
    const int bkh  = (lane >> 3) & 1;
    const int vkey = (lane & 7) + (((lane >> 3) & 1) << 3);
    const int vdh  = (lane >> 4) << 3;

    float ostash[8][4];

    for (int s = 0; s < 2; s++) {
        const __half* Kh_ = KH[s];
        const __half* Vh_ = VH[s];

        float m[2] = { -1e30f, -1e30f }, l[2] = { 0.0f, 0.0f };
        float oacc[8][4];
        #pragma unroll
        for (int nt = 0; nt < 8; nt++)
            #pragma unroll
            for (int c = 0; c < 4; c++) oacc[nt][c] = 0.0f;

        for (int kt = 0; kt < PS / 64; kt++) {
            __syncthreads();
            #pragma unroll
            for (int j = 0; j < 4; j++) {
                const int cc = j * 128 + tid;
                const int r = cc >> 3, seg = cc & 7;
                const size_t go = (size_t)(b * PS + kt * 64 + r) * LQKV + h * PDH + seg * 8;
                const uint32_t so = r * ROWB + seg * 16;
                cpasync16(kh_s + so, Kh_ + go);
                cpasync16(vh_s + so, Vh_ + go);
            }
            CP_COMMIT();
            CP_WAIT(0);
            __syncthreads();

            // --- scores S = Q @ K^T ---
            float sacc[8][4];
            #pragma unroll
            for (int nt = 0; nt < 8; nt++)
                #pragma unroll
                for (int c = 0; c < 4; c++) sacc[nt][c] = 0.0f;

            #pragma unroll
            for (int ks = 0; ks < 4; ks++) {
                #pragma unroll
                for (int ntp = 0; ntp < 4; ntp++) {
                    const uint32_t addr = kh_s + (ntp * 16 + bkey) * ROWB
                                          + ks * 32 + bkh * 16;
                    uint32_t th[4];
                    ldm4(th, addr);
                    const uint32_t b0h[2] = { th[0], th[1] }, b1h[2] = { th[2], th[3] };
                    mma16816(sacc[2 * ntp],     qf[ks], b0h);
                    mma16816(sacc[2 * ntp + 1], qf[ks], b1h);
                }
            }

            // --- online softmax in base-2 ---
            #pragma unroll
            for (int nt = 0; nt < 8; nt++)
                #pragma unroll
                for (int c = 0; c < 4; c++) sacc[nt][c] *= SC2;

            #pragma unroll
            for (int half = 0; half < 2; half++) {
                float mx = -1e30f;
                #pragma unroll
                for (int nt = 0; nt < 8; nt++)
                    mx = fmaxf(mx, fmaxf(sacc[nt][2 * half], sacc[nt][2 * half + 1]));
                mx = fmaxf(mx, __shfl_xor_sync(0xffffffffu, mx, 1));
                mx = fmaxf(mx, __shfl_xor_sync(0xffffffffu, mx, 2));
                const float mn = fmaxf(m[half], mx);
                const float corr = exp2f(m[half] - mn);
                m[half] = mn;
                float rs = 0.0f;
                #pragma unroll
                for (int nt = 0; nt < 8; nt++) {
                    const float p0 = exp2f(sacc[nt][2 * half] - mn);
                    const float p1 = exp2f(sacc[nt][2 * half + 1] - mn);
                    sacc[nt][2 * half] = p0;
                    sacc[nt][2 * half + 1] = p1;
                    rs += p0 + p1;
                }
                rs += __shfl_xor_sync(0xffffffffu, rs, 1);
                rs += __shfl_xor_sync(0xffffffffu, rs, 2);
                l[half] = l[half] * corr + rs;
                #pragma unroll
                for (int nt = 0; nt < 8; nt++) {
                    oacc[nt][2 * half]     *= corr;
                    oacc[nt][2 * half + 1] *= corr;
                }
            }

            // --- pack P into fp16 A-fragments ---
            uint32_t ph[8][2];
            #pragma unroll
            for (int nt = 0; nt < 8; nt++) {
                #pragma unroll
                for (int half = 0; half < 2; half++) {
                    ph[nt][half] = packh(__float2half_rn(sacc[nt][2 * half]),
                                         __float2half_rn(sacc[nt][2 * half + 1]));
                }
            }

            // --- O += P @ V ---
            #pragma unroll
            for (int ks = 0; ks < 4; ks++) {
                const uint32_t pa[4] = { ph[2 * ks][0], ph[2 * ks][1],
                                         ph[2 * ks + 1][0], ph[2 * ks + 1][1] };
                #pragma unroll
                for (int dhp = 0; dhp < 4; dhp++) {
                    const uint32_t addr = vh_s + (ks * 16 + vkey) * ROWB
                                          + (dhp * 16 + vdh) * 2;
                    uint32_t th[4];
                    ldm4t(th, addr);
                    const uint32_t b0h[2] = { th[0], th[1] }, b1h[2] = { th[2], th[3] };
                    mma16816(oacc[2 * dhp],     pa, b0h);
                    mma16816(oacc[2 * dhp + 1], pa, b1h);
                }
            }
        }

        if (s == 0) {
            const float i0 = ws0 / l[0], i1 = ws0 / l[1];
            #pragma unroll
            for (int nt = 0; nt < 8; nt++) {
                ostash[nt][0] = oacc[nt][0] * i0;
                ostash[nt][1] = oacc[nt][1] * i0;
                ostash[nt][2] = oacc[nt][2] * i1;
                ostash[nt][3] = oacc[nt][3] * i1;
            }
        } else {
            const float i0 = ws1 / l[0], i1 = ws1 / l[1];
            const int r0 = qt * 64 + wid * 16 + g;
            #pragma unroll
            for (int nt = 0; nt < 8; nt++) {
                const int col = h * PDH + nt * 8 + tig * 2;
                const float v00 = ostash[nt][0] + oacc[nt][0] * i0;
                const float v01 = ostash[nt][1] + oacc[nt][1] * i0;
                const float v10 = ostash[nt][2] + oacc[nt][2] * i1;
                const float v11 = ostash[nt][3] + oacc[nt][3] * i1;
                const size_t o0 = (size_t)(b * PS + r0) * PH + col;
                const size_t o1 = (size_t)(b * PS + r0 + 8) * PH + col;
                *(__half2*)(ctx + o0) = __halves2half2(__float2half_rn(v00),
                                                       __float2half_rn(v01));
                *(__half2*)(ctx + o1) = __halves2half2(__float2half_rn(v10),
                                                       __float2half_rn(v11));
            }
        }
    }
}

// ---------------------------------------------------------------------------
// Launch
// ---------------------------------------------------------------------------
extern "C" void kernel_launch(void* const* d_in, const int* in_sizes, int n_in,
                              void* d_out, int out_size)
{
    const float* hx = (const float*)d_in[0];
    const float* hy = (const float*)d_in[1];
    const float* Wf[8] = { (const float*)d_in[2],  (const float*)d_in[4],
                           (const float*)d_in[6],  (const float*)d_in[8],
                           (const float*)d_in[10], (const float*)d_in[12],
                           (const float*)d_in[14], (const float*)d_in[16] };
    const float* Bf[8] = { (const float*)d_in[3],  (const float*)d_in[5],
                           (const float*)d_in[7],  (const float*)d_in[9],
                           (const float*)d_in[11], (const float*)d_in[13],
                           (const float*)d_in[15], (const float*)d_in[17] };
    // order: 0=q 1=k 2=v 3=o 4=qd 5=kd 6=vd 7=od
    const float* pw11 = (const float*)d_in[18];
    const float* pw12 = (const float*)d_in[19];
    const float* pw21 = (const float*)d_in[20];
    const float* pw22 = (const float*)d_in[21];
    float* out = (float*)d_out;

    __half *xh, *yh, *qkvx, *qkvy, *cxh, *cyh, *w;
    float *bcx, *bcy;
    cudaGetSymbolAddress((void**)&xh,   g_xh);
    cudaGetSymbolAddress((void**)&yh,   g_yh);
    cudaGetSymbolAddress((void**)&qkvx, g_qkvx);
    cudaGetSymbolAddress((void**)&qkvy, g_qkvy);
    cudaGetSymbolAddress((void**)&cxh,  g_cxh);
    cudaGetSymbolAddress((void**)&cyh,  g_cyh);
    cudaGetSymbolAddress((void**)&w,    g_w);
    cudaGetSymbolAddress((void**)&bcx,  g_bcx);
    cudaGetSymbolAddress((void**)&bcy,  g_bcy);

    // conversions + bias concat
    {
        const int n4a = PELEMS / 4, n4w = WN / 4;
        dim3 gi((n4a + 255) / 256, 2);
        cvt_inputs<<<gi, 256>>>(hx, hy, xh, yh);
        dim3 gw((n4w + 255) / 256, 8);
        cvt_weights<<<gw, 256>>>(Wf[0], Wf[1], Wf[2], Wf[3],
                                 Wf[4], Wf[5], Wf[6], Wf[7], w);
        concat_biases<<<dim3(9, 2), 256>>>(Bf[0], Bf[1], Bf[2], bcx,
                                           Bf[4], Bf[5], Bf[6], bcy);
    }

    cudaFuncSetAttribute(mm_gemm, cudaFuncAttributeMaxDynamicSharedMemorySize,
                         GEMM_SMEM);
    cudaFuncSetAttribute(attn_mma, cudaFuncAttributeMaxDynamicSharedMemorySize,
                         ATT_SMEM);

    // fused QKV projections for BOTH streams in one launch (N = 2304)
    {
        const dim3 gq(LQKV / 128, 2 * (PM / 128));    // (18, 128)
        mm_gemm<<<gq, 256, GEMM_SMEM>>>(
            xh, w + 0 * (size_t)WN, bcx, nullptr, nullptr, nullptr, qkvx,
            yh, w + 4 * (size_t)WN, bcy, nullptr, nullptr, nullptr, qkvy,
            PH, LQKV);
    }

    // dual-stream flash attention, both outputs in one launch
    {
        const dim3 ga(2 * (PS / 64), PNH, PB);        // (32, 12, 8)
        attn_mma<<<ga, 128, ATT_SMEM>>>(qkvx, qkvy,
                                        pw11, pw12, pw21, pw22, cxh, cyh);
    }

    // output projections for BOTH streams in one launch
    {
        const dim3 go(PH / 128, 2 * (PM / 128));      // (6, 128)
        mm_gemm<<<go, 256, GEMM_SMEM>>>(
            cxh, w + 3 * (size_t)WN, Bf[3], pw11, pw12, out, nullptr,
            cyh, w + 7 * (size_t)WN, Bf[7], pw21, pw22, out + (size_t)PM * PH, nullptr,
            PH, PH);
    }
}

// round 14
// speedup vs baseline: 4.1550x; 1.0719x over previous
#include <cuda_runtime.h>
#include <cuda_fp16.h>
#include <cstdint>

// Problem constants
#define PB  8
#define PS  1024
#define PH  768
#define PNH 12
#define PDH 64
#define PM  (PB * PS)          // 8192
#define PELEMS (PM * PH)       // 6291456
#define WN  (PH * PH)          // 589824
#define LQKV 2304              // fused q|k|v row stride

// ---------------------------------------------------------------------------
// Scratch (static device globals — no allocation)
// ---------------------------------------------------------------------------
__device__ __half g_xh [PELEMS];
__device__ __half g_yh [PELEMS];
__device__ __half g_qkvx[PM * LQKV];
__device__ __half g_qkvy[PM * LQKV];
__device__ __half g_cxh[PELEMS];
__device__ __half g_cyh[PELEMS];
__device__ __half g_w[8 * WN];
__device__ float g_bcx[LQKV], g_bcy[LQKV];

// ---------------------------------------------------------------------------
// Helpers (sm_80+-portable: ldmatrix + mma.sync + cp.async only)
// ---------------------------------------------------------------------------
__device__ __forceinline__ uint32_t smem_u32(const void* p) {
    uint32_t a;
    asm("{ .reg .u64 t; cvta.to.shared.u64 t, %1; cvt.u32.u64 %0, t; }"
        : "=r"(a) : "l"(p));
    return a;
}

__device__ __forceinline__ void cpasync16(uint32_t dst, const void* src) {
    asm volatile("cp.async.cg.shared.global [%0], [%1], 16;"
                 :: "r"(dst), "l"(src));
}
#define CP_COMMIT() asm volatile("cp.async.commit_group;")
#define CP_WAIT(n)  asm volatile("cp.async.wait_group %0;" :: "n"(n))

__device__ __forceinline__ void ldm4(uint32_t r[4], uint32_t addr) {
    asm volatile("ldmatrix.sync.aligned.m8n8.x4.shared.b16 {%0,%1,%2,%3}, [%4];"
        : "=r"(r[0]), "=r"(r[1]), "=r"(r[2]), "=r"(r[3]) : "r"(addr));
}
__device__ __forceinline__ void ldm4t(uint32_t r[4], uint32_t addr) {
    asm volatile("ldmatrix.sync.aligned.m8n8.x4.trans.shared.b16 {%0,%1,%2,%3}, [%4];"
        : "=r"(r[0]), "=r"(r[1]), "=r"(r[2]), "=r"(r[3]) : "r"(addr));
}

__device__ __forceinline__ void mma16816(float c[4], const uint32_t a[4],
                                         const uint32_t b[2]) {
    asm volatile("mma.sync.aligned.m16n8k16.row.col.f32.f16.f16.f32 "
        "{%0,%1,%2,%3}, {%4,%5,%6,%7}, {%8,%9}, {%0,%1,%2,%3};"
        : "+f"(c[0]), "+f"(c[1]), "+f"(c[2]), "+f"(c[3])
        : "r"(a[0]), "r"(a[1]), "r"(a[2]), "r"(a[3]), "r"(b[0]), "r"(b[1]));
}

__device__ __forceinline__ uint32_t packh(__half a, __half b) {
    __half2 t = __halves2half2(a, b);
    return *(uint32_t*)&t;
}

// ---------------------------------------------------------------------------
// fp32 -> fp16 conversions ; bias concatenation
// ---------------------------------------------------------------------------
__global__ void cvt_inputs(const float* __restrict__ hx, const float* __restrict__ hy,
                           __half* __restrict__ xh, __half* __restrict__ yh)
{
    int i = blockIdx.x * blockDim.x + threadIdx.x;
    if (i >= PELEMS / 4) return;
    const float* src = blockIdx.y ? hy : hx;
    __half* dst = blockIdx.y ? yh : xh;
    float4 v = *(const float4*)(src + (size_t)i * 4);
    ((__half2*)dst)[i * 2 + 0] = __halves2half2(__float2half_rn(v.x), __float2half_rn(v.y));
    ((__half2*)dst)[i * 2 + 1] = __halves2half2(__float2half_rn(v.z), __float2half_rn(v.w));
}

__global__ void cvt_weights(const float* w0, const float* w1, const float* w2,
                            const float* w3, const float* w4, const float* w5,
                            const float* w6, const float* w7,
                            __half* __restrict__ dst)
{
    int i = blockIdx.x * blockDim.x + threadIdx.x;
    if (i >= WN / 4) return;
    const int s = blockIdx.y;
    const float* src;
    switch (s) {
        case 0: src = w0; break; case 1: src = w1; break;
        case 2: src = w2; break; case 3: src = w3; break;
        case 4: src = w4; break; case 5: src = w5; break;
        case 6: src = w6; break; default: src = w7; break;
    }
    float4 v = *(const float4*)(src + (size_t)i * 4);
    __half2* ph = (__half2*)(dst + (size_t)s * WN);
    ph[i * 2 + 0] = __halves2half2(__float2half_rn(v.x), __float2half_rn(v.y));
    ph[i * 2 + 1] = __halves2half2(__float2half_rn(v.z), __float2half_rn(v.w));
}

__global__ void concat_biases(const float* __restrict__ a0, const float* __restrict__ a1,
                              const float* __restrict__ a2, float* __restrict__ ox,
                              const float* __restrict__ b0, const float* __restrict__ b1,
                              const float* __restrict__ b2, float* __restrict__ oy)
{
    int i = blockIdx.x * blockDim.x + threadIdx.x;
    const float* s0 = blockIdx.y ? b0 : a0;
    const float* s1 = blockIdx.y ? b1 : a1;
    const float* s2 = blockIdx.y ? b2 : a2;
    float* o = blockIdx.y ? oy : ox;
    if (i < PH) o[i] = s0[i];
    else if (i < 2 * PH) o[i] = s1[i - PH];
    else if (i < 3 * PH) o[i] = s2[i - 2 * PH];
}

// ---------------------------------------------------------------------------
// fp16 GEMM: C[M,N] = A[M,768] @ W[N,768]^T + bscale*bias
// Single fp16 planes. CTA tile 128x128, K-chunk 32, cp.async 3-stage
// pipeline, ONE barrier per iteration. 256 threads. Dual-config dispatch.
// ---------------------------------------------------------------------------
#define GBK   32
#define GKCH  (PH / GBK)         // 24
#define GSA   40                 // smem row stride fp16 (80B)
#define PLANE_B (128 * GSA * 2)  // 10240
#define STAGE_B (2 * PLANE_B)    // 20480  [A][W]
#define GEMM_SMEM (3 * STAGE_B)  // 61440

__global__ void __launch_bounds__(256)
mm_gemm(const __half* __restrict__ A1, const __half* __restrict__ W1,
        const float* __restrict__ bias1,
        const float* __restrict__ s1a, const float* __restrict__ s1b,
        float* __restrict__ Cf1, __half* __restrict__ C1h,
        const __half* __restrict__ A2, const __half* __restrict__ W2,
        const float* __restrict__ bias2,
        const float* __restrict__ s2a, const float* __restrict__ s2b,
        float* __restrict__ Cf2, __half* __restrict__ C2h,
        int lda, int ldc)
{
    extern __shared__ char smem[];
    const uint32_t sb = smem_u32(smem);
    const int tid = threadIdx.x;
    const int wid = tid >> 5, lane = tid & 31;
    const int warpM = wid >> 2, warpN = wid & 3;

    int by = blockIdx.y;
    const bool second = (by >= 64);
    if (second) by -= 64;

    const __half* A        = second ? A2    : A1;
    const __half* W        = second ? W2    : W1;
    const float* bias      = second ? bias2 : bias1;
    const float* sa        = second ? s2a   : s1a;
    const float* sbv       = second ? s2b   : s1b;
    float* Cf              = second ? Cf2   : Cf1;
    __half* Ch             = second ? C2h   : C1h;

    const int row0 = by * 128, col0 = blockIdx.x * 128;

    const __half* g0 = A + (size_t)row0 * lda;
    const __half* g2 = W + (size_t)col0 * PH;

    float acc[4][4][4];
    #pragma unroll
    for (int mt = 0; mt < 4; mt++)
        #pragma unroll
        for (int nt = 0; nt < 4; nt++)
            #pragma unroll
            for (int c = 0; c < 4; c++) acc[mt][nt][c] = 0.0f;

    const int arow  = warpM * 64 + (lane & 15);
    const int akh   = lane >> 4;
    const int bkey  = warpN * 32 + (lane & 7) + ((lane >> 4) << 3);
    const int bkh   = (lane >> 3) & 1;

#define G_LOAD(kc, st) do {                                                   \
    const uint32_t dbase = sb + (st) * STAGE_B;                               \
    _Pragma("unroll")                                                         \
    for (int j = 0; j < 2; j++) {                                             \
        const int cc = j * 256 + tid;                                         \
        const int r = cc >> 2, seg = cc & 3;                                  \
        const uint32_t so = r * (GSA * 2) + seg * 16;                         \
        const size_t goA = (size_t)r * lda + (kc) * GBK + seg * 8;            \
        const size_t goW = (size_t)r * PH  + (kc) * GBK + seg * 8;            \
        cpasync16(dbase + 0 * PLANE_B + so, g0 + goA);                        \
        cpasync16(dbase + 1 * PLANE_B + so, g2 + goW);                        \
    }                                                                         \
} while (0)

    G_LOAD(0, 0);
    CP_COMMIT();
    G_LOAD(1, 1);
    CP_COMMIT();

    for (int kc = 0; kc < GKCH; kc++) {
        if (kc + 1 < GKCH) { CP_WAIT(1); } else { CP_WAIT(0); }
        __syncthreads();   // tile kc visible to all; everyone past compute kc-1
        if (kc + 2 < GKCH) {
            G_LOAD(kc + 2, (kc + 2) % 3);   // overwrites stage of tile kc-1 (safe)
            CP_COMMIT();
        }

        const uint32_t stb = sb + (kc % 3) * STAGE_B;
        #pragma unroll
        for (int ks = 0; ks < 2; ks++) {
            uint32_t af[4][4];
            #pragma unroll
            for (int mt = 0; mt < 4; mt++)
                ldm4(af[mt], stb + (arow + mt * 16) * (GSA * 2) + ks * 32 + akh * 16);
            uint32_t bf[4][2];
            #pragma unroll
            for (int ntp = 0; ntp < 2; ntp++) {
                const uint32_t addr = stb + PLANE_B
                                      + (bkey + ntp * 16) * (GSA * 2)
                                      + ks * 32 + bkh * 16;
                uint32_t t[4];
                ldm4(t, addr);
                bf[2 * ntp][0] = t[0]; bf[2 * ntp][1] = t[1];
                bf[2 * ntp + 1][0] = t[2]; bf[2 * ntp + 1][1] = t[3];
            }
            #pragma unroll
            for (int mt = 0; mt < 4; mt++)
                #pragma unroll
                for (int nt = 0; nt < 4; nt++)
                    mma16816(acc[mt][nt], af[mt], bf[nt]);
        }
    }

    const int g = lane >> 2, tig = lane & 3;
    const float bscale = sa ? (*sa + *sbv) : 1.0f;
    #pragma unroll
    for (int mt = 0; mt < 4; mt++) {
        const int r0 = row0 + warpM * 64 + mt * 16 + g;
        #pragma unroll
        for (int nt = 0; nt < 4; nt++) {
            const int col = col0 + warpN * 32 + nt * 8 + tig * 2;
            const float b0 = bscale * bias[col];
            const float b1 = bscale * bias[col + 1];
            const float v00 = acc[mt][nt][0] + b0, v01 = acc[mt][nt][1] + b1;
            const float v10 = acc[mt][nt][2] + b0, v11 = acc[mt][nt][3] + b1;
            if (Cf) {
                *(float2*)(Cf + (size_t)r0 * ldc + col)       = make_float2(v00, v01);
                *(float2*)(Cf + (size_t)(r0 + 8) * ldc + col) = make_float2(v10, v11);
            }
            if (Ch) {
                *(__half2*)(Ch + (size_t)r0 * ldc + col) =
                    __halves2half2(__float2half_rn(v00), __float2half_rn(v01));
                *(__half2*)(Ch + (size_t)(r0 + 8) * ldc + col) =
                    __halves2half2(__float2half_rn(v10), __float2half_rn(v11));
            }
        }
    }
}

// ---------------------------------------------------------------------------
// Dual-stream flash attention, fp16 single-plane Q/K/V, both outputs in one
// launch, DOUBLE-BUFFERED KV tiles with one barrier per tile.
// blockIdx.x&1 selects output stream; adjacent CTAs share KV tiles in L2.
// 64 q-rows, 4 warps, base-2 softmax.
// smem: [Q][K0][V0][K1][V1]
// ---------------------------------------------------------------------------
#define AST     72                    // fp16 row stride (144B)
#define ROWB    (AST * 2)             // 144
#define ATILE_B (64 * ROWB)           // 9216
#define ATT_SMEM (5 * ATILE_B)        // 46080
#define SC2     0.1803368801f         // 0.125 * log2(e)

__global__ void __launch_bounds__(128)
attn_mma(const __half* __restrict__ qkvx, const __half* __restrict__ qkvy,
         const float* __restrict__ pw11, const float* __restrict__ pw12,
         const float* __restrict__ pw21, const float* __restrict__ pw22,
         __half* __restrict__ cxh, __half* __restrict__ cyh)
{
    extern __shared__ char smem[];
    const uint32_t sb = smem_u32(smem);

    const int st = blockIdx.x & 1;
    const int qt = blockIdx.x >> 1;
    const int h = blockIdx.y, b = blockIdx.z;
    const int tid = threadIdx.x, wid = tid >> 5, lane = tid & 31;
    const int g = lane >> 2, tig = lane & 3;

    const __half* Qh = st ? qkvy : qkvx;
    const __half* const KH[2] = { qkvx + PH, qkvy + PH };
    const __half* const VH[2] = { qkvx + 2 * PH, qkvy + 2 * PH };
    const float ws0 = st ? *pw22 : *pw11;
    const float ws1 = st ? *pw21 : *pw12;
    __half* ctx = st ? cyh : cxh;

    // --- load Q tile via cp.async ---
    #pragma unroll
    for (int j = 0; j < 4; j++) {
        const int cc = j * 128 + tid;
        const int r = cc >> 3, seg = cc & 7;
        const size_t go = (size_t)(b * PS + qt * 64 + r) * LQKV + h * PDH + seg * 8;
        cpasync16(sb + r * ROWB + seg * 16, Qh + go);
    }
    CP_COMMIT();
    CP_WAIT(0);
    __syncthreads();

    // --- Q fragments (registers, reused across phases) ---
    uint32_t qf[4][4];
    {
        const int qrow = wid * 16 + (lane & 15);
        const int khalf = lane >> 4;
        #pragma unroll
        for (int ks = 0; ks < 4; ks++)
            ldm4(qf[ks], sb + qrow * ROWB + ks * 32 + khalf * 16);
    }

    const int bkey = (lane & 7) + ((lane >> 4) << 3);
    const int bkh  = (lane >> 3) & 1;
    const int vkey = (lane & 7) + (((lane >> 3) & 1) << 3);
    const int vdh  = (lane >> 4) << 3;

#define KV_LOAD(Kp, Vp, kt, buf) do {                                         \
    const uint32_t kbase = sb + ATILE_B + (buf) * 2 * ATILE_B;                \
    _Pragma("unroll")                                                         \
    for (int j = 0; j < 4; j++) {                                             \
        const int cc = j * 128 + tid;                                         \
        const int r = cc >> 3, seg = cc & 7;                                  \
        const size_t go = (size_t)(b * PS + (kt) * 64 + r) * LQKV             \
                          + h * PDH + seg * 8;                                \
        const uint32_t so = r * ROWB + seg * 16;                              \
        cpasync16(kbase + so,           Kp + go);                             \
        cpasync16(kbase + ATILE_B + so, Vp + go);                             \
    }                                                                         \
    CP_COMMIT();                                                              \
} while (0)

    float ostash[8][4];

    for (int s = 0; s < 2; s++) {
        const __half* Kh_ = KH[s];
        const __half* Vh_ = VH[s];

        float m[2] = { -1e30f, -1e30f }, l[2] = { 0.0f, 0.0f };
        float oacc[8][4];
        #pragma unroll
        for (int nt = 0; nt < 8; nt++)
            #pragma unroll
            for (int c = 0; c < 4; c++) oacc[nt][c] = 0.0f;

        KV_LOAD(Kh_, Vh_, 0, 0);

        for (int kt = 0; kt < PS / 64; kt++) {
            CP_WAIT(0);          // tile kt resident (this thread's parts)
            __syncthreads();     // all threads' parts visible; compute kt-1 done
            if (kt + 1 < PS / 64)
                KV_LOAD(Kh_, Vh_, kt + 1, (kt + 1) & 1);  // flies during compute

            const uint32_t kh_s = sb + ATILE_B + (kt & 1) * 2 * ATILE_B;
            const uint32_t vh_s = kh_s + ATILE_B;

            // --- scores S = Q @ K^T ---
            float sacc[8][4];
            #pragma unroll
            for (int nt = 0; nt < 8; nt++)
                #pragma unroll
                for (int c = 0; c < 4; c++) sacc[nt][c] = 0.0f;

            #pragma unroll
            for (int ks = 0; ks < 4; ks++) {
                #pragma unroll
                for (int ntp = 0; ntp < 4; ntp++) {
                    const uint32_t addr = kh_s + (ntp * 16 + bkey) * ROWB
                                          + ks * 32 + bkh * 16;
                    uint32_t th[4];
                    ldm4(th, addr);
                    const uint32_t b0h[2] = { th[0], th[1] }, b1h[2] = { th[2], th[3] };
                    mma16816(sacc[2 * ntp],     qf[ks], b0h);
                    mma16816(sacc[2 * ntp + 1], qf[ks], b1h);
                }
            }

            // --- online softmax in base-2 ---
            #pragma unroll
            for (int nt = 0; nt < 8; nt++)
                #pragma unroll
                for (int c = 0; c < 4; c++) sacc[nt][c] *= SC2;

            #pragma unroll
            for (int half = 0; half < 2; half++) {
                float mx = -1e30f;
                #pragma unroll
                for (int nt = 0; nt < 8; nt++)
                    mx = fmaxf(mx, fmaxf(sacc[nt][2 * half], sacc[nt][2 * half + 1]));
                mx = fmaxf(mx, __shfl_xor_sync(0xffffffffu, mx, 1));
                mx = fmaxf(mx, __shfl_xor_sync(0xffffffffu, mx, 2));
                const float mn = fmaxf(m[half], mx);
                const float corr = exp2f(m[half] - mn);
                m[half] = mn;
                float rs = 0.0f;
                #pragma unroll
                for (int nt = 0; nt < 8; nt++) {
                    const float p0 = exp2f(sacc[nt][2 * half] - mn);
                    const float p1 = exp2f(sacc[nt][2 * half + 1] - mn);
                    sacc[nt][2 * half] = p0;
                    sacc[nt][2 * half + 1] = p1;
                    rs += p0 + p1;
                }
                rs += __shfl_xor_sync(0xffffffffu, rs, 1);
                rs += __shfl_xor_sync(0xffffffffu, rs, 2);
                l[half] = l[half] * corr + rs;
                #pragma unroll
                for (int nt = 0; nt < 8; nt++) {
                    oacc[nt][2 * half]     *= corr;
                    oacc[nt][2 * half + 1] *= corr;
                }
            }

            // --- pack P into fp16 A-fragments ---
            uint32_t ph[8][2];
            #pragma unroll
            for (int nt = 0; nt < 8; nt++) {
                #pragma unroll
                for (int half = 0; half < 2; half++) {
                    ph[nt][half] = packh(__float2half_rn(sacc[nt][2 * half]),
                                         __float2half_rn(sacc[nt][2 * half + 1]));
                }
            }

            // --- O += P @ V ---
            #pragma unroll
            for (int ks = 0; ks < 4; ks++) {
                const uint32_t pa[4] = { ph[2 * ks][0], ph[2 * ks][1],
                                         ph[2 * ks + 1][0], ph[2 * ks + 1][1] };
                #pragma unroll
                for (int dhp = 0; dhp < 4; dhp++) {
                    const uint32_t addr = vh_s + (ks * 16 + vkey) * ROWB
                                          + (dhp * 16 + vdh) * 2;
                    uint32_t th[4];
                    ldm4t(th, addr);
                    const uint32_t b0h[2] = { th[0], th[1] }, b1h[2] = { th[2], th[3] };
                    mma16816(oacc[2 * dhp],     pa, b0h);
                    mma16816(oacc[2 * dhp + 1], pa, b1h);
                }
            }
        }

        if (s == 0) {
            const float i0 = ws0 / l[0], i1 = ws0 / l[1];
            #pragma unroll
            for (int nt = 0; nt < 8; nt++) {
                ostash[nt][0] = oacc[nt][0] * i0;
                ostash[nt][1] = oacc[nt][1] * i0;
                ostash[nt][2] = oacc[nt][2] * i1;
                ostash[nt][3] = oacc[nt][3] * i1;
            }
        } else {
            const float i0 = ws1 / l[0], i1 = ws1 / l[1];
            const int r0 = qt * 64 + wid * 16 + g;
            #pragma unroll
            for (int nt = 0; nt < 8; nt++) {
                const int col = h * PDH + nt * 8 + tig * 2;
                const float v00 = ostash[nt][0] + oacc[nt][0] * i0;
                const float v01 = ostash[nt][1] + oacc[nt][1] * i0;
                const float v10 = ostash[nt][2] + oacc[nt][2] * i1;
                const float v11 = ostash[nt][3] + oacc[nt][3] * i1;
                const size_t o0 = (size_t)(b * PS + r0) * PH + col;
                const size_t o1 = (size_t)(b * PS + r0 + 8) * PH + col;
                *(__half2*)(ctx + o0) = __halves2half2(__float2half_rn(v00),
                                                       __float2half_rn(v01));
                *(__half2*)(ctx + o1) = __halves2half2(__float2half_rn(v10),
                                                       __float2half_rn(v11));
            }
        }
    }
}

// ---------------------------------------------------------------------------
// Launch
// ---------------------------------------------------------------------------
extern "C" void kernel_launch(void* const* d_in, const int* in_sizes, int n_in,
                              void* d_out, int out_size)
{
    const float* hx = (const float*)d_in[0];
    const float* hy = (const float*)d_in[1];
    const float* Wf[8] = { (const float*)d_in[2],  (const float*)d_in[4],
                           (const float*)d_in[6],  (const float*)d_in[8],
                           (const float*)d_in[10], (const float*)d_in[12],
                           (const float*)d_in[14], (const float*)d_in[16] };
    const float* Bf[8] = { (const float*)d_in[3],  (const float*)d_in[5],
                           (const float*)d_in[7],  (const float*)d_in[9],
                           (const float*)d_in[11], (const float*)d_in[13],
                           (const float*)d_in[15], (const float*)d_in[17] };
    // order: 0=q 1=k 2=v 3=o 4=qd 5=kd 6=vd 7=od
    const float* pw11 = (const float*)d_in[18];
    const float* pw12 = (const float*)d_in[19];
    const float* pw21 = (const float*)d_in[20];
    const float* pw22 = (const float*)d_in[21];
    float* out = (float*)d_out;

    __half *xh, *yh, *qkvx, *qkvy, *cxh, *cyh, *w;
    float *bcx, *bcy;
    cudaGetSymbolAddress((void**)&xh,   g_xh);
    cudaGetSymbolAddress((void**)&yh,   g_yh);
    cudaGetSymbolAddress((void**)&qkvx, g_qkvx);
    cudaGetSymbolAddress((void**)&qkvy, g_qkvy);
    cudaGetSymbolAddress((void**)&cxh,  g_cxh);
    cudaGetSymbolAddress((void**)&cyh,  g_cyh);
    cudaGetSymbolAddress((void**)&w,    g_w);
    cudaGetSymbolAddress((void**)&bcx,  g_bcx);
    cudaGetSymbolAddress((void**)&bcy,  g_bcy);

    // conversions + bias concat
    {
        const int n4a = PELEMS / 4, n4w = WN / 4;
        dim3 gi((n4a + 255) / 256, 2);
        cvt_inputs<<<gi, 256>>>(hx, hy, xh, yh);
        dim3 gw((n4w + 255) / 256, 8);
        cvt_weights<<<gw, 256>>>(Wf[0], Wf[1], Wf[2], Wf[3],
                                 Wf[4], Wf[5], Wf[6], Wf[7], w);
        concat_biases<<<dim3(9, 2), 256>>>(Bf[0], Bf[1], Bf[2], bcx,
                                           Bf[4], Bf[5], Bf[6], bcy);
    }

    cudaFuncSetAttribute(mm_gemm, cudaFuncAttributeMaxDynamicSharedMemorySize,
                         GEMM_SMEM);
    cudaFuncSetAttribute(attn_mma, cudaFuncAttributeMaxDynamicSharedMemorySize,
                         ATT_SMEM);

    // fused QKV projections for BOTH streams in one launch (N = 2304)
    {
        const dim3 gq(LQKV / 128, 2 * (PM / 128));    // (18, 128)
        mm_gemm<<<gq, 256, GEMM_SMEM>>>(
            xh, w + 0 * (size_t)WN, bcx, nullptr, nullptr, nullptr, qkvx,
            yh, w + 4 * (size_t)WN, bcy, nullptr, nullptr, nullptr, qkvy,
            PH, LQKV);
    }

    // dual-stream flash attention, both outputs in one launch
    {
        const dim3 ga(2 * (PS / 64), PNH, PB);        // (32, 12, 8)
        attn_mma<<<ga, 128, ATT_SMEM>>>(qkvx, qkvy,
                                        pw11, pw12, pw21, pw22, cxh, cyh);
    }

    // output projections for BOTH streams in one launch
    {
        const dim3 go(PH / 128, 2 * (PM / 128));      // (6, 128)
        mm_gemm<<<go, 256, GEMM_SMEM>>>(
            cxh, w + 3 * (size_t)WN, Bf[3], pw11, pw12, out, nullptr,
            cyh, w + 7 * (size_t)WN, Bf[7], pw21, pw22, out + (size_t)PM * PH, nullptr,
            PH, PH);
    }
}